// round 6
// baseline (speedup 1.0000x reference)
#include <cuda_runtime.h>
#include <math.h>
#include <stdint.h>

#define MT   4096    // B*T rows
#define DM   1024
#define DFF  4096
#define DQKV 3072

// ---------------- scratch (device globals; no allocation allowed) -----------
__device__ float g_xn[MT * DM];
__device__ float g_qkv[MT * DQKV];
__device__ float g_attn[MT * DM];
__device__ float g_x1[MT * DM];
__device__ float g_h[MT * DFF];
// tf32-rounded weights
__device__ float g_wqkv[DQKV * DM];
__device__ float g_wo[DM * DM];
__device__ float g_w1[DFF * DM];
__device__ float g_w2[DM * DFF];

// ---------------- helpers ----------------
__device__ __forceinline__ float tf32rna_f(float x) {
    uint32_t r;
    asm("cvt.rna.tf32.f32 %0, %1;" : "=r"(r) : "f"(x));
    return __uint_as_float(r);
}

__device__ __forceinline__ void mma_tf32(float c[4], uint32_t a0, uint32_t a1,
                                         uint32_t a2, uint32_t a3,
                                         uint32_t b0, uint32_t b1) {
    asm volatile(
        "mma.sync.aligned.m16n8k8.row.col.f32.tf32.tf32.f32 "
        "{%0,%1,%2,%3}, {%4,%5,%6,%7}, {%8,%9}, {%0,%1,%2,%3};"
        : "+f"(c[0]), "+f"(c[1]), "+f"(c[2]), "+f"(c[3])
        : "r"(a0), "r"(a1), "r"(a2), "r"(a3), "r"(b0), "r"(b1));
}

__device__ __forceinline__ float gelu_exact(float x) {
    return 0.5f * x * (1.0f + erff(x * 0.70710678118654752f));
}

__device__ __forceinline__ void cp_async16(uint32_t smaddr, const void* gptr) {
    asm volatile("cp.async.cg.shared.global [%0], [%1], 16;"
                 :: "r"(smaddr), "l"(gptr) : "memory");
}
#define CP_COMMIT()  asm volatile("cp.async.commit_group;" ::: "memory")
#define CP_WAIT(n)   asm volatile("cp.async.wait_group %0;" :: "n"(n) : "memory")

#define GM_NONE 0
#define GM_GELU 1
#define GM_RES  2

// ---------------- weight tf32 pre-round ----------------
__global__ void roundw_kernel(const float* __restrict__ src,
                              float* __restrict__ dst, int n4) {
    int i = blockIdx.x * blockDim.x + threadIdx.x;
    if (i < n4) {
        float4 v = reinterpret_cast<const float4*>(src)[i];
        v.x = tf32rna_f(v.x); v.y = tf32rna_f(v.y);
        v.z = tf32rna_f(v.z); v.w = tf32rna_f(v.w);
        reinterpret_cast<float4*>(dst)[i] = v;
    }
}

__global__ void roundqkv_kernel(const float* __restrict__ wq,
                                const float* __restrict__ wk,
                                const float* __restrict__ wv,
                                float* __restrict__ dst) {
    int seg = blockIdx.y;
    const float* src = (seg == 0) ? wq : ((seg == 1) ? wk : wv);
    int n4 = DM * DM / 4;
    int i = blockIdx.x * blockDim.x + threadIdx.x;
    if (i < n4) {
        float4 v = reinterpret_cast<const float4*>(src)[i];
        v.x = tf32rna_f(v.x); v.y = tf32rna_f(v.y);
        v.z = tf32rna_f(v.z); v.w = tf32rna_f(v.w);
        reinterpret_cast<float4*>(dst)[seg * n4 + i] = v;
    }
}

// ============================================================================
// tf32 tensor-core GEMM (as R5): C[m,n] = sum_k A[m,k] * B[n,k]  (+ epilogue)
// CTA tile 128x128x32, 4 warps, 3-stage cp.async, chunk swizzle c^=(row&7).
// ============================================================================
#define KT 32
#define TILEB (128 * KT * 4)             // 16 KB
#define GEMM_SMEM (3 * 2 * TILEB)        // 96 KB

template <int MODE>
__global__ __launch_bounds__(128, 2)
void gemm_tc(const float* __restrict__ A, const float* __restrict__ B,
             const float* __restrict__ Res, float* __restrict__ C,
             int M, int N, int K) {
    extern __shared__ char sm[];
    uint32_t smb = (uint32_t)__cvta_generic_to_shared(sm);

    int tid = threadIdx.x;
    int wid = tid >> 5;
    int lane = tid & 31;
    int wm = wid >> 1;
    int wn = wid & 1;
    int g  = lane >> 2;
    int t4 = lane & 3;

    int m0 = blockIdx.y * 128;
    int n0 = blockIdx.x * 128;
    const float* Ag = A + (size_t)m0 * K;
    const float* Bg = B + (size_t)n0 * K;

    int crow[8]; uint32_t coff[8]; int cchunk[8];
#pragma unroll
    for (int it = 0; it < 8; it++) {
        int idx = it * 128 + tid;
        int r = idx >> 3;
        int c = idx & 7;
        crow[it] = r;
        coff[it] = (uint32_t)(r * 128 + ((c ^ (r & 7)) << 4));
        cchunk[it] = c;
    }

    float acc[4][8][4];
#pragma unroll
    for (int i = 0; i < 4; i++)
#pragma unroll
        for (int j = 0; j < 8; j++)
#pragma unroll
            for (int r = 0; r < 4; r++) acc[i][j][r] = 0.f;

    int NT = K / KT;

    auto issue = [&](int t, int st) {
        uint32_t As = smb + st * 2 * TILEB;
        uint32_t Bs = As + TILEB;
        const float* Agt = Ag + t * KT;
        const float* Bgt = Bg + t * KT;
#pragma unroll
        for (int it = 0; it < 8; it++) {
            cp_async16(As + coff[it], Agt + (size_t)crow[it] * K + cchunk[it] * 4);
            cp_async16(Bs + coff[it], Bgt + (size_t)crow[it] * K + cchunk[it] * 4);
        }
    };

    issue(0, 0); CP_COMMIT();
    if (NT > 1) issue(1, 1);
    CP_COMMIT();

    for (int t = 0; t < NT; t++) {
        int st = t % 3;
        CP_WAIT(1);
        __syncthreads();

        uint32_t As = smb + st * 2 * TILEB;
        uint32_t Bs = As + TILEB;
#pragma unroll
        for (int s = 0; s < 4; s++) {
            uint32_t af[4][4];
#pragma unroll
            for (int i = 0; i < 4; i++) {
                uint32_t row = (uint32_t)(wm * 64 + i * 16 + g);
                uint32_t base = As + row * 128 + (t4 << 2);
                uint32_t c0 = (uint32_t)(((2 * s) ^ g) << 4);
                uint32_t c1 = (uint32_t)(((2 * s + 1) ^ g) << 4);
                asm volatile("ld.shared.b32 %0, [%1];" : "=r"(af[i][0]) : "r"(base + c0));
                asm volatile("ld.shared.b32 %0, [%1];" : "=r"(af[i][1]) : "r"(base + c0 + 1024));
                asm volatile("ld.shared.b32 %0, [%1];" : "=r"(af[i][2]) : "r"(base + c1));
                asm volatile("ld.shared.b32 %0, [%1];" : "=r"(af[i][3]) : "r"(base + c1 + 1024));
            }
            uint32_t bf[8][2];
#pragma unroll
            for (int j = 0; j < 8; j++) {
                uint32_t row = (uint32_t)(wn * 64 + j * 8 + g);
                uint32_t base = Bs + row * 128 + (t4 << 2);
                uint32_t c0 = (uint32_t)(((2 * s) ^ g) << 4);
                uint32_t c1 = (uint32_t)(((2 * s + 1) ^ g) << 4);
                asm volatile("ld.shared.b32 %0, [%1];" : "=r"(bf[j][0]) : "r"(base + c0));
                asm volatile("ld.shared.b32 %0, [%1];" : "=r"(bf[j][1]) : "r"(base + c1));
            }
#pragma unroll
            for (int i = 0; i < 4; i++)
#pragma unroll
                for (int j = 0; j < 8; j++)
                    mma_tf32(acc[i][j], af[i][0], af[i][1], af[i][2], af[i][3],
                             bf[j][0], bf[j][1]);
        }

        if (t + 2 < NT) issue(t + 2, (t + 2) % 3);
        CP_COMMIT();
    }

    // epilogue
#pragma unroll
    for (int i = 0; i < 4; i++) {
#pragma unroll
        for (int j = 0; j < 8; j++) {
            int mlo = m0 + wm * 64 + i * 16 + g;
            int n   = n0 + wn * 64 + j * 8 + t4 * 2;
            float2 v0 = make_float2(acc[i][j][0], acc[i][j][1]);
            float2 v1 = make_float2(acc[i][j][2], acc[i][j][3]);
            if (MODE == GM_GELU) {
                v0.x = tf32rna_f(gelu_exact(v0.x));
                v0.y = tf32rna_f(gelu_exact(v0.y));
                v1.x = tf32rna_f(gelu_exact(v1.x));
                v1.y = tf32rna_f(gelu_exact(v1.y));
            }
            if (MODE == GM_RES) {
                float2 r0 = *reinterpret_cast<const float2*>(Res + (size_t)mlo * N + n);
                float2 r1 = *reinterpret_cast<const float2*>(Res + (size_t)(mlo + 8) * N + n);
                v0.x += r0.x; v0.y += r0.y;
                v1.x += r1.x; v1.y += r1.y;
            }
            *reinterpret_cast<float2*>(C + (size_t)mlo * N + n) = v0;
            *reinterpret_cast<float2*>(C + (size_t)(mlo + 8) * N + n) = v1;
        }
    }
}

// ---------------- rmsnorm (tf32-rounded output; feeds GEMMs only) ----------
__global__ void rmsnorm_kernel(const float* __restrict__ x,
                               const float* __restrict__ w,
                               float* __restrict__ out) {
    int row = blockIdx.x;
    int tid = threadIdx.x;
    const float4* x4 = reinterpret_cast<const float4*>(x + (size_t)row * DM);
    const float4* w4 = reinterpret_cast<const float4*>(w);
    float4* o4 = reinterpret_cast<float4*>(out + (size_t)row * DM);
    float4 v = x4[tid];
    float ss = v.x * v.x + v.y * v.y + v.z * v.z + v.w * v.w;
#pragma unroll
    for (int off = 16; off; off >>= 1)
        ss += __shfl_xor_sync(0xffffffffu, ss, off);
    __shared__ float sred[8];
    __shared__ float stot;
    if ((tid & 31) == 0) sred[tid >> 5] = ss;
    __syncthreads();
    if (tid == 0) {
        float t = 0.f;
#pragma unroll
        for (int i = 0; i < 8; i++) t += sred[i];
        stot = rsqrtf(t * (1.0f / DM) + 1e-5f);
    }
    __syncthreads();
    float rinv = stot;
    float4 wv = w4[tid];
    float4 r;
    r.x = tf32rna_f(wv.x * v.x * rinv);
    r.y = tf32rna_f(wv.y * v.y * rinv);
    r.z = tf32rna_f(wv.z * v.z * rinv);
    r.w = tf32rna_f(wv.w * v.w * rinv);
    o4[tid] = r;
}

// ============================================================================
// Tensor-core causal flash attention (tf32), cp.async double-buffered K/V.
// Bq=128 (8 warps x 16 rows), Bk=64, dk=64. Grid (16,16,2), 256 threads.
// K/V staged raw fp32 (HW tf32 truncation in MMA). Q/P RNA-rounded.
// ============================================================================
#define QS_PAD 68
#define KS_PAD 68
#define VS_PAD 72
#define PW_PAD 68
#define KV_K_F (64 * KS_PAD)
#define KV_V_F (64 * VS_PAD)
#define ATT_SMEM_FLOATS (128 * QS_PAD + 2 * KV_K_F + 2 * KV_V_F + 8 * 16 * PW_PAD)
#define ATT_SMEM_BYTES  (ATT_SMEM_FLOATS * 4)

__global__ __launch_bounds__(256)
void attn_tc(const float* __restrict__ q, const float* __restrict__ k,
             const float* __restrict__ v, float* __restrict__ o,
             int ldin, int ldo) {
    extern __shared__ float smf[];
    float* Qs  = smf;                          // 128*68
    float* Kb  = Qs + 128 * QS_PAD;            // 2 x 64*68
    float* Vb  = Kb + 2 * KV_K_F;              // 2 x 64*72
    float* Pw  = Vb + 2 * KV_V_F;              // 8*16*68
    uint32_t Kb_u = (uint32_t)__cvta_generic_to_shared(Kb);
    uint32_t Vb_u = (uint32_t)__cvta_generic_to_shared(Vb);

    int qb  = blockIdx.x;
    int h   = blockIdx.y;
    int b   = blockIdx.z;
    int tid = threadIdx.x;
    int wid = tid >> 5;
    int lane = tid & 31;
    int g  = lane >> 2;
    int t4 = lane & 3;
    int row0 = b * 2048;
    int col0 = h * 64;

    int qrowg = qb * 128 + wid * 16;
    float* Pme = Pw + wid * 16 * PW_PAD;

    // staging coords for K/V (1024 chunks each): r = id>>4, c = id&15
    int sr = tid >> 4;           // rows this thread covers: sr, sr+16, sr+32, sr+48
    int sc = tid & 15;

    auto stage_kv = [&](int jb, int buf) {
        uint32_t Kst = Kb_u + (uint32_t)buf * (KV_K_F * 4);
        uint32_t Vst = Vb_u + (uint32_t)buf * (KV_V_F * 4);
#pragma unroll
        for (int it = 0; it < 4; it++) {
            int r = sr + it * 16;
            size_t gi = (size_t)(row0 + jb * 64 + r) * ldin + col0 + sc * 4;
            cp_async16(Kst + (uint32_t)(r * (KS_PAD * 4) + sc * 16), k + gi);
            cp_async16(Vst + (uint32_t)(r * (VS_PAD * 4) + sc * 16), v + gi);
        }
    };

    // stage Q block (128x64), scaled by 0.125, tf32-rounded
#pragma unroll
    for (int it = 0; it < 8; it++) {
        int id = it * 256 + tid;
        int r  = id >> 4;
        int c4 = id & 15;
        float4 val = *reinterpret_cast<const float4*>(
            q + (size_t)(row0 + qb * 128 + r) * ldin + col0 + c4 * 4);
        val.x = tf32rna_f(val.x * 0.125f);
        val.y = tf32rna_f(val.y * 0.125f);
        val.z = tf32rna_f(val.z * 0.125f);
        val.w = tf32rna_f(val.w * 0.125f);
        *reinterpret_cast<float4*>(&Qs[r * QS_PAD + c4 * 4]) = val;
    }

    stage_kv(0, 0); CP_COMMIT();

    float m_i[2] = {-1e30f, -1e30f};
    float l_i[2] = {0.f, 0.f};
    float oacc[8][4];
#pragma unroll
    for (int j = 0; j < 8; j++)
#pragma unroll
        for (int r = 0; r < 4; r++) oacc[j][r] = 0.f;

    int nkb = 2 * qb + 2;
    for (int jb = 0; jb < nkb; jb++) {
        int buf = jb & 1;
        __syncthreads();   // everyone done with buffer buf (used at jb-2) and Pw
        if (jb + 1 < nkb) {
            stage_kv(jb + 1, buf ^ 1);
            CP_COMMIT();
            CP_WAIT(1);
        } else {
            CP_WAIT(0);
        }
        __syncthreads();

        if (jb * 64 > qrowg + 15) continue;
        bool full_vis = (jb * 64 + 63 <= qrowg);

        const float* Ks = Kb + buf * KV_K_F;
        const float* Vs = Vb + buf * KV_V_F;

        float sacc[8][4];
#pragma unroll
        for (int j = 0; j < 8; j++)
#pragma unroll
            for (int r = 0; r < 4; r++) sacc[j][r] = 0.f;

#pragma unroll
        for (int s = 0; s < 8; s++) {
            int qr = wid * 16;
            uint32_t a0 = __float_as_uint(Qs[(qr + g) * QS_PAD + s * 8 + t4]);
            uint32_t a1 = __float_as_uint(Qs[(qr + g + 8) * QS_PAD + s * 8 + t4]);
            uint32_t a2 = __float_as_uint(Qs[(qr + g) * QS_PAD + s * 8 + t4 + 4]);
            uint32_t a3 = __float_as_uint(Qs[(qr + g + 8) * QS_PAD + s * 8 + t4 + 4]);
#pragma unroll
            for (int jn = 0; jn < 8; jn++) {
                uint32_t b0 = __float_as_uint(Ks[(jn * 8 + g) * KS_PAD + s * 8 + t4]);
                uint32_t b1 = __float_as_uint(Ks[(jn * 8 + g) * KS_PAD + s * 8 + t4 + 4]);
                mma_tf32(sacc[jn], a0, a1, a2, a3, b0, b1);
            }
        }

        if (!full_vis) {
            int colb = jb * 64 + 2 * t4;
            int r0i = qrowg + g;
            int r1i = qrowg + g + 8;
#pragma unroll
            for (int jn = 0; jn < 8; jn++) {
                int c = colb + jn * 8;
                if (c     > r0i) sacc[jn][0] = -1e30f;
                if (c + 1 > r0i) sacc[jn][1] = -1e30f;
                if (c     > r1i) sacc[jn][2] = -1e30f;
                if (c + 1 > r1i) sacc[jn][3] = -1e30f;
            }
        }

#pragma unroll
        for (int half = 0; half < 2; half++) {
            int e0 = half * 2;
            float mx = -1e30f;
#pragma unroll
            for (int jn = 0; jn < 8; jn++)
                mx = fmaxf(mx, fmaxf(sacc[jn][e0], sacc[jn][e0 + 1]));
            mx = fmaxf(mx, __shfl_xor_sync(0xffffffffu, mx, 1));
            mx = fmaxf(mx, __shfl_xor_sync(0xffffffffu, mx, 2));
            float mnew = fmaxf(m_i[half], mx);
            float alpha = __expf(m_i[half] - mnew);
            float rs = 0.f;
            int prow = (g + 8 * half) * PW_PAD + 2 * t4;
#pragma unroll
            for (int jn = 0; jn < 8; jn++) {
                float p0 = __expf(sacc[jn][e0] - mnew);
                float p1 = __expf(sacc[jn][e0 + 1] - mnew);
                rs += p0 + p1;
                float2 pv = make_float2(tf32rna_f(p0), tf32rna_f(p1));
                *reinterpret_cast<float2*>(&Pme[prow + jn * 8]) = pv;
            }
            rs += __shfl_xor_sync(0xffffffffu, rs, 1);
            rs += __shfl_xor_sync(0xffffffffu, rs, 2);
            l_i[half] = l_i[half] * alpha + rs;
            m_i[half] = mnew;
#pragma unroll
            for (int jn = 0; jn < 8; jn++) {
                oacc[jn][e0]     *= alpha;
                oacc[jn][e0 + 1] *= alpha;
            }
        }
        __syncwarp();

#pragma unroll
        for (int s = 0; s < 8; s++) {
            uint32_t a0 = __float_as_uint(Pme[g * PW_PAD + s * 8 + t4]);
            uint32_t a1 = __float_as_uint(Pme[(g + 8) * PW_PAD + s * 8 + t4]);
            uint32_t a2 = __float_as_uint(Pme[g * PW_PAD + s * 8 + t4 + 4]);
            uint32_t a3 = __float_as_uint(Pme[(g + 8) * PW_PAD + s * 8 + t4 + 4]);
#pragma unroll
            for (int jn = 0; jn < 8; jn++) {
                uint32_t b0 = __float_as_uint(Vs[(s * 8 + t4) * VS_PAD + jn * 8 + g]);
                uint32_t b1 = __float_as_uint(Vs[(s * 8 + t4 + 4) * VS_PAD + jn * 8 + g]);
                mma_tf32(oacc[jn], a0, a1, a2, a3, b0, b1);
            }
        }
        __syncwarp();
    }

#pragma unroll
    for (int half = 0; half < 2; half++) {
        float inv = 1.0f / l_i[half];
        int r = row0 + qrowg + g + 8 * half;
        int e0 = half * 2;
#pragma unroll
        for (int jn = 0; jn < 8; jn++) {
            float2 ov = make_float2(tf32rna_f(oacc[jn][e0] * inv),
                                    tf32rna_f(oacc[jn][e0 + 1] * inv));
            *reinterpret_cast<float2*>(o + (size_t)r * ldo + col0 + jn * 8 + 2 * t4) = ov;
        }
    }
}

// ---------------- launch ----------------
extern "C" void kernel_launch(void* const* d_in, const int* in_sizes, int n_in,
                              void* d_out, int out_size) {
    const float* x     = (const float*)d_in[0];
    const float* wq    = (const float*)d_in[1];
    const float* wk    = (const float*)d_in[2];
    const float* wv    = (const float*)d_in[3];
    const float* wo    = (const float*)d_in[4];
    const float* ln1_w = (const float*)d_in[5];
    const float* ln2_w = (const float*)d_in[6];
    const float* w1    = (const float*)d_in[7];
    const float* w2    = (const float*)d_in[8];
    float* out = (float*)d_out;

    float *p_xn, *p_qkv, *p_attn, *p_x1, *p_h;
    float *p_wqkv, *p_wo, *p_w1, *p_w2;
    cudaGetSymbolAddress((void**)&p_xn, g_xn);
    cudaGetSymbolAddress((void**)&p_qkv, g_qkv);
    cudaGetSymbolAddress((void**)&p_attn, g_attn);
    cudaGetSymbolAddress((void**)&p_x1, g_x1);
    cudaGetSymbolAddress((void**)&p_h, g_h);
    cudaGetSymbolAddress((void**)&p_wqkv, g_wqkv);
    cudaGetSymbolAddress((void**)&p_wo, g_wo);
    cudaGetSymbolAddress((void**)&p_w1, g_w1);
    cudaGetSymbolAddress((void**)&p_w2, g_w2);

    cudaFuncSetAttribute(gemm_tc<GM_NONE>, cudaFuncAttributeMaxDynamicSharedMemorySize, GEMM_SMEM);
    cudaFuncSetAttribute(gemm_tc<GM_GELU>, cudaFuncAttributeMaxDynamicSharedMemorySize, GEMM_SMEM);
    cudaFuncSetAttribute(gemm_tc<GM_RES>,  cudaFuncAttributeMaxDynamicSharedMemorySize, GEMM_SMEM);
    cudaFuncSetAttribute(attn_tc, cudaFuncAttributeMaxDynamicSharedMemorySize, ATT_SMEM_BYTES);

    dim3 gd_qkv(DQKV / 128, MT / 128);  // 24 x 32
    dim3 gd_1024(DM / 128, MT / 128);   // 8 x 32
    dim3 gd_ff(DFF / 128, MT / 128);    // 32 x 32

    // 0. pre-round weights to tf32 values
    int n4a = DM * DM / 4;
    int n4f = DFF * DM / 4;
    roundqkv_kernel<<<dim3((n4a + 255) / 256, 3), 256>>>(wq, wk, wv, p_wqkv);
    roundw_kernel<<<(n4a + 255) / 256, 256>>>(wo, p_wo, n4a);
    roundw_kernel<<<(n4f + 255) / 256, 256>>>(w1, p_w1, n4f);
    roundw_kernel<<<(n4f + 255) / 256, 256>>>(w2, p_w2, n4f);

    // 1. xn1 = rmsnorm(x, ln1_w)
    rmsnorm_kernel<<<MT, 256>>>(x, ln1_w, p_xn);

    // 2. fused QKV = xn1 @ wqkv.T   ([MT, 3072])
    gemm_tc<GM_NONE><<<gd_qkv, 128, GEMM_SMEM>>>(p_xn, p_wqkv, nullptr, p_qkv, MT, DQKV, DM);

    // 3. causal flash attention (Q,K,V strided in fused buffer)
    attn_tc<<<dim3(16, 16, 2), 256, ATT_SMEM_BYTES>>>(
        p_qkv, p_qkv + DM, p_qkv + 2 * DM, p_attn, DQKV, DM);

    // 4. x1 = x + attn @ wo.T
    gemm_tc<GM_RES><<<gd_1024, 128, GEMM_SMEM>>>(p_attn, p_wo, x, p_x1, MT, DM, DM);

    // 5. xn2 = rmsnorm(x1, ln2_w)
    rmsnorm_kernel<<<MT, 256>>>(p_x1, ln2_w, p_xn);

    // 6. h = gelu(xn2 @ w1.T)
    gemm_tc<GM_GELU><<<gd_ff, 128, GEMM_SMEM>>>(p_xn, p_w1, nullptr, p_h, MT, DFF, DM);

    // 7. out = x1 + h @ w2.T
    gemm_tc<GM_RES><<<gd_1024, 128, GEMM_SMEM>>>(p_h, p_w2, p_x1, out, MT, DM, DFF);
}

// round 7
// speedup vs baseline: 1.0252x; 1.0252x over previous
#include <cuda_runtime.h>
#include <math.h>
#include <stdint.h>

#define MT   4096    // B*T rows
#define DM   1024
#define DFF  4096
#define DQKV 3072

// ---------------- scratch (device globals; no allocation allowed) -----------
__device__ float g_xn[MT * DM];
__device__ float g_qkv[MT * DQKV];
__device__ float g_attn[MT * DM];
__device__ float g_x1[MT * DM];
__device__ float g_h[MT * DFF];
// tf32-rounded weights
__device__ float g_wqkv[DQKV * DM];
__device__ float g_wo[DM * DM];
__device__ float g_w1[DFF * DM];
__device__ float g_w2[DM * DFF];

// ---------------- helpers ----------------
__device__ __forceinline__ float tf32rna_f(float x) {
    uint32_t r;
    asm("cvt.rna.tf32.f32 %0, %1;" : "=r"(r) : "f"(x));
    return __uint_as_float(r);
}

__device__ __forceinline__ void mma_tf32(float c[4], uint32_t a0, uint32_t a1,
                                         uint32_t a2, uint32_t a3,
                                         uint32_t b0, uint32_t b1) {
    asm volatile(
        "mma.sync.aligned.m16n8k8.row.col.f32.tf32.tf32.f32 "
        "{%0,%1,%2,%3}, {%4,%5,%6,%7}, {%8,%9}, {%0,%1,%2,%3};"
        : "+f"(c[0]), "+f"(c[1]), "+f"(c[2]), "+f"(c[3])
        : "r"(a0), "r"(a1), "r"(a2), "r"(a3), "r"(b0), "r"(b1));
}

__device__ __forceinline__ float gelu_exact(float x) {
    return 0.5f * x * (1.0f + erff(x * 0.70710678118654752f));
}

__device__ __forceinline__ void cp_async16(uint32_t smaddr, const void* gptr) {
    asm volatile("cp.async.cg.shared.global [%0], [%1], 16;"
                 :: "r"(smaddr), "l"(gptr) : "memory");
}
#define CP_COMMIT()  asm volatile("cp.async.commit_group;" ::: "memory")
#define CP_WAIT(n)   asm volatile("cp.async.wait_group %0;" :: "n"(n) : "memory")

#define GM_NONE 0
#define GM_GELU 1
#define GM_RES  2

// ---------------- weight tf32 pre-round ----------------
__global__ void roundw_kernel(const float* __restrict__ src,
                              float* __restrict__ dst, int n4) {
    int i = blockIdx.x * blockDim.x + threadIdx.x;
    if (i < n4) {
        float4 v = reinterpret_cast<const float4*>(src)[i];
        v.x = tf32rna_f(v.x); v.y = tf32rna_f(v.y);
        v.z = tf32rna_f(v.z); v.w = tf32rna_f(v.w);
        reinterpret_cast<float4*>(dst)[i] = v;
    }
}

__global__ void roundqkv_kernel(const float* __restrict__ wq,
                                const float* __restrict__ wk,
                                const float* __restrict__ wv,
                                float* __restrict__ dst) {
    int seg = blockIdx.y;
    const float* src = (seg == 0) ? wq : ((seg == 1) ? wk : wv);
    int n4 = DM * DM / 4;
    int i = blockIdx.x * blockDim.x + threadIdx.x;
    if (i < n4) {
        float4 v = reinterpret_cast<const float4*>(src)[i];
        v.x = tf32rna_f(v.x); v.y = tf32rna_f(v.y);
        v.z = tf32rna_f(v.z); v.w = tf32rna_f(v.w);
        reinterpret_cast<float4*>(dst)[seg * n4 + i] = v;
    }
}

// ============================================================================
// tf32 tensor-core GEMM: C[m,n] = sum_k A[m,k] * B[n,k]  (+ epilogue)
// CTA tile 128x128x32, 4 warps, 3-stage cp.async, chunk swizzle c^=(row&7).
// NEW: register double-buffered fragments — LDS for s-step s+1 overlap the
// MMAs of s-step s, hiding the 29-cycle shared-memory latency.
// ============================================================================
#define KT 32
#define TILEB (128 * KT * 4)             // 16 KB
#define GEMM_SMEM (3 * 2 * TILEB)        // 96 KB

template <int MODE>
__global__ __launch_bounds__(128, 2)
void gemm_tc(const float* __restrict__ A, const float* __restrict__ B,
             const float* __restrict__ Res, float* __restrict__ C,
             int M, int N, int K) {
    extern __shared__ char sm[];
    uint32_t smb = (uint32_t)__cvta_generic_to_shared(sm);

    int tid = threadIdx.x;
    int wid = tid >> 5;
    int lane = tid & 31;
    int wm = wid >> 1;
    int wn = wid & 1;
    int g  = lane >> 2;
    int t4 = lane & 3;

    int m0 = blockIdx.y * 128;
    int n0 = blockIdx.x * 128;
    const float* Ag = A + (size_t)m0 * K;
    const float* Bg = B + (size_t)n0 * K;

    int crow[8]; uint32_t coff[8]; int cchunk[8];
#pragma unroll
    for (int it = 0; it < 8; it++) {
        int idx = it * 128 + tid;
        int r = idx >> 3;
        int c = idx & 7;
        crow[it] = r;
        coff[it] = (uint32_t)(r * 128 + ((c ^ (r & 7)) << 4));
        cchunk[it] = c;
    }

    float acc[4][8][4];
#pragma unroll
    for (int i = 0; i < 4; i++)
#pragma unroll
        for (int j = 0; j < 8; j++)
#pragma unroll
            for (int r = 0; r < 4; r++) acc[i][j][r] = 0.f;

    int NT = K / KT;

    auto issue = [&](int t, int st) {
        uint32_t As = smb + st * 2 * TILEB;
        uint32_t Bs = As + TILEB;
        const float* Agt = Ag + t * KT;
        const float* Bgt = Bg + t * KT;
#pragma unroll
        for (int it = 0; it < 8; it++) {
            cp_async16(As + coff[it], Agt + (size_t)crow[it] * K + cchunk[it] * 4);
            cp_async16(Bs + coff[it], Bgt + (size_t)crow[it] * K + cchunk[it] * 4);
        }
    };

    // per-warp fragment base addresses (stage-relative)
    uint32_t arow_b[4], brow_b[8];
#pragma unroll
    for (int i = 0; i < 4; i++)
        arow_b[i] = (uint32_t)((wm * 64 + i * 16 + g) * 128 + (t4 << 2));
#pragma unroll
    for (int j = 0; j < 8; j++)
        brow_b[j] = (uint32_t)((wn * 64 + j * 8 + g) * 128 + (t4 << 2));

    issue(0, 0); CP_COMMIT();
    if (NT > 1) issue(1, 1);
    CP_COMMIT();

    uint32_t afb[2][4][4];
    uint32_t bfb[2][8][2];

    for (int t = 0; t < NT; t++) {
        int st = t % 3;
        CP_WAIT(1);
        __syncthreads();

        // start global loads for t+2 immediately (stage freed at t-1)
        if (t + 2 < NT) issue(t + 2, (t + 2) % 3);
        CP_COMMIT();

        uint32_t As = smb + st * 2 * TILEB;
        uint32_t Bs = As + TILEB;

        // load s=0 fragments into buffer 0
        {
            uint32_t c0 = (uint32_t)((0 ^ g) << 4);
            uint32_t c1 = (uint32_t)((1 ^ g) << 4);
#pragma unroll
            for (int i = 0; i < 4; i++) {
                uint32_t base = As + arow_b[i];
                asm volatile("ld.shared.b32 %0, [%1];" : "=r"(afb[0][i][0]) : "r"(base + c0));
                asm volatile("ld.shared.b32 %0, [%1];" : "=r"(afb[0][i][1]) : "r"(base + c0 + 1024));
                asm volatile("ld.shared.b32 %0, [%1];" : "=r"(afb[0][i][2]) : "r"(base + c1));
                asm volatile("ld.shared.b32 %0, [%1];" : "=r"(afb[0][i][3]) : "r"(base + c1 + 1024));
            }
#pragma unroll
            for (int j = 0; j < 8; j++) {
                uint32_t base = Bs + brow_b[j];
                asm volatile("ld.shared.b32 %0, [%1];" : "=r"(bfb[0][j][0]) : "r"(base + c0));
                asm volatile("ld.shared.b32 %0, [%1];" : "=r"(bfb[0][j][1]) : "r"(base + c1));
            }
        }

#pragma unroll
        for (int s = 0; s < 4; s++) {
            int cur = s & 1;
            int nxt = cur ^ 1;
            if (s < 3) {
                uint32_t c0 = (uint32_t)(((2 * (s + 1)) ^ g) << 4);
                uint32_t c1 = (uint32_t)(((2 * (s + 1) + 1) ^ g) << 4);
#pragma unroll
                for (int i = 0; i < 4; i++) {
                    uint32_t base = As + arow_b[i];
                    asm volatile("ld.shared.b32 %0, [%1];" : "=r"(afb[nxt][i][0]) : "r"(base + c0));
                    asm volatile("ld.shared.b32 %0, [%1];" : "=r"(afb[nxt][i][1]) : "r"(base + c0 + 1024));
                    asm volatile("ld.shared.b32 %0, [%1];" : "=r"(afb[nxt][i][2]) : "r"(base + c1));
                    asm volatile("ld.shared.b32 %0, [%1];" : "=r"(afb[nxt][i][3]) : "r"(base + c1 + 1024));
                }
#pragma unroll
                for (int j = 0; j < 8; j++) {
                    uint32_t base = Bs + brow_b[j];
                    asm volatile("ld.shared.b32 %0, [%1];" : "=r"(bfb[nxt][j][0]) : "r"(base + c0));
                    asm volatile("ld.shared.b32 %0, [%1];" : "=r"(bfb[nxt][j][1]) : "r"(base + c1));
                }
            }
#pragma unroll
            for (int i = 0; i < 4; i++)
#pragma unroll
                for (int j = 0; j < 8; j++)
                    mma_tf32(acc[i][j], afb[cur][i][0], afb[cur][i][1],
                             afb[cur][i][2], afb[cur][i][3],
                             bfb[cur][j][0], bfb[cur][j][1]);
        }
    }

    // epilogue
#pragma unroll
    for (int i = 0; i < 4; i++) {
#pragma unroll
        for (int j = 0; j < 8; j++) {
            int mlo = m0 + wm * 64 + i * 16 + g;
            int n   = n0 + wn * 64 + j * 8 + t4 * 2;
            float2 v0 = make_float2(acc[i][j][0], acc[i][j][1]);
            float2 v1 = make_float2(acc[i][j][2], acc[i][j][3]);
            if (MODE == GM_GELU) {
                v0.x = tf32rna_f(gelu_exact(v0.x));
                v0.y = tf32rna_f(gelu_exact(v0.y));
                v1.x = tf32rna_f(gelu_exact(v1.x));
                v1.y = tf32rna_f(gelu_exact(v1.y));
            }
            if (MODE == GM_RES) {
                float2 r0 = *reinterpret_cast<const float2*>(Res + (size_t)mlo * N + n);
                float2 r1 = *reinterpret_cast<const float2*>(Res + (size_t)(mlo + 8) * N + n);
                v0.x += r0.x; v0.y += r0.y;
                v1.x += r1.x; v1.y += r1.y;
            }
            *reinterpret_cast<float2*>(C + (size_t)mlo * N + n) = v0;
            *reinterpret_cast<float2*>(C + (size_t)(mlo + 8) * N + n) = v1;
        }
    }
}

// ---------------- rmsnorm (tf32-rounded output; feeds GEMMs only) ----------
__global__ void rmsnorm_kernel(const float* __restrict__ x,
                               const float* __restrict__ w,
                               float* __restrict__ out) {
    int row = blockIdx.x;
    int tid = threadIdx.x;
    const float4* x4 = reinterpret_cast<const float4*>(x + (size_t)row * DM);
    const float4* w4 = reinterpret_cast<const float4*>(w);
    float4* o4 = reinterpret_cast<float4*>(out + (size_t)row * DM);
    float4 v = x4[tid];
    float ss = v.x * v.x + v.y * v.y + v.z * v.z + v.w * v.w;
#pragma unroll
    for (int off = 16; off; off >>= 1)
        ss += __shfl_xor_sync(0xffffffffu, ss, off);
    __shared__ float sred[8];
    __shared__ float stot;
    if ((tid & 31) == 0) sred[tid >> 5] = ss;
    __syncthreads();
    if (tid == 0) {
        float t = 0.f;
#pragma unroll
        for (int i = 0; i < 8; i++) t += sred[i];
        stot = rsqrtf(t * (1.0f / DM) + 1e-5f);
    }
    __syncthreads();
    float rinv = stot;
    float4 wv = w4[tid];
    float4 r;
    r.x = tf32rna_f(wv.x * v.x * rinv);
    r.y = tf32rna_f(wv.y * v.y * rinv);
    r.z = tf32rna_f(wv.z * v.z * rinv);
    r.w = tf32rna_f(wv.w * v.w * rinv);
    o4[tid] = r;
}

// ============================================================================
// Tensor-core causal flash attention (tf32), cp.async double-buffered K/V.
// Bq=128 (8 warps x 16 rows), Bk=64, dk=64. Grid (16,16,2), 256 threads.
// ============================================================================
#define QS_PAD 68
#define KS_PAD 68
#define VS_PAD 72
#define PW_PAD 68
#define KV_K_F (64 * KS_PAD)
#define KV_V_F (64 * VS_PAD)
#define ATT_SMEM_FLOATS (128 * QS_PAD + 2 * KV_K_F + 2 * KV_V_F + 8 * 16 * PW_PAD)
#define ATT_SMEM_BYTES  (ATT_SMEM_FLOATS * 4)

__global__ __launch_bounds__(256)
void attn_tc(const float* __restrict__ q, const float* __restrict__ k,
             const float* __restrict__ v, float* __restrict__ o,
             int ldin, int ldo) {
    extern __shared__ float smf[];
    float* Qs  = smf;
    float* Kb  = Qs + 128 * QS_PAD;
    float* Vb  = Kb + 2 * KV_K_F;
    float* Pw  = Vb + 2 * KV_V_F;
    uint32_t Kb_u = (uint32_t)__cvta_generic_to_shared(Kb);
    uint32_t Vb_u = (uint32_t)__cvta_generic_to_shared(Vb);

    int qb  = blockIdx.x;
    int h   = blockIdx.y;
    int b   = blockIdx.z;
    int tid = threadIdx.x;
    int wid = tid >> 5;
    int lane = tid & 31;
    int g  = lane >> 2;
    int t4 = lane & 3;
    int row0 = b * 2048;
    int col0 = h * 64;

    int qrowg = qb * 128 + wid * 16;
    float* Pme = Pw + wid * 16 * PW_PAD;

    int sr = tid >> 4;
    int sc = tid & 15;

    auto stage_kv = [&](int jb, int buf) {
        uint32_t Kst = Kb_u + (uint32_t)buf * (KV_K_F * 4);
        uint32_t Vst = Vb_u + (uint32_t)buf * (KV_V_F * 4);
#pragma unroll
        for (int it = 0; it < 4; it++) {
            int r = sr + it * 16;
            size_t gi = (size_t)(row0 + jb * 64 + r) * ldin + col0 + sc * 4;
            cp_async16(Kst + (uint32_t)(r * (KS_PAD * 4) + sc * 16), k + gi);
            cp_async16(Vst + (uint32_t)(r * (VS_PAD * 4) + sc * 16), v + gi);
        }
    };

#pragma unroll
    for (int it = 0; it < 8; it++) {
        int id = it * 256 + tid;
        int r  = id >> 4;
        int c4 = id & 15;
        float4 val = *reinterpret_cast<const float4*>(
            q + (size_t)(row0 + qb * 128 + r) * ldin + col0 + c4 * 4);
        val.x = tf32rna_f(val.x * 0.125f);
        val.y = tf32rna_f(val.y * 0.125f);
        val.z = tf32rna_f(val.z * 0.125f);
        val.w = tf32rna_f(val.w * 0.125f);
        *reinterpret_cast<float4*>(&Qs[r * QS_PAD + c4 * 4]) = val;
    }

    stage_kv(0, 0); CP_COMMIT();

    float m_i[2] = {-1e30f, -1e30f};
    float l_i[2] = {0.f, 0.f};
    float oacc[8][4];
#pragma unroll
    for (int j = 0; j < 8; j++)
#pragma unroll
        for (int r = 0; r < 4; r++) oacc[j][r] = 0.f;

    int nkb = 2 * qb + 2;
    for (int jb = 0; jb < nkb; jb++) {
        int buf = jb & 1;
        __syncthreads();
        if (jb + 1 < nkb) {
            stage_kv(jb + 1, buf ^ 1);
            CP_COMMIT();
            CP_WAIT(1);
        } else {
            CP_WAIT(0);
        }
        __syncthreads();

        if (jb * 64 > qrowg + 15) continue;
        bool full_vis = (jb * 64 + 63 <= qrowg);

        const float* Ks = Kb + buf * KV_K_F;
        const float* Vs = Vb + buf * KV_V_F;

        float sacc[8][4];
#pragma unroll
        for (int j = 0; j < 8; j++)
#pragma unroll
            for (int r = 0; r < 4; r++) sacc[j][r] = 0.f;

#pragma unroll
        for (int s = 0; s < 8; s++) {
            int qr = wid * 16;
            uint32_t a0 = __float_as_uint(Qs[(qr + g) * QS_PAD + s * 8 + t4]);
            uint32_t a1 = __float_as_uint(Qs[(qr + g + 8) * QS_PAD + s * 8 + t4]);
            uint32_t a2 = __float_as_uint(Qs[(qr + g) * QS_PAD + s * 8 + t4 + 4]);
            uint32_t a3 = __float_as_uint(Qs[(qr + g + 8) * QS_PAD + s * 8 + t4 + 4]);
#pragma unroll
            for (int jn = 0; jn < 8; jn++) {
                uint32_t b0 = __float_as_uint(Ks[(jn * 8 + g) * KS_PAD + s * 8 + t4]);
                uint32_t b1 = __float_as_uint(Ks[(jn * 8 + g) * KS_PAD + s * 8 + t4 + 4]);
                mma_tf32(sacc[jn], a0, a1, a2, a3, b0, b1);
            }
        }

        if (!full_vis) {
            int colb = jb * 64 + 2 * t4;
            int r0i = qrowg + g;
            int r1i = qrowg + g + 8;
#pragma unroll
            for (int jn = 0; jn < 8; jn++) {
                int c = colb + jn * 8;
                if (c     > r0i) sacc[jn][0] = -1e30f;
                if (c + 1 > r0i) sacc[jn][1] = -1e30f;
                if (c     > r1i) sacc[jn][2] = -1e30f;
                if (c + 1 > r1i) sacc[jn][3] = -1e30f;
            }
        }

#pragma unroll
        for (int half = 0; half < 2; half++) {
            int e0 = half * 2;
            float mx = -1e30f;
#pragma unroll
            for (int jn = 0; jn < 8; jn++)
                mx = fmaxf(mx, fmaxf(sacc[jn][e0], sacc[jn][e0 + 1]));
            mx = fmaxf(mx, __shfl_xor_sync(0xffffffffu, mx, 1));
            mx = fmaxf(mx, __shfl_xor_sync(0xffffffffu, mx, 2));
            float mnew = fmaxf(m_i[half], mx);
            float alpha = __expf(m_i[half] - mnew);
            float rs = 0.f;
            int prow = (g + 8 * half) * PW_PAD + 2 * t4;
#pragma unroll
            for (int jn = 0; jn < 8; jn++) {
                float p0 = __expf(sacc[jn][e0] - mnew);
                float p1 = __expf(sacc[jn][e0 + 1] - mnew);
                rs += p0 + p1;
                float2 pv = make_float2(tf32rna_f(p0), tf32rna_f(p1));
                *reinterpret_cast<float2*>(&Pme[prow + jn * 8]) = pv;
            }
            rs += __shfl_xor_sync(0xffffffffu, rs, 1);
            rs += __shfl_xor_sync(0xffffffffu, rs, 2);
            l_i[half] = l_i[half] * alpha + rs;
            m_i[half] = mnew;
#pragma unroll
            for (int jn = 0; jn < 8; jn++) {
                oacc[jn][e0]     *= alpha;
                oacc[jn][e0 + 1] *= alpha;
            }
        }
        __syncwarp();

#pragma unroll
        for (int s = 0; s < 8; s++) {
            uint32_t a0 = __float_as_uint(Pme[g * PW_PAD + s * 8 + t4]);
            uint32_t a1 = __float_as_uint(Pme[(g + 8) * PW_PAD + s * 8 + t4]);
            uint32_t a2 = __float_as_uint(Pme[g * PW_PAD + s * 8 + t4 + 4]);
            uint32_t a3 = __float_as_uint(Pme[(g + 8) * PW_PAD + s * 8 + t4 + 4]);
#pragma unroll
            for (int jn = 0; jn < 8; jn++) {
                uint32_t b0 = __float_as_uint(Vs[(s * 8 + t4) * VS_PAD + jn * 8 + g]);
                uint32_t b1 = __float_as_uint(Vs[(s * 8 + t4 + 4) * VS_PAD + jn * 8 + g]);
                mma_tf32(oacc[jn], a0, a1, a2, a3, b0, b1);
            }
        }
        __syncwarp();
    }

#pragma unroll
    for (int half = 0; half < 2; half++) {
        float inv = 1.0f / l_i[half];
        int r = row0 + qrowg + g + 8 * half;
        int e0 = half * 2;
#pragma unroll
        for (int jn = 0; jn < 8; jn++) {
            float2 ov = make_float2(tf32rna_f(oacc[jn][e0] * inv),
                                    tf32rna_f(oacc[jn][e0 + 1] * inv));
            *reinterpret_cast<float2*>(o + (size_t)r * ldo + col0 + jn * 8 + 2 * t4) = ov;
        }
    }
}

// ---------------- launch ----------------
extern "C" void kernel_launch(void* const* d_in, const int* in_sizes, int n_in,
                              void* d_out, int out_size) {
    const float* x     = (const float*)d_in[0];
    const float* wq    = (const float*)d_in[1];
    const float* wk    = (const float*)d_in[2];
    const float* wv    = (const float*)d_in[3];
    const float* wo    = (const float*)d_in[4];
    const float* ln1_w = (const float*)d_in[5];
    const float* ln2_w = (const float*)d_in[6];
    const float* w1    = (const float*)d_in[7];
    const float* w2    = (const float*)d_in[8];
    float* out = (float*)d_out;

    float *p_xn, *p_qkv, *p_attn, *p_x1, *p_h;
    float *p_wqkv, *p_wo, *p_w1, *p_w2;
    cudaGetSymbolAddress((void**)&p_xn, g_xn);
    cudaGetSymbolAddress((void**)&p_qkv, g_qkv);
    cudaGetSymbolAddress((void**)&p_attn, g_attn);
    cudaGetSymbolAddress((void**)&p_x1, g_x1);
    cudaGetSymbolAddress((void**)&p_h, g_h);
    cudaGetSymbolAddress((void**)&p_wqkv, g_wqkv);
    cudaGetSymbolAddress((void**)&p_wo, g_wo);
    cudaGetSymbolAddress((void**)&p_w1, g_w1);
    cudaGetSymbolAddress((void**)&p_w2, g_w2);

    cudaFuncSetAttribute(gemm_tc<GM_NONE>, cudaFuncAttributeMaxDynamicSharedMemorySize, GEMM_SMEM);
    cudaFuncSetAttribute(gemm_tc<GM_GELU>, cudaFuncAttributeMaxDynamicSharedMemorySize, GEMM_SMEM);
    cudaFuncSetAttribute(gemm_tc<GM_RES>,  cudaFuncAttributeMaxDynamicSharedMemorySize, GEMM_SMEM);
    cudaFuncSetAttribute(attn_tc, cudaFuncAttributeMaxDynamicSharedMemorySize, ATT_SMEM_BYTES);

    dim3 gd_qkv(DQKV / 128, MT / 128);  // 24 x 32
    dim3 gd_1024(DM / 128, MT / 128);   // 8 x 32
    dim3 gd_ff(DFF / 128, MT / 128);    // 32 x 32

    int n4a = DM * DM / 4;
    int n4f = DFF * DM / 4;
    roundqkv_kernel<<<dim3((n4a + 255) / 256, 3), 256>>>(wq, wk, wv, p_wqkv);
    roundw_kernel<<<(n4a + 255) / 256, 256>>>(wo, p_wo, n4a);
    roundw_kernel<<<(n4f + 255) / 256, 256>>>(w1, p_w1, n4f);
    roundw_kernel<<<(n4f + 255) / 256, 256>>>(w2, p_w2, n4f);

    rmsnorm_kernel<<<MT, 256>>>(x, ln1_w, p_xn);

    gemm_tc<GM_NONE><<<gd_qkv, 128, GEMM_SMEM>>>(p_xn, p_wqkv, nullptr, p_qkv, MT, DQKV, DM);

    attn_tc<<<dim3(16, 16, 2), 256, ATT_SMEM_BYTES>>>(
        p_qkv, p_qkv + DM, p_qkv + 2 * DM, p_attn, DQKV, DM);

    gemm_tc<GM_RES><<<gd_1024, 128, GEMM_SMEM>>>(p_attn, p_wo, x, p_x1, MT, DM, DM);

    rmsnorm_kernel<<<MT, 256>>>(p_x1, ln2_w, p_xn);

    gemm_tc<GM_GELU><<<gd_ff, 128, GEMM_SMEM>>>(p_xn, p_w1, nullptr, p_h, MT, DFF, DM);

    gemm_tc<GM_RES><<<gd_1024, 128, GEMM_SMEM>>>(p_h, p_w2, p_x1, out, MT, DM, DFF);
}

// round 8
// speedup vs baseline: 1.0700x; 1.0437x over previous
#include <cuda_runtime.h>
#include <math.h>
#include <stdint.h>

#define MT   4096    // B*T rows
#define DM   1024
#define DFF  4096

// ---------------- scratch (device globals; no allocation allowed) -----------
__device__ float g_xn[MT * DM];
__device__ float g_q[MT * DM];
__device__ float g_k[MT * DM];
__device__ float g_v[MT * DM];
__device__ float g_attn[MT * DM];
__device__ float g_x1[MT * DM];
__device__ float g_h[MT * DFF];

// ---------------- helpers ----------------
__device__ __forceinline__ float tf32rna_f(float x) {
    uint32_t r;
    asm("cvt.rna.tf32.f32 %0, %1;" : "=r"(r) : "f"(x));
    return __uint_as_float(r);
}
__device__ __forceinline__ float ex2f(float x) {
    float r;
    asm("ex2.approx.f32 %0, %1;" : "=f"(r) : "f"(x));
    return r;
}

__device__ __forceinline__ void mma_tf32(float c[4], uint32_t a0, uint32_t a1,
                                         uint32_t a2, uint32_t a3,
                                         uint32_t b0, uint32_t b1) {
    asm volatile(
        "mma.sync.aligned.m16n8k8.row.col.f32.tf32.tf32.f32 "
        "{%0,%1,%2,%3}, {%4,%5,%6,%7}, {%8,%9}, {%0,%1,%2,%3};"
        : "+f"(c[0]), "+f"(c[1]), "+f"(c[2]), "+f"(c[3])
        : "r"(a0), "r"(a1), "r"(a2), "r"(a3), "r"(b0), "r"(b1));
}

__device__ __forceinline__ float gelu_exact(float x) {
    return 0.5f * x * (1.0f + erff(x * 0.70710678118654752f));
}

__device__ __forceinline__ void cp_async16(uint32_t smaddr, const void* gptr) {
    asm volatile("cp.async.cg.shared.global [%0], [%1], 16;"
                 :: "r"(smaddr), "l"(gptr) : "memory");
}
#define CP_COMMIT()  asm volatile("cp.async.commit_group;" ::: "memory")
#define CP_WAIT(n)   asm volatile("cp.async.wait_group %0;" :: "n"(n) : "memory")

#define GM_NONE 0
#define GM_GELU 1
#define GM_RES  2

// ============================================================================
// tf32 tensor-core GEMM (R7 design, unchanged): C[m,n] = sum_k A[m,k]*B[n,k]
// B may be raw fp32 (HW handles low mantissa bits in tf32 mma).
// ============================================================================
#define KT 32
#define TILEB (128 * KT * 4)             // 16 KB
#define GEMM_SMEM (3 * 2 * TILEB)        // 96 KB

template <int MODE>
__global__ __launch_bounds__(128, 2)
void gemm_tc(const float* __restrict__ A, const float* __restrict__ B,
             const float* __restrict__ Res, float* __restrict__ C,
             int M, int N, int K) {
    extern __shared__ char sm[];
    uint32_t smb = (uint32_t)__cvta_generic_to_shared(sm);

    int tid = threadIdx.x;
    int wid = tid >> 5;
    int lane = tid & 31;
    int wm = wid >> 1;
    int wn = wid & 1;
    int g  = lane >> 2;
    int t4 = lane & 3;

    int m0 = blockIdx.y * 128;
    int n0 = blockIdx.x * 128;
    const float* Ag = A + (size_t)m0 * K;
    const float* Bg = B + (size_t)n0 * K;

    int crow[8]; uint32_t coff[8]; int cchunk[8];
#pragma unroll
    for (int it = 0; it < 8; it++) {
        int idx = it * 128 + tid;
        int r = idx >> 3;
        int c = idx & 7;
        crow[it] = r;
        coff[it] = (uint32_t)(r * 128 + ((c ^ (r & 7)) << 4));
        cchunk[it] = c;
    }

    float acc[4][8][4];
#pragma unroll
    for (int i = 0; i < 4; i++)
#pragma unroll
        for (int j = 0; j < 8; j++)
#pragma unroll
            for (int r = 0; r < 4; r++) acc[i][j][r] = 0.f;

    int NT = K / KT;

    auto issue = [&](int t, int st) {
        uint32_t As = smb + st * 2 * TILEB;
        uint32_t Bs = As + TILEB;
        const float* Agt = Ag + t * KT;
        const float* Bgt = Bg + t * KT;
#pragma unroll
        for (int it = 0; it < 8; it++) {
            cp_async16(As + coff[it], Agt + (size_t)crow[it] * K + cchunk[it] * 4);
            cp_async16(Bs + coff[it], Bgt + (size_t)crow[it] * K + cchunk[it] * 4);
        }
    };

    uint32_t arow_b[4], brow_b[8];
#pragma unroll
    for (int i = 0; i < 4; i++)
        arow_b[i] = (uint32_t)((wm * 64 + i * 16 + g) * 128 + (t4 << 2));
#pragma unroll
    for (int j = 0; j < 8; j++)
        brow_b[j] = (uint32_t)((wn * 64 + j * 8 + g) * 128 + (t4 << 2));

    issue(0, 0); CP_COMMIT();
    if (NT > 1) issue(1, 1);
    CP_COMMIT();

    uint32_t afb[2][4][4];
    uint32_t bfb[2][8][2];

    for (int t = 0; t < NT; t++) {
        int st = t % 3;
        CP_WAIT(1);
        __syncthreads();

        if (t + 2 < NT) issue(t + 2, (t + 2) % 3);
        CP_COMMIT();

        uint32_t As = smb + st * 2 * TILEB;
        uint32_t Bs = As + TILEB;

        {
            uint32_t c0 = (uint32_t)((0 ^ g) << 4);
            uint32_t c1 = (uint32_t)((1 ^ g) << 4);
#pragma unroll
            for (int i = 0; i < 4; i++) {
                uint32_t base = As + arow_b[i];
                asm volatile("ld.shared.b32 %0, [%1];" : "=r"(afb[0][i][0]) : "r"(base + c0));
                asm volatile("ld.shared.b32 %0, [%1];" : "=r"(afb[0][i][1]) : "r"(base + c0 + 1024));
                asm volatile("ld.shared.b32 %0, [%1];" : "=r"(afb[0][i][2]) : "r"(base + c1));
                asm volatile("ld.shared.b32 %0, [%1];" : "=r"(afb[0][i][3]) : "r"(base + c1 + 1024));
            }
#pragma unroll
            for (int j = 0; j < 8; j++) {
                uint32_t base = Bs + brow_b[j];
                asm volatile("ld.shared.b32 %0, [%1];" : "=r"(bfb[0][j][0]) : "r"(base + c0));
                asm volatile("ld.shared.b32 %0, [%1];" : "=r"(bfb[0][j][1]) : "r"(base + c1));
            }
        }

#pragma unroll
        for (int s = 0; s < 4; s++) {
            int cur = s & 1;
            int nxt = cur ^ 1;
            if (s < 3) {
                uint32_t c0 = (uint32_t)(((2 * (s + 1)) ^ g) << 4);
                uint32_t c1 = (uint32_t)(((2 * (s + 1) + 1) ^ g) << 4);
#pragma unroll
                for (int i = 0; i < 4; i++) {
                    uint32_t base = As + arow_b[i];
                    asm volatile("ld.shared.b32 %0, [%1];" : "=r"(afb[nxt][i][0]) : "r"(base + c0));
                    asm volatile("ld.shared.b32 %0, [%1];" : "=r"(afb[nxt][i][1]) : "r"(base + c0 + 1024));
                    asm volatile("ld.shared.b32 %0, [%1];" : "=r"(afb[nxt][i][2]) : "r"(base + c1));
                    asm volatile("ld.shared.b32 %0, [%1];" : "=r"(afb[nxt][i][3]) : "r"(base + c1 + 1024));
                }
#pragma unroll
                for (int j = 0; j < 8; j++) {
                    uint32_t base = Bs + brow_b[j];
                    asm volatile("ld.shared.b32 %0, [%1];" : "=r"(bfb[nxt][j][0]) : "r"(base + c0));
                    asm volatile("ld.shared.b32 %0, [%1];" : "=r"(bfb[nxt][j][1]) : "r"(base + c1));
                }
            }
#pragma unroll
            for (int i = 0; i < 4; i++)
#pragma unroll
                for (int j = 0; j < 8; j++)
                    mma_tf32(acc[i][j], afb[cur][i][0], afb[cur][i][1],
                             afb[cur][i][2], afb[cur][i][3],
                             bfb[cur][j][0], bfb[cur][j][1]);
        }
    }

    // epilogue
#pragma unroll
    for (int i = 0; i < 4; i++) {
#pragma unroll
        for (int j = 0; j < 8; j++) {
            int mlo = m0 + wm * 64 + i * 16 + g;
            int n   = n0 + wn * 64 + j * 8 + t4 * 2;
            float2 v0 = make_float2(acc[i][j][0], acc[i][j][1]);
            float2 v1 = make_float2(acc[i][j][2], acc[i][j][3]);
            if (MODE == GM_GELU) {
                v0.x = tf32rna_f(gelu_exact(v0.x));
                v0.y = tf32rna_f(gelu_exact(v0.y));
                v1.x = tf32rna_f(gelu_exact(v1.x));
                v1.y = tf32rna_f(gelu_exact(v1.y));
            }
            if (MODE == GM_RES) {
                float2 r0 = *reinterpret_cast<const float2*>(Res + (size_t)mlo * N + n);
                float2 r1 = *reinterpret_cast<const float2*>(Res + (size_t)(mlo + 8) * N + n);
                v0.x += r0.x; v0.y += r0.y;
                v1.x += r1.x; v1.y += r1.y;
            }
            *reinterpret_cast<float2*>(C + (size_t)mlo * N + n) = v0;
            *reinterpret_cast<float2*>(C + (size_t)(mlo + 8) * N + n) = v1;
        }
    }
}

// ---------------- rmsnorm (tf32-rounded output; feeds GEMMs only) ----------
__global__ void rmsnorm_kernel(const float* __restrict__ x,
                               const float* __restrict__ w,
                               float* __restrict__ out) {
    int row = blockIdx.x;
    int tid = threadIdx.x;
    const float4* x4 = reinterpret_cast<const float4*>(x + (size_t)row * DM);
    const float4* w4 = reinterpret_cast<const float4*>(w);
    float4* o4 = reinterpret_cast<float4*>(out + (size_t)row * DM);
    float4 v = x4[tid];
    float ss = v.x * v.x + v.y * v.y + v.z * v.z + v.w * v.w;
#pragma unroll
    for (int off = 16; off; off >>= 1)
        ss += __shfl_xor_sync(0xffffffffu, ss, off);
    __shared__ float sred[8];
    __shared__ float stot;
    if ((tid & 31) == 0) sred[tid >> 5] = ss;
    __syncthreads();
    if (tid == 0) {
        float t = 0.f;
#pragma unroll
        for (int i = 0; i < 8; i++) t += sred[i];
        stot = rsqrtf(t * (1.0f / DM) + 1e-5f);
    }
    __syncthreads();
    float rinv = stot;
    float4 wv = w4[tid];
    float4 r;
    r.x = tf32rna_f(wv.x * v.x * rinv);
    r.y = tf32rna_f(wv.y * v.y * rinv);
    r.z = tf32rna_f(wv.z * v.z * rinv);
    r.w = tf32rna_f(wv.w * v.w * rinv);
    o4[tid] = r;
}

// ============================================================================
// Tensor-core causal flash attention (tf32), single-buffered K/V for
// 2 CTAs/SM occupancy. Scores computed in log2 domain (ex2 softmax).
// Bq=128 (8 warps x 16 rows), Bk=64, dk=64. Grid (16,16,2), 256 threads.
// ============================================================================
#define QS_PAD 68
#define KS_PAD 68
#define VS_PAD 72
#define PW_PAD 68
#define ATT_SMEM_FLOATS (128 * QS_PAD + 64 * KS_PAD + 64 * VS_PAD + 8 * 16 * PW_PAD)
#define ATT_SMEM_BYTES  (ATT_SMEM_FLOATS * 4)   // 105472 B -> 2 CTAs/SM

__global__ __launch_bounds__(256, 2)
void attn_tc(const float* __restrict__ q, const float* __restrict__ k,
             const float* __restrict__ v, float* __restrict__ o) {
    extern __shared__ float smf[];
    float* Qs  = smf;
    float* Ks  = Qs + 128 * QS_PAD;
    float* Vs  = Ks + 64 * KS_PAD;
    float* Pw  = Vs + 64 * VS_PAD;
    uint32_t Ks_u = (uint32_t)__cvta_generic_to_shared(Ks);
    uint32_t Vs_u = (uint32_t)__cvta_generic_to_shared(Vs);

    int qb  = blockIdx.x;
    int h   = blockIdx.y;
    int b   = blockIdx.z;
    int tid = threadIdx.x;
    int wid = tid >> 5;
    int lane = tid & 31;
    int g  = lane >> 2;
    int t4 = lane & 3;
    int row0 = b * 2048;
    int col0 = h * 64;

    int qrowg = qb * 128 + wid * 16;
    float* Pme = Pw + wid * 16 * PW_PAD;

    int sr = tid >> 4;
    int sc = tid & 15;

    // stage Q block (128x64), scaled by 0.125*log2(e), tf32-rounded
    const float QSCALE = 0.125f * 1.4426950408889634f;
#pragma unroll
    for (int it = 0; it < 8; it++) {
        int id = it * 256 + tid;
        int r  = id >> 4;
        int c4 = id & 15;
        float4 val = *reinterpret_cast<const float4*>(
            q + (size_t)(row0 + qb * 128 + r) * DM + col0 + c4 * 4);
        val.x = tf32rna_f(val.x * QSCALE);
        val.y = tf32rna_f(val.y * QSCALE);
        val.z = tf32rna_f(val.z * QSCALE);
        val.w = tf32rna_f(val.w * QSCALE);
        *reinterpret_cast<float4*>(&Qs[r * QS_PAD + c4 * 4]) = val;
    }

    float m_i[2] = {-1e30f, -1e30f};
    float l_i[2] = {0.f, 0.f};
    float oacc[8][4];
#pragma unroll
    for (int j = 0; j < 8; j++)
#pragma unroll
        for (int r = 0; r < 4; r++) oacc[j][r] = 0.f;

    int nkb = 2 * qb + 2;
    for (int jb = 0; jb < nkb; jb++) {
        __syncthreads();   // all warps done with previous K/V
        // stage K/V for this block (synchronous; 2 CTAs/SM hide the latency)
#pragma unroll
        for (int it = 0; it < 4; it++) {
            int r = sr + it * 16;
            size_t gi = (size_t)(row0 + jb * 64 + r) * DM + col0 + sc * 4;
            cp_async16(Ks_u + (uint32_t)(r * (KS_PAD * 4) + sc * 16), k + gi);
            cp_async16(Vs_u + (uint32_t)(r * (VS_PAD * 4) + sc * 16), v + gi);
        }
        CP_COMMIT();
        CP_WAIT(0);
        __syncthreads();

        if (jb * 64 > qrowg + 15) continue;
        bool full_vis = (jb * 64 + 63 <= qrowg);

        float sacc[8][4];
#pragma unroll
        for (int j = 0; j < 8; j++)
#pragma unroll
            for (int r = 0; r < 4; r++) sacc[j][r] = 0.f;

#pragma unroll
        for (int s = 0; s < 8; s++) {
            int qr = wid * 16;
            uint32_t a0 = __float_as_uint(Qs[(qr + g) * QS_PAD + s * 8 + t4]);
            uint32_t a1 = __float_as_uint(Qs[(qr + g + 8) * QS_PAD + s * 8 + t4]);
            uint32_t a2 = __float_as_uint(Qs[(qr + g) * QS_PAD + s * 8 + t4 + 4]);
            uint32_t a3 = __float_as_uint(Qs[(qr + g + 8) * QS_PAD + s * 8 + t4 + 4]);
#pragma unroll
            for (int jn = 0; jn < 8; jn++) {
                uint32_t b0 = __float_as_uint(Ks[(jn * 8 + g) * KS_PAD + s * 8 + t4]);
                uint32_t b1 = __float_as_uint(Ks[(jn * 8 + g) * KS_PAD + s * 8 + t4 + 4]);
                mma_tf32(sacc[jn], a0, a1, a2, a3, b0, b1);
            }
        }

        if (!full_vis) {
            int colb = jb * 64 + 2 * t4;
            int r0i = qrowg + g;
            int r1i = qrowg + g + 8;
#pragma unroll
            for (int jn = 0; jn < 8; jn++) {
                int c = colb + jn * 8;
                if (c     > r0i) sacc[jn][0] = -1e30f;
                if (c + 1 > r0i) sacc[jn][1] = -1e30f;
                if (c     > r1i) sacc[jn][2] = -1e30f;
                if (c + 1 > r1i) sacc[jn][3] = -1e30f;
            }
        }

        // online softmax in log2 domain
#pragma unroll
        for (int half = 0; half < 2; half++) {
            int e0 = half * 2;
            float mx = -1e30f;
#pragma unroll
            for (int jn = 0; jn < 8; jn++)
                mx = fmaxf(mx, fmaxf(sacc[jn][e0], sacc[jn][e0 + 1]));
            mx = fmaxf(mx, __shfl_xor_sync(0xffffffffu, mx, 1));
            mx = fmaxf(mx, __shfl_xor_sync(0xffffffffu, mx, 2));
            float mnew = fmaxf(m_i[half], mx);
            float alpha = ex2f(m_i[half] - mnew);
            float rs = 0.f;
            int prow = (g + 8 * half) * PW_PAD + 2 * t4;
#pragma unroll
            for (int jn = 0; jn < 8; jn++) {
                float p0 = ex2f(sacc[jn][e0] - mnew);
                float p1 = ex2f(sacc[jn][e0 + 1] - mnew);
                rs += p0 + p1;
                float2 pv = make_float2(tf32rna_f(p0), tf32rna_f(p1));
                *reinterpret_cast<float2*>(&Pme[prow + jn * 8]) = pv;
            }
            rs += __shfl_xor_sync(0xffffffffu, rs, 1);
            rs += __shfl_xor_sync(0xffffffffu, rs, 2);
            l_i[half] = l_i[half] * alpha + rs;
            m_i[half] = mnew;
#pragma unroll
            for (int jn = 0; jn < 8; jn++) {
                oacc[jn][e0]     *= alpha;
                oacc[jn][e0 + 1] *= alpha;
            }
        }
        __syncwarp();

#pragma unroll
        for (int s = 0; s < 8; s++) {
            uint32_t a0 = __float_as_uint(Pme[g * PW_PAD + s * 8 + t4]);
            uint32_t a1 = __float_as_uint(Pme[(g + 8) * PW_PAD + s * 8 + t4]);
            uint32_t a2 = __float_as_uint(Pme[g * PW_PAD + s * 8 + t4 + 4]);
            uint32_t a3 = __float_as_uint(Pme[(g + 8) * PW_PAD + s * 8 + t4 + 4]);
#pragma unroll
            for (int jn = 0; jn < 8; jn++) {
                uint32_t b0 = __float_as_uint(Vs[(s * 8 + t4) * VS_PAD + jn * 8 + g]);
                uint32_t b1 = __float_as_uint(Vs[(s * 8 + t4 + 4) * VS_PAD + jn * 8 + g]);
                mma_tf32(oacc[jn], a0, a1, a2, a3, b0, b1);
            }
        }
        __syncwarp();
    }

#pragma unroll
    for (int half = 0; half < 2; half++) {
        float inv = 1.0f / l_i[half];
        int r = row0 + qrowg + g + 8 * half;
        int e0 = half * 2;
#pragma unroll
        for (int jn = 0; jn < 8; jn++) {
            float2 ov = make_float2(tf32rna_f(oacc[jn][e0] * inv),
                                    tf32rna_f(oacc[jn][e0 + 1] * inv));
            *reinterpret_cast<float2*>(o + (size_t)r * DM + col0 + jn * 8 + 2 * t4) = ov;
        }
    }
}

// ---------------- launch ----------------
extern "C" void kernel_launch(void* const* d_in, const int* in_sizes, int n_in,
                              void* d_out, int out_size) {
    const float* x     = (const float*)d_in[0];
    const float* wq    = (const float*)d_in[1];
    const float* wk    = (const float*)d_in[2];
    const float* wv    = (const float*)d_in[3];
    const float* wo    = (const float*)d_in[4];
    const float* ln1_w = (const float*)d_in[5];
    const float* ln2_w = (const float*)d_in[6];
    const float* w1    = (const float*)d_in[7];
    const float* w2    = (const float*)d_in[8];
    float* out = (float*)d_out;

    float *p_xn, *p_q, *p_k, *p_v, *p_attn, *p_x1, *p_h;
    cudaGetSymbolAddress((void**)&p_xn, g_xn);
    cudaGetSymbolAddress((void**)&p_q, g_q);
    cudaGetSymbolAddress((void**)&p_k, g_k);
    cudaGetSymbolAddress((void**)&p_v, g_v);
    cudaGetSymbolAddress((void**)&p_attn, g_attn);
    cudaGetSymbolAddress((void**)&p_x1, g_x1);
    cudaGetSymbolAddress((void**)&p_h, g_h);

    cudaFuncSetAttribute(gemm_tc<GM_NONE>, cudaFuncAttributeMaxDynamicSharedMemorySize, GEMM_SMEM);
    cudaFuncSetAttribute(gemm_tc<GM_GELU>, cudaFuncAttributeMaxDynamicSharedMemorySize, GEMM_SMEM);
    cudaFuncSetAttribute(gemm_tc<GM_RES>,  cudaFuncAttributeMaxDynamicSharedMemorySize, GEMM_SMEM);
    cudaFuncSetAttribute(attn_tc, cudaFuncAttributeMaxDynamicSharedMemorySize, ATT_SMEM_BYTES);

    dim3 gd_1024(DM / 128, MT / 128);   // 8 x 32
    dim3 gd_ff(DFF / 128, MT / 128);    // 32 x 32

    // 1. xn1 = rmsnorm(x, ln1_w)   (RNA-rounded activations)
    rmsnorm_kernel<<<MT, 256>>>(x, ln1_w, p_xn);

    // 2. Q, K, V (weights fed raw; tf32 conversion in HW)
    gemm_tc<GM_NONE><<<gd_1024, 128, GEMM_SMEM>>>(p_xn, wq, nullptr, p_q, MT, DM, DM);
    gemm_tc<GM_NONE><<<gd_1024, 128, GEMM_SMEM>>>(p_xn, wk, nullptr, p_k, MT, DM, DM);
    gemm_tc<GM_NONE><<<gd_1024, 128, GEMM_SMEM>>>(p_xn, wv, nullptr, p_v, MT, DM, DM);

    // 3. causal flash attention
    attn_tc<<<dim3(16, 16, 2), 256, ATT_SMEM_BYTES>>>(p_q, p_k, p_v, p_attn);

    // 4. x1 = x + attn @ wo.T
    gemm_tc<GM_RES><<<gd_1024, 128, GEMM_SMEM>>>(p_attn, wo, x, p_x1, MT, DM, DM);

    // 5. xn2 = rmsnorm(x1, ln2_w)
    rmsnorm_kernel<<<MT, 256>>>(p_x1, ln2_w, p_xn);

    // 6. h = gelu(xn2 @ w1.T)
    gemm_tc<GM_GELU><<<gd_ff, 128, GEMM_SMEM>>>(p_xn, w1, nullptr, p_h, MT, DFF, DM);

    // 7. out = x1 + h @ w2.T
    gemm_tc<GM_RES><<<gd_1024, 128, GEMM_SMEM>>>(p_h, w2, p_x1, out, MT, DM, DFF);
}

// round 11
// speedup vs baseline: 1.5369x; 1.4364x over previous
#include <cuda_runtime.h>
#include <cuda_fp16.h>
#include <math.h>
#include <stdint.h>

#define MT   4096    // B*T rows
#define DM   1024
#define DFF  4096

// ---------------- scratch (device globals; no allocation allowed) -----------
__device__ __half g_xn[MT * DM];
__device__ float  g_q[MT * DM];
__device__ float  g_k[MT * DM];
__device__ float  g_v[MT * DM];
__device__ __half g_attn[MT * DM];
__device__ float  g_x1[MT * DM];
__device__ __half g_h[MT * DFF];
// fp16 weights
__device__ __half g_wq[DM * DM];
__device__ __half g_wk[DM * DM];
__device__ __half g_wv[DM * DM];
__device__ __half g_wo[DM * DM];
__device__ __half g_w1[DFF * DM];
__device__ __half g_w2[DM * DFF];

// ---------------- helpers ----------------
__device__ __forceinline__ float tf32rna_f(float x) {
    uint32_t r;
    asm("cvt.rna.tf32.f32 %0, %1;" : "=r"(r) : "f"(x));
    return __uint_as_float(r);
}
__device__ __forceinline__ float ex2f(float x) {
    float r;
    asm("ex2.approx.f32 %0, %1;" : "=f"(r) : "f"(x));
    return r;
}

__device__ __forceinline__ void mma_tf32(float c[4], uint32_t a0, uint32_t a1,
                                         uint32_t a2, uint32_t a3,
                                         uint32_t b0, uint32_t b1) {
    asm volatile(
        "mma.sync.aligned.m16n8k8.row.col.f32.tf32.tf32.f32 "
        "{%0,%1,%2,%3}, {%4,%5,%6,%7}, {%8,%9}, {%0,%1,%2,%3};"
        : "+f"(c[0]), "+f"(c[1]), "+f"(c[2]), "+f"(c[3])
        : "r"(a0), "r"(a1), "r"(a2), "r"(a3), "r"(b0), "r"(b1));
}

__device__ __forceinline__ void mma_f16(float c[4], uint32_t a0, uint32_t a1,
                                        uint32_t a2, uint32_t a3,
                                        uint32_t b0, uint32_t b1) {
    asm volatile(
        "mma.sync.aligned.m16n8k16.row.col.f32.f16.f16.f32 "
        "{%0,%1,%2,%3}, {%4,%5,%6,%7}, {%8,%9}, {%0,%1,%2,%3};"
        : "+f"(c[0]), "+f"(c[1]), "+f"(c[2]), "+f"(c[3])
        : "r"(a0), "r"(a1), "r"(a2), "r"(a3), "r"(b0), "r"(b1));
}

__device__ __forceinline__ float gelu_exact(float x) {
    return 0.5f * x * (1.0f + erff(x * 0.70710678118654752f));
}

__device__ __forceinline__ void cp_async16(uint32_t smaddr, const void* gptr) {
    asm volatile("cp.async.cg.shared.global [%0], [%1], 16;"
                 :: "r"(smaddr), "l"(gptr) : "memory");
}
#define CP_COMMIT()  asm volatile("cp.async.commit_group;" ::: "memory")
#define CP_WAIT(n)   asm volatile("cp.async.wait_group %0;" :: "n"(n) : "memory")

#define GM_NONE 0
#define GM_GELU 1
#define GM_RES  2

// ---------------- fp32 -> fp16 conversion ----------------
__global__ void cvt_h_kernel(const float* __restrict__ src,
                             __half* __restrict__ dst, int n4) {
    int i = blockIdx.x * blockDim.x + threadIdx.x;
    if (i < n4) {
        float4 v = reinterpret_cast<const float4*>(src)[i];
        __half2* d2 = reinterpret_cast<__half2*>(dst);
        d2[i * 2]     = __floats2half2_rn(v.x, v.y);
        d2[i * 2 + 1] = __floats2half2_rn(v.z, v.w);
    }
}

// ============================================================================
// fp16 tensor-core GEMM: C[m,n] = sum_k A[m,k] * B[n,k]  (+ epilogue)
// CTA tile 128x128x64, 4 warps (2Mx2N), warp tile 64x64 (4x8 m16n8k16).
// 3-stage cp.async; rows 128B (64 halves), chunk swizzle c^=(row&7).
// Register double-buffered fragments (same addressing as validated tf32 ver).
// ============================================================================
#define KT 64                            // halves per tile row (128 B)
#define TILEB (128 * KT * 2)             // 16 KB
#define GEMM_SMEM (3 * 2 * TILEB)        // 96 KB

template <int MODE>
__global__ __launch_bounds__(128, 2)
void gemm_h(const __half* __restrict__ A, const __half* __restrict__ B,
            const float* __restrict__ Res, float* __restrict__ C,
            __half* __restrict__ Ch, int M, int N, int K) {
    extern __shared__ char sm[];
    uint32_t smb = (uint32_t)__cvta_generic_to_shared(sm);

    int tid = threadIdx.x;
    int wid = tid >> 5;
    int lane = tid & 31;
    int wm = wid >> 1;
    int wn = wid & 1;
    int g  = lane >> 2;
    int t4 = lane & 3;

    int m0 = blockIdx.y * 128;
    int n0 = blockIdx.x * 128;
    const __half* Ag = A + (size_t)m0 * K;
    const __half* Bg = B + (size_t)n0 * K;

    int crow[8]; uint32_t coff[8]; int cchunk[8];
#pragma unroll
    for (int it = 0; it < 8; it++) {
        int idx = it * 128 + tid;
        int r = idx >> 3;
        int c = idx & 7;
        crow[it] = r;
        coff[it] = (uint32_t)(r * 128 + ((c ^ (r & 7)) << 4));
        cchunk[it] = c;
    }

    float acc[4][8][4];
#pragma unroll
    for (int i = 0; i < 4; i++)
#pragma unroll
        for (int j = 0; j < 8; j++)
#pragma unroll
            for (int r = 0; r < 4; r++) acc[i][j][r] = 0.f;

    int NT = K / KT;

    auto issue = [&](int t, int st) {
        uint32_t As = smb + st * 2 * TILEB;
        uint32_t Bs = As + TILEB;
        const __half* Agt = Ag + t * KT;
        const __half* Bgt = Bg + t * KT;
#pragma unroll
        for (int it = 0; it < 8; it++) {
            cp_async16(As + coff[it], Agt + (size_t)crow[it] * K + cchunk[it] * 8);
            cp_async16(Bs + coff[it], Bgt + (size_t)crow[it] * K + cchunk[it] * 8);
        }
    };

    uint32_t arow_b[4], brow_b[8];
#pragma unroll
    for (int i = 0; i < 4; i++)
        arow_b[i] = (uint32_t)((wm * 64 + i * 16 + g) * 128 + (t4 << 2));
#pragma unroll
    for (int j = 0; j < 8; j++)
        brow_b[j] = (uint32_t)((wn * 64 + j * 8 + g) * 128 + (t4 << 2));

    issue(0, 0); CP_COMMIT();
    if (NT > 1) issue(1, 1);
    CP_COMMIT();

    uint32_t afb[2][4][4];
    uint32_t bfb[2][8][2];

    for (int t = 0; t < NT; t++) {
        int st = t % 3;
        CP_WAIT(1);
        __syncthreads();

        if (t + 2 < NT) issue(t + 2, (t + 2) % 3);
        CP_COMMIT();

        uint32_t As = smb + st * 2 * TILEB;
        uint32_t Bs = As + TILEB;

        // s-step s covers k = s*16 .. s*16+15: chunks 2s (k 0-7) and 2s+1 (k 8-15)
        {
            uint32_t c0 = (uint32_t)((0 ^ g) << 4);
            uint32_t c1 = (uint32_t)((1 ^ g) << 4);
#pragma unroll
            for (int i = 0; i < 4; i++) {
                uint32_t base = As + arow_b[i];
                asm volatile("ld.shared.b32 %0, [%1];" : "=r"(afb[0][i][0]) : "r"(base + c0));
                asm volatile("ld.shared.b32 %0, [%1];" : "=r"(afb[0][i][1]) : "r"(base + c0 + 1024));
                asm volatile("ld.shared.b32 %0, [%1];" : "=r"(afb[0][i][2]) : "r"(base + c1));
                asm volatile("ld.shared.b32 %0, [%1];" : "=r"(afb[0][i][3]) : "r"(base + c1 + 1024));
            }
#pragma unroll
            for (int j = 0; j < 8; j++) {
                uint32_t base = Bs + brow_b[j];
                asm volatile("ld.shared.b32 %0, [%1];" : "=r"(bfb[0][j][0]) : "r"(base + c0));
                asm volatile("ld.shared.b32 %0, [%1];" : "=r"(bfb[0][j][1]) : "r"(base + c1));
            }
        }

#pragma unroll
        for (int s = 0; s < 4; s++) {
            int cur = s & 1;
            int nxt = cur ^ 1;
            if (s < 3) {
                uint32_t c0 = (uint32_t)(((2 * (s + 1)) ^ g) << 4);
                uint32_t c1 = (uint32_t)(((2 * (s + 1) + 1) ^ g) << 4);
#pragma unroll
                for (int i = 0; i < 4; i++) {
                    uint32_t base = As + arow_b[i];
                    asm volatile("ld.shared.b32 %0, [%1];" : "=r"(afb[nxt][i][0]) : "r"(base + c0));
                    asm volatile("ld.shared.b32 %0, [%1];" : "=r"(afb[nxt][i][1]) : "r"(base + c0 + 1024));
                    asm volatile("ld.shared.b32 %0, [%1];" : "=r"(afb[nxt][i][2]) : "r"(base + c1));
                    asm volatile("ld.shared.b32 %0, [%1];" : "=r"(afb[nxt][i][3]) : "r"(base + c1 + 1024));
                }
#pragma unroll
                for (int j = 0; j < 8; j++) {
                    uint32_t base = Bs + brow_b[j];
                    asm volatile("ld.shared.b32 %0, [%1];" : "=r"(bfb[nxt][j][0]) : "r"(base + c0));
                    asm volatile("ld.shared.b32 %0, [%1];" : "=r"(bfb[nxt][j][1]) : "r"(base + c1));
                }
            }
#pragma unroll
            for (int i = 0; i < 4; i++)
#pragma unroll
                for (int j = 0; j < 8; j++)
                    mma_f16(acc[i][j], afb[cur][i][0], afb[cur][i][1],
                            afb[cur][i][2], afb[cur][i][3],
                            bfb[cur][j][0], bfb[cur][j][1]);
        }
    }

    // epilogue
#pragma unroll
    for (int i = 0; i < 4; i++) {
#pragma unroll
        for (int j = 0; j < 8; j++) {
            int mlo = m0 + wm * 64 + i * 16 + g;
            int n   = n0 + wn * 64 + j * 8 + t4 * 2;
            float2 v0 = make_float2(acc[i][j][0], acc[i][j][1]);
            float2 v1 = make_float2(acc[i][j][2], acc[i][j][3]);
            if (MODE == GM_GELU) {
                // fp16 output for chaining into the next GEMM
                __half2 h0 = __floats2half2_rn(gelu_exact(v0.x), gelu_exact(v0.y));
                __half2 h1 = __floats2half2_rn(gelu_exact(v1.x), gelu_exact(v1.y));
                *reinterpret_cast<__half2*>(Ch + (size_t)mlo * N + n) = h0;
                *reinterpret_cast<__half2*>(Ch + (size_t)(mlo + 8) * N + n) = h1;
            } else {
                if (MODE == GM_RES) {
                    float2 r0 = *reinterpret_cast<const float2*>(Res + (size_t)mlo * N + n);
                    float2 r1 = *reinterpret_cast<const float2*>(Res + (size_t)(mlo + 8) * N + n);
                    v0.x += r0.x; v0.y += r0.y;
                    v1.x += r1.x; v1.y += r1.y;
                }
                *reinterpret_cast<float2*>(C + (size_t)mlo * N + n) = v0;
                *reinterpret_cast<float2*>(C + (size_t)(mlo + 8) * N + n) = v1;
            }
        }
    }
}

// ---------------- rmsnorm: fp32 in, fp16 out ----------------
__global__ void rmsnorm_kernel(const float* __restrict__ x,
                               const float* __restrict__ w,
                               __half* __restrict__ out) {
    int row = blockIdx.x;
    int tid = threadIdx.x;
    const float4* x4 = reinterpret_cast<const float4*>(x + (size_t)row * DM);
    const float4* w4 = reinterpret_cast<const float4*>(w);
    float4 v = x4[tid];
    float ss = v.x * v.x + v.y * v.y + v.z * v.z + v.w * v.w;
#pragma unroll
    for (int off = 16; off; off >>= 1)
        ss += __shfl_xor_sync(0xffffffffu, ss, off);
    __shared__ float sred[8];
    __shared__ float stot;
    if ((tid & 31) == 0) sred[tid >> 5] = ss;
    __syncthreads();
    if (tid == 0) {
        float t = 0.f;
#pragma unroll
        for (int i = 0; i < 8; i++) t += sred[i];
        stot = rsqrtf(t * (1.0f / DM) + 1e-5f);
    }
    __syncthreads();
    float rinv = stot;
    float4 wv = w4[tid];
    __half2* o2 = reinterpret_cast<__half2*>(out + (size_t)row * DM);
    o2[tid * 2]     = __floats2half2_rn(wv.x * v.x * rinv, wv.y * v.y * rinv);
    o2[tid * 2 + 1] = __floats2half2_rn(wv.z * v.z * rinv, wv.w * v.w * rinv);
}

// ============================================================================
// Tensor-core causal flash attention (tf32 math, unchanged from R8),
// fp32 q/k/v inputs, fp16 output (feeds the wo GEMM).
// ============================================================================
#define QS_PAD 68
#define KS_PAD 68
#define VS_PAD 72
#define PW_PAD 68
#define ATT_SMEM_FLOATS (128 * QS_PAD + 64 * KS_PAD + 64 * VS_PAD + 8 * 16 * PW_PAD)
#define ATT_SMEM_BYTES  (ATT_SMEM_FLOATS * 4)   // ~103 KB -> 2 CTAs/SM

__global__ __launch_bounds__(256, 2)
void attn_tc(const float* __restrict__ q, const float* __restrict__ k,
             const float* __restrict__ v, __half* __restrict__ o) {
    extern __shared__ float smf[];
    float* Qs  = smf;
    float* Ks  = Qs + 128 * QS_PAD;
    float* Vs  = Ks + 64 * KS_PAD;
    float* Pw  = Vs + 64 * VS_PAD;
    uint32_t Ks_u = (uint32_t)__cvta_generic_to_shared(Ks);
    uint32_t Vs_u = (uint32_t)__cvta_generic_to_shared(Vs);

    int qb  = blockIdx.x;
    int h   = blockIdx.y;
    int b   = blockIdx.z;
    int tid = threadIdx.x;
    int wid = tid >> 5;
    int lane = tid & 31;
    int g  = lane >> 2;
    int t4 = lane & 3;
    int row0 = b * 2048;
    int col0 = h * 64;

    int qrowg = qb * 128 + wid * 16;
    float* Pme = Pw + wid * 16 * PW_PAD;

    int sr = tid >> 4;
    int sc = tid & 15;

    const float QSCALE = 0.125f * 1.4426950408889634f;
#pragma unroll
    for (int it = 0; it < 8; it++) {
        int id = it * 256 + tid;
        int r  = id >> 4;
        int c4 = id & 15;
        float4 val = *reinterpret_cast<const float4*>(
            q + (size_t)(row0 + qb * 128 + r) * DM + col0 + c4 * 4);
        val.x = tf32rna_f(val.x * QSCALE);
        val.y = tf32rna_f(val.y * QSCALE);
        val.z = tf32rna_f(val.z * QSCALE);
        val.w = tf32rna_f(val.w * QSCALE);
        *reinterpret_cast<float4*>(&Qs[r * QS_PAD + c4 * 4]) = val;
    }

    float m_i[2] = {-1e30f, -1e30f};
    float l_i[2] = {0.f, 0.f};
    float oacc[8][4];
#pragma unroll
    for (int j = 0; j < 8; j++)
#pragma unroll
        for (int r = 0; r < 4; r++) oacc[j][r] = 0.f;

    int nkb = 2 * qb + 2;
    for (int jb = 0; jb < nkb; jb++) {
        __syncthreads();
#pragma unroll
        for (int it = 0; it < 4; it++) {
            int r = sr + it * 16;
            size_t gi = (size_t)(row0 + jb * 64 + r) * DM + col0 + sc * 4;
            cp_async16(Ks_u + (uint32_t)(r * (KS_PAD * 4) + sc * 16), k + gi);
            cp_async16(Vs_u + (uint32_t)(r * (VS_PAD * 4) + sc * 16), v + gi);
        }
        CP_COMMIT();
        CP_WAIT(0);
        __syncthreads();

        if (jb * 64 > qrowg + 15) continue;
        bool full_vis = (jb * 64 + 63 <= qrowg);

        float sacc[8][4];
#pragma unroll
        for (int j = 0; j < 8; j++)
#pragma unroll
            for (int r = 0; r < 4; r++) sacc[j][r] = 0.f;

#pragma unroll
        for (int s = 0; s < 8; s++) {
            int qr = wid * 16;
            uint32_t a0 = __float_as_uint(Qs[(qr + g) * QS_PAD + s * 8 + t4]);
            uint32_t a1 = __float_as_uint(Qs[(qr + g + 8) * QS_PAD + s * 8 + t4]);
            uint32_t a2 = __float_as_uint(Qs[(qr + g) * QS_PAD + s * 8 + t4 + 4]);
            uint32_t a3 = __float_as_uint(Qs[(qr + g + 8) * QS_PAD + s * 8 + t4 + 4]);
#pragma unroll
            for (int jn = 0; jn < 8; jn++) {
                uint32_t b0 = __float_as_uint(Ks[(jn * 8 + g) * KS_PAD + s * 8 + t4]);
                uint32_t b1 = __float_as_uint(Ks[(jn * 8 + g) * KS_PAD + s * 8 + t4 + 4]);
                mma_tf32(sacc[jn], a0, a1, a2, a3, b0, b1);
            }
        }

        if (!full_vis) {
            int colb = jb * 64 + 2 * t4;
            int r0i = qrowg + g;
            int r1i = qrowg + g + 8;
#pragma unroll
            for (int jn = 0; jn < 8; jn++) {
                int c = colb + jn * 8;
                if (c     > r0i) sacc[jn][0] = -1e30f;
                if (c + 1 > r0i) sacc[jn][1] = -1e30f;
                if (c     > r1i) sacc[jn][2] = -1e30f;
                if (c + 1 > r1i) sacc[jn][3] = -1e30f;
            }
        }

#pragma unroll
        for (int half = 0; half < 2; half++) {
            int e0 = half * 2;
            float mx = -1e30f;
#pragma unroll
            for (int jn = 0; jn < 8; jn++)
                mx = fmaxf(mx, fmaxf(sacc[jn][e0], sacc[jn][e0 + 1]));
            mx = fmaxf(mx, __shfl_xor_sync(0xffffffffu, mx, 1));
            mx = fmaxf(mx, __shfl_xor_sync(0xffffffffu, mx, 2));
            float mnew = fmaxf(m_i[half], mx);
            float alpha = ex2f(m_i[half] - mnew);
            float rs = 0.f;
            int prow = (g + 8 * half) * PW_PAD + 2 * t4;
#pragma unroll
            for (int jn = 0; jn < 8; jn++) {
                float p0 = ex2f(sacc[jn][e0] - mnew);
                float p1 = ex2f(sacc[jn][e0 + 1] - mnew);
                rs += p0 + p1;
                float2 pv = make_float2(tf32rna_f(p0), tf32rna_f(p1));
                *reinterpret_cast<float2*>(&Pme[prow + jn * 8]) = pv;
            }
            rs += __shfl_xor_sync(0xffffffffu, rs, 1);
            rs += __shfl_xor_sync(0xffffffffu, rs, 2);
            l_i[half] = l_i[half] * alpha + rs;
            m_i[half] = mnew;
#pragma unroll
            for (int jn = 0; jn < 8; jn++) {
                oacc[jn][e0]     *= alpha;
                oacc[jn][e0 + 1] *= alpha;
            }
        }
        __syncwarp();

#pragma unroll
        for (int s = 0; s < 8; s++) {
            uint32_t a0 = __float_as_uint(Pme[g * PW_PAD + s * 8 + t4]);
            uint32_t a1 = __float_as_uint(Pme[(g + 8) * PW_PAD + s * 8 + t4]);
            uint32_t a2 = __float_as_uint(Pme[g * PW_PAD + s * 8 + t4 + 4]);
            uint32_t a3 = __float_as_uint(Pme[(g + 8) * PW_PAD + s * 8 + t4 + 4]);
#pragma unroll
            for (int jn = 0; jn < 8; jn++) {
                uint32_t b0 = __float_as_uint(Vs[(s * 8 + t4) * VS_PAD + jn * 8 + g]);
                uint32_t b1 = __float_as_uint(Vs[(s * 8 + t4 + 4) * VS_PAD + jn * 8 + g]);
                mma_tf32(oacc[jn], a0, a1, a2, a3, b0, b1);
            }
        }
        __syncwarp();
    }

    // fp16 output
#pragma unroll
    for (int half = 0; half < 2; half++) {
        float inv = 1.0f / l_i[half];
        int r = row0 + qrowg + g + 8 * half;
        int e0 = half * 2;
#pragma unroll
        for (int jn = 0; jn < 8; jn++) {
            __half2 ov = __floats2half2_rn(oacc[jn][e0] * inv, oacc[jn][e0 + 1] * inv);
            *reinterpret_cast<__half2*>(o + (size_t)r * DM + col0 + jn * 8 + 2 * t4) = ov;
        }
    }
}

// ---------------- launch ----------------
extern "C" void kernel_launch(void* const* d_in, const int* in_sizes, int n_in,
                              void* d_out, int out_size) {
    const float* x     = (const float*)d_in[0];
    const float* wq    = (const float*)d_in[1];
    const float* wk    = (const float*)d_in[2];
    const float* wv    = (const float*)d_in[3];
    const float* wo    = (const float*)d_in[4];
    const float* ln1_w = (const float*)d_in[5];
    const float* ln2_w = (const float*)d_in[6];
    const float* w1    = (const float*)d_in[7];
    const float* w2    = (const float*)d_in[8];
    float* out = (float*)d_out;

    __half *p_xn, *p_attn, *p_h;
    __half *p_wq, *p_wk, *p_wv, *p_wo, *p_w1, *p_w2;
    float *p_q, *p_k, *p_v, *p_x1;
    cudaGetSymbolAddress((void**)&p_xn, g_xn);
    cudaGetSymbolAddress((void**)&p_q, g_q);
    cudaGetSymbolAddress((void**)&p_k, g_k);
    cudaGetSymbolAddress((void**)&p_v, g_v);
    cudaGetSymbolAddress((void**)&p_attn, g_attn);
    cudaGetSymbolAddress((void**)&p_x1, g_x1);
    cudaGetSymbolAddress((void**)&p_h, g_h);
    cudaGetSymbolAddress((void**)&p_wq, g_wq);
    cudaGetSymbolAddress((void**)&p_wk, g_wk);
    cudaGetSymbolAddress((void**)&p_wv, g_wv);
    cudaGetSymbolAddress((void**)&p_wo, g_wo);
    cudaGetSymbolAddress((void**)&p_w1, g_w1);
    cudaGetSymbolAddress((void**)&p_w2, g_w2);

    cudaFuncSetAttribute(gemm_h<GM_NONE>, cudaFuncAttributeMaxDynamicSharedMemorySize, GEMM_SMEM);
    cudaFuncSetAttribute(gemm_h<GM_GELU>, cudaFuncAttributeMaxDynamicSharedMemorySize, GEMM_SMEM);
    cudaFuncSetAttribute(gemm_h<GM_RES>,  cudaFuncAttributeMaxDynamicSharedMemorySize, GEMM_SMEM);
    cudaFuncSetAttribute(attn_tc, cudaFuncAttributeMaxDynamicSharedMemorySize, ATT_SMEM_BYTES);

    dim3 gd_1024(DM / 128, MT / 128);   // 8 x 32
    dim3 gd_ff(DFF / 128, MT / 128);    // 32 x 32

    // 0. weights -> fp16
    int n4a = DM * DM / 4;
    int n4f = DFF * DM / 4;
    cvt_h_kernel<<<(n4a + 255) / 256, 256>>>(wq, p_wq, n4a);
    cvt_h_kernel<<<(n4a + 255) / 256, 256>>>(wk, p_wk, n4a);
    cvt_h_kernel<<<(n4a + 255) / 256, 256>>>(wv, p_wv, n4a);
    cvt_h_kernel<<<(n4a + 255) / 256, 256>>>(wo, p_wo, n4a);
    cvt_h_kernel<<<(n4f + 255) / 256, 256>>>(w1, p_w1, n4f);
    cvt_h_kernel<<<(n4f + 255) / 256, 256>>>(w2, p_w2, n4f);

    // 1. xn1 = rmsnorm(x, ln1_w) -> fp16
    rmsnorm_kernel<<<MT, 256>>>(x, ln1_w, p_xn);

    // 2. Q, K, V (fp16 x fp16 -> fp32)
    gemm_h<GM_NONE><<<gd_1024, 128, GEMM_SMEM>>>(p_xn, p_wq, nullptr, p_q, nullptr, MT, DM, DM);
    gemm_h<GM_NONE><<<gd_1024, 128, GEMM_SMEM>>>(p_xn, p_wk, nullptr, p_k, nullptr, MT, DM, DM);
    gemm_h<GM_NONE><<<gd_1024, 128, GEMM_SMEM>>>(p_xn, p_wv, nullptr, p_v, nullptr, MT, DM, DM);

    // 3. causal flash attention (fp32 in, fp16 out)
    attn_tc<<<dim3(16, 16, 2), 256, ATT_SMEM_BYTES>>>(p_q, p_k, p_v, p_attn);

    // 4. x1 = x + attn @ wo.T  (fp32 out)
    gemm_h<GM_RES><<<gd_1024, 128, GEMM_SMEM>>>(p_attn, p_wo, x, p_x1, nullptr, MT, DM, DM);

    // 5. xn2 = rmsnorm(x1, ln2_w) -> fp16
    rmsnorm_kernel<<<MT, 256>>>(p_x1, ln2_w, p_xn);

    // 6. h = gelu(xn2 @ w1.T) -> fp16
    gemm_h<GM_GELU><<<gd_ff, 128, GEMM_SMEM>>>(p_xn, p_w1, nullptr, nullptr, p_h, MT, DFF, DM);

    // 7. out = x1 + h @ w2.T  (fp32 out)
    gemm_h<GM_RES><<<gd_1024, 128, GEMM_SMEM>>>(p_h, p_w2, p_x1, out, nullptr, MT, DM, DFF);
}

// round 13
// speedup vs baseline: 1.8411x; 1.1980x over previous
#include <cuda_runtime.h>
#include <cuda_fp16.h>
#include <math.h>
#include <stdint.h>

#define MT   4096    // B*T rows
#define DM   1024
#define DFF  4096

// ---------------- scratch (device globals; no allocation allowed) -----------
__device__ __half g_xn[MT * DM];
__device__ __half g_q[MT * DM];
__device__ __half g_k[MT * DM];
__device__ __half g_v[MT * DM];
__device__ __half g_attn[MT * DM];
__device__ float  g_x1[MT * DM];
__device__ __half g_h[MT * DFF];
// fp16 weights
__device__ __half g_wq[DM * DM];
__device__ __half g_wk[DM * DM];
__device__ __half g_wv[DM * DM];
__device__ __half g_wo[DM * DM];
__device__ __half g_w1[DFF * DM];
__device__ __half g_w2[DM * DFF];

// ---------------- helpers ----------------
__device__ __forceinline__ float ex2f(float x) {
    float r;
    asm("ex2.approx.f32 %0, %1;" : "=f"(r) : "f"(x));
    return r;
}

__device__ __forceinline__ void mma_f16(float c[4], uint32_t a0, uint32_t a1,
                                        uint32_t a2, uint32_t a3,
                                        uint32_t b0, uint32_t b1) {
    asm volatile(
        "mma.sync.aligned.m16n8k16.row.col.f32.f16.f16.f32 "
        "{%0,%1,%2,%3}, {%4,%5,%6,%7}, {%8,%9}, {%0,%1,%2,%3};"
        : "+f"(c[0]), "+f"(c[1]), "+f"(c[2]), "+f"(c[3])
        : "r"(a0), "r"(a1), "r"(a2), "r"(a3), "r"(b0), "r"(b1));
}

__device__ __forceinline__ float gelu_exact(float x) {
    return 0.5f * x * (1.0f + erff(x * 0.70710678118654752f));
}

__device__ __forceinline__ void cp_async16(uint32_t smaddr, const void* gptr) {
    asm volatile("cp.async.cg.shared.global [%0], [%1], 16;"
                 :: "r"(smaddr), "l"(gptr) : "memory");
}
#define CP_COMMIT()  asm volatile("cp.async.commit_group;" ::: "memory")
#define CP_WAIT(n)   asm volatile("cp.async.wait_group %0;" :: "n"(n) : "memory")

#define GM_NONE 0
#define GM_GELU 1
#define GM_RES  2
#define GM_H16  3

// ---------------- all-weights fp32 -> fp16 conversion (one launch) ----------
#define NS (DM * DM / 4)      // 262144  (2^18) float4 per small weight
#define NB (DFF * DM / 4)     // 1048576 (2^20) float4 per big weight
#define NTOT (4 * NS + 2 * NB)

__global__ void cvt_all_kernel(const float* __restrict__ wq, const float* __restrict__ wk,
                               const float* __restrict__ wv, const float* __restrict__ wo,
                               const float* __restrict__ w1, const float* __restrict__ w2,
                               __half* dq, __half* dk, __half* dv, __half* dwo,
                               __half* d1, __half* d2) {
    int i = blockIdx.x * blockDim.x + threadIdx.x;
    if (i >= NTOT) return;
    const float* s;
    __half* d;
    int off;
    if (i < 4 * NS) {
        int seg = i >> 18;
        off = i & (NS - 1);
        s = (seg == 0) ? wq : (seg == 1) ? wk : (seg == 2) ? wv : wo;
        d = (seg == 0) ? dq : (seg == 1) ? dk : (seg == 2) ? dv : dwo;
    } else {
        int j = i - 4 * NS;
        int seg = j >> 20;
        off = j & (NB - 1);
        s = seg ? w2 : w1;
        d = seg ? d2 : d1;
    }
    float4 v = reinterpret_cast<const float4*>(s)[off];
    __half2* d2p = reinterpret_cast<__half2*>(d);
    d2p[off * 2]     = __floats2half2_rn(v.x, v.y);
    d2p[off * 2 + 1] = __floats2half2_rn(v.z, v.w);
}

// ============================================================================
// fp16 tensor-core GEMM (R11 design + GM_H16 mode)
// ============================================================================
#define KT 64                            // halves per tile row (128 B)
#define TILEB (128 * KT * 2)             // 16 KB
#define GEMM_SMEM (3 * 2 * TILEB)        // 96 KB

template <int MODE>
__global__ __launch_bounds__(128, 2)
void gemm_h(const __half* __restrict__ A, const __half* __restrict__ B,
            const float* __restrict__ Res, float* __restrict__ C,
            __half* __restrict__ Ch, int M, int N, int K) {
    extern __shared__ char sm[];
    uint32_t smb = (uint32_t)__cvta_generic_to_shared(sm);

    int tid = threadIdx.x;
    int wid = tid >> 5;
    int lane = tid & 31;
    int wm = wid >> 1;
    int wn = wid & 1;
    int g  = lane >> 2;
    int t4 = lane & 3;

    int m0 = blockIdx.y * 128;
    int n0 = blockIdx.x * 128;
    const __half* Ag = A + (size_t)m0 * K;
    const __half* Bg = B + (size_t)n0 * K;

    int crow[8]; uint32_t coff[8]; int cchunk[8];
#pragma unroll
    for (int it = 0; it < 8; it++) {
        int idx = it * 128 + tid;
        int r = idx >> 3;
        int c = idx & 7;
        crow[it] = r;
        coff[it] = (uint32_t)(r * 128 + ((c ^ (r & 7)) << 4));
        cchunk[it] = c;
    }

    float acc[4][8][4];
#pragma unroll
    for (int i = 0; i < 4; i++)
#pragma unroll
        for (int j = 0; j < 8; j++)
#pragma unroll
            for (int r = 0; r < 4; r++) acc[i][j][r] = 0.f;

    int NT = K / KT;

    auto issue = [&](int t, int st) {
        uint32_t As = smb + st * 2 * TILEB;
        uint32_t Bs = As + TILEB;
        const __half* Agt = Ag + t * KT;
        const __half* Bgt = Bg + t * KT;
#pragma unroll
        for (int it = 0; it < 8; it++) {
            cp_async16(As + coff[it], Agt + (size_t)crow[it] * K + cchunk[it] * 8);
            cp_async16(Bs + coff[it], Bgt + (size_t)crow[it] * K + cchunk[it] * 8);
        }
    };

    uint32_t arow_b[4], brow_b[8];
#pragma unroll
    for (int i = 0; i < 4; i++)
        arow_b[i] = (uint32_t)((wm * 64 + i * 16 + g) * 128 + (t4 << 2));
#pragma unroll
    for (int j = 0; j < 8; j++)
        brow_b[j] = (uint32_t)((wn * 64 + j * 8 + g) * 128 + (t4 << 2));

    issue(0, 0); CP_COMMIT();
    if (NT > 1) issue(1, 1);
    CP_COMMIT();

    uint32_t afb[2][4][4];
    uint32_t bfb[2][8][2];

    for (int t = 0; t < NT; t++) {
        int st = t % 3;
        CP_WAIT(1);
        __syncthreads();

        if (t + 2 < NT) issue(t + 2, (t + 2) % 3);
        CP_COMMIT();

        uint32_t As = smb + st * 2 * TILEB;
        uint32_t Bs = As + TILEB;

        {
            uint32_t c0 = (uint32_t)((0 ^ g) << 4);
            uint32_t c1 = (uint32_t)((1 ^ g) << 4);
#pragma unroll
            for (int i = 0; i < 4; i++) {
                uint32_t base = As + arow_b[i];
                asm volatile("ld.shared.b32 %0, [%1];" : "=r"(afb[0][i][0]) : "r"(base + c0));
                asm volatile("ld.shared.b32 %0, [%1];" : "=r"(afb[0][i][1]) : "r"(base + c0 + 1024));
                asm volatile("ld.shared.b32 %0, [%1];" : "=r"(afb[0][i][2]) : "r"(base + c1));
                asm volatile("ld.shared.b32 %0, [%1];" : "=r"(afb[0][i][3]) : "r"(base + c1 + 1024));
            }
#pragma unroll
            for (int j = 0; j < 8; j++) {
                uint32_t base = Bs + brow_b[j];
                asm volatile("ld.shared.b32 %0, [%1];" : "=r"(bfb[0][j][0]) : "r"(base + c0));
                asm volatile("ld.shared.b32 %0, [%1];" : "=r"(bfb[0][j][1]) : "r"(base + c1));
            }
        }

#pragma unroll
        for (int s = 0; s < 4; s++) {
            int cur = s & 1;
            int nxt = cur ^ 1;
            if (s < 3) {
                uint32_t c0 = (uint32_t)(((2 * (s + 1)) ^ g) << 4);
                uint32_t c1 = (uint32_t)(((2 * (s + 1) + 1) ^ g) << 4);
#pragma unroll
                for (int i = 0; i < 4; i++) {
                    uint32_t base = As + arow_b[i];
                    asm volatile("ld.shared.b32 %0, [%1];" : "=r"(afb[nxt][i][0]) : "r"(base + c0));
                    asm volatile("ld.shared.b32 %0, [%1];" : "=r"(afb[nxt][i][1]) : "r"(base + c0 + 1024));
                    asm volatile("ld.shared.b32 %0, [%1];" : "=r"(afb[nxt][i][2]) : "r"(base + c1));
                    asm volatile("ld.shared.b32 %0, [%1];" : "=r"(afb[nxt][i][3]) : "r"(base + c1 + 1024));
                }
#pragma unroll
                for (int j = 0; j < 8; j++) {
                    uint32_t base = Bs + brow_b[j];
                    asm volatile("ld.shared.b32 %0, [%1];" : "=r"(bfb[nxt][j][0]) : "r"(base + c0));
                    asm volatile("ld.shared.b32 %0, [%1];" : "=r"(bfb[nxt][j][1]) : "r"(base + c1));
                }
            }
#pragma unroll
            for (int i = 0; i < 4; i++)
#pragma unroll
                for (int j = 0; j < 8; j++)
                    mma_f16(acc[i][j], afb[cur][i][0], afb[cur][i][1],
                            afb[cur][i][2], afb[cur][i][3],
                            bfb[cur][j][0], bfb[cur][j][1]);
        }
    }

    // epilogue
#pragma unroll
    for (int i = 0; i < 4; i++) {
#pragma unroll
        for (int j = 0; j < 8; j++) {
            int mlo = m0 + wm * 64 + i * 16 + g;
            int n   = n0 + wn * 64 + j * 8 + t4 * 2;
            float2 v0 = make_float2(acc[i][j][0], acc[i][j][1]);
            float2 v1 = make_float2(acc[i][j][2], acc[i][j][3]);
            if (MODE == GM_GELU) {
                __half2 h0 = __floats2half2_rn(gelu_exact(v0.x), gelu_exact(v0.y));
                __half2 h1 = __floats2half2_rn(gelu_exact(v1.x), gelu_exact(v1.y));
                *reinterpret_cast<__half2*>(Ch + (size_t)mlo * N + n) = h0;
                *reinterpret_cast<__half2*>(Ch + (size_t)(mlo + 8) * N + n) = h1;
            } else if (MODE == GM_H16) {
                *reinterpret_cast<__half2*>(Ch + (size_t)mlo * N + n) =
                    __floats2half2_rn(v0.x, v0.y);
                *reinterpret_cast<__half2*>(Ch + (size_t)(mlo + 8) * N + n) =
                    __floats2half2_rn(v1.x, v1.y);
            } else {
                if (MODE == GM_RES) {
                    float2 r0 = *reinterpret_cast<const float2*>(Res + (size_t)mlo * N + n);
                    float2 r1 = *reinterpret_cast<const float2*>(Res + (size_t)(mlo + 8) * N + n);
                    v0.x += r0.x; v0.y += r0.y;
                    v1.x += r1.x; v1.y += r1.y;
                }
                *reinterpret_cast<float2*>(C + (size_t)mlo * N + n) = v0;
                *reinterpret_cast<float2*>(C + (size_t)(mlo + 8) * N + n) = v1;
            }
        }
    }
}

// ---------------- rmsnorm: fp32 in, fp16 out ----------------
__global__ void rmsnorm_kernel(const float* __restrict__ x,
                               const float* __restrict__ w,
                               __half* __restrict__ out) {
    int row = blockIdx.x;
    int tid = threadIdx.x;
    const float4* x4 = reinterpret_cast<const float4*>(x + (size_t)row * DM);
    const float4* w4 = reinterpret_cast<const float4*>(w);
    float4 v = x4[tid];
    float ss = v.x * v.x + v.y * v.y + v.z * v.z + v.w * v.w;
#pragma unroll
    for (int off = 16; off; off >>= 1)
        ss += __shfl_xor_sync(0xffffffffu, ss, off);
    __shared__ float sred[8];
    __shared__ float stot;
    if ((tid & 31) == 0) sred[tid >> 5] = ss;
    __syncthreads();
    if (tid == 0) {
        float t = 0.f;
#pragma unroll
        for (int i = 0; i < 8; i++) t += sred[i];
        stot = rsqrtf(t * (1.0f / DM) + 1e-5f);
    }
    __syncthreads();
    float rinv = stot;
    float4 wv = w4[tid];
    __half2* o2 = reinterpret_cast<__half2*>(out + (size_t)row * DM);
    o2[tid * 2]     = __floats2half2_rn(wv.x * v.x * rinv, wv.y * v.y * rinv);
    o2[tid * 2 + 1] = __floats2half2_rn(wv.z * v.z * rinv, wv.w * v.w * rinv);
}

// ============================================================================
// fp16 tensor-core causal flash attention.
// Bq=128 (8 warps x 16 rows), Bk=64, dk=64. Grid (16,16,2), 256 threads.
// S = QK^T and O += PV via mma.m16n8k16.f16 (fp32 accum).
// K [key][dk] is col-major B for S (direct LDS); V [key][dk] is row-major B
// for PV -> ldmatrix.x2.trans. log2-domain softmax (ex2).
// ============================================================================
#define QS_PADH 72
#define KS_PADH 72
#define VS_PADH 72
#define PW_PADH 72
#define ATT_SMEM_BYTES ((128 * QS_PADH + 64 * KS_PADH + 64 * VS_PADH + 128 * PW_PADH) * 2)

__global__ __launch_bounds__(256, 2)
void attn_h(const __half* __restrict__ q, const __half* __restrict__ k,
            const __half* __restrict__ v, __half* __restrict__ o) {
    extern __shared__ __half smh[];
    __half* Qs = smh;                         // 128 x 72
    __half* Ks = Qs + 128 * QS_PADH;          // 64 x 72
    __half* Vs = Ks + 64 * KS_PADH;           // 64 x 72
    __half* Pw = Vs + 64 * VS_PADH;           // 8 warps x 16 x 72
    uint32_t Ks_u = (uint32_t)__cvta_generic_to_shared(Ks);
    uint32_t Vs_u = (uint32_t)__cvta_generic_to_shared(Vs);

    int qb  = blockIdx.x;
    int h   = blockIdx.y;
    int b   = blockIdx.z;
    int tid = threadIdx.x;
    int wid = tid >> 5;
    int lane = tid & 31;
    int g  = lane >> 2;
    int t4 = lane & 3;
    int row0 = b * 2048;
    int col0 = h * 64;

    int qrowg = qb * 128 + wid * 16;
    __half* Pme = Pw + wid * 16 * PW_PADH;
    int lrow = (lane & 7) + ((lane >> 3) & 1) * 8;   // ldmatrix x2 row pattern

    // stage Q (128x64 halves), scale by 0.125*log2(e) in fp32, store fp16
    const float QSCALE = 0.125f * 1.4426950408889634f;
#pragma unroll
    for (int it = 0; it < 8; it++) {
        int id = it * 256 + tid;
        int r  = id >> 4;
        int c  = id & 15;                    // uint2 chunk: 4 halves
        uint2 raw = *reinterpret_cast<const uint2*>(
            q + (size_t)(row0 + qb * 128 + r) * DM + col0 + c * 4);
        __half2 h0 = *reinterpret_cast<__half2*>(&raw.x);
        __half2 h1 = *reinterpret_cast<__half2*>(&raw.y);
        float2 f0 = __half22float2(h0);
        float2 f1 = __half22float2(h1);
        __half2 s0 = __floats2half2_rn(f0.x * QSCALE, f0.y * QSCALE);
        __half2 s1 = __floats2half2_rn(f1.x * QSCALE, f1.y * QSCALE);
        uint2 outw;
        outw.x = *reinterpret_cast<uint32_t*>(&s0);
        outw.y = *reinterpret_cast<uint32_t*>(&s1);
        *reinterpret_cast<uint2*>(&Qs[r * QS_PADH + c * 4]) = outw;
    }

    float m_i[2] = {-1e30f, -1e30f};
    float l_i[2] = {0.f, 0.f};
    float oacc[8][4];
#pragma unroll
    for (int j = 0; j < 8; j++)
#pragma unroll
        for (int r = 0; r < 4; r++) oacc[j][r] = 0.f;

    int nkb = 2 * qb + 2;
    for (int jb = 0; jb < nkb; jb++) {
        __syncthreads();
        // stage K/V (64 rows x 64 halves = 128 B/row) via cp.async
#pragma unroll
        for (int it = 0; it < 2; it++) {
            int id = it * 256 + tid;
            int r = id >> 3;
            int c = id & 7;
            size_t gi = (size_t)(row0 + jb * 64 + r) * DM + col0 + c * 8;
            cp_async16(Ks_u + (uint32_t)(r * (KS_PADH * 2) + c * 16), k + gi);
            cp_async16(Vs_u + (uint32_t)(r * (VS_PADH * 2) + c * 16), v + gi);
        }
        CP_COMMIT();
        CP_WAIT(0);
        __syncthreads();

        if (jb * 64 > qrowg + 15) continue;
        bool full_vis = (jb * 64 + 63 <= qrowg);

        // ---- S = Q K^T : 4 k-steps of 16, 8 n-tiles ----
        float sacc[8][4];
#pragma unroll
        for (int j = 0; j < 8; j++)
#pragma unroll
            for (int r = 0; r < 4; r++) sacc[j][r] = 0.f;

        int qr = wid * 16;
#pragma unroll
        for (int s = 0; s < 4; s++) {
            int kof = s * 16 + 2 * t4;
            uint32_t a0 = *reinterpret_cast<const uint32_t*>(&Qs[(qr + g) * QS_PADH + kof]);
            uint32_t a1 = *reinterpret_cast<const uint32_t*>(&Qs[(qr + g + 8) * QS_PADH + kof]);
            uint32_t a2 = *reinterpret_cast<const uint32_t*>(&Qs[(qr + g) * QS_PADH + kof + 8]);
            uint32_t a3 = *reinterpret_cast<const uint32_t*>(&Qs[(qr + g + 8) * QS_PADH + kof + 8]);
#pragma unroll
            for (int jn = 0; jn < 8; jn++) {
                uint32_t b0 = *reinterpret_cast<const uint32_t*>(&Ks[(jn * 8 + g) * KS_PADH + kof]);
                uint32_t b1 = *reinterpret_cast<const uint32_t*>(&Ks[(jn * 8 + g) * KS_PADH + kof + 8]);
                mma_f16(sacc[jn], a0, a1, a2, a3, b0, b1);
            }
        }

        if (!full_vis) {
            int colb = jb * 64 + 2 * t4;
            int r0i = qrowg + g;
            int r1i = qrowg + g + 8;
#pragma unroll
            for (int jn = 0; jn < 8; jn++) {
                int c = colb + jn * 8;
                if (c     > r0i) sacc[jn][0] = -1e30f;
                if (c + 1 > r0i) sacc[jn][1] = -1e30f;
                if (c     > r1i) sacc[jn][2] = -1e30f;
                if (c + 1 > r1i) sacc[jn][3] = -1e30f;
            }
        }

        // ---- online softmax (log2 domain) ----
#pragma unroll
        for (int half = 0; half < 2; half++) {
            int e0 = half * 2;
            float mx = -1e30f;
#pragma unroll
            for (int jn = 0; jn < 8; jn++)
                mx = fmaxf(mx, fmaxf(sacc[jn][e0], sacc[jn][e0 + 1]));
            mx = fmaxf(mx, __shfl_xor_sync(0xffffffffu, mx, 1));
            mx = fmaxf(mx, __shfl_xor_sync(0xffffffffu, mx, 2));
            float mnew = fmaxf(m_i[half], mx);
            float alpha = ex2f(m_i[half] - mnew);
            float rs = 0.f;
            int prow = (g + 8 * half) * PW_PADH + 2 * t4;
#pragma unroll
            for (int jn = 0; jn < 8; jn++) {
                float p0 = ex2f(sacc[jn][e0] - mnew);
                float p1 = ex2f(sacc[jn][e0 + 1] - mnew);
                rs += p0 + p1;
                *reinterpret_cast<__half2*>(&Pme[prow + jn * 8]) =
                    __floats2half2_rn(p0, p1);
            }
            rs += __shfl_xor_sync(0xffffffffu, rs, 1);
            rs += __shfl_xor_sync(0xffffffffu, rs, 2);
            l_i[half] = l_i[half] * alpha + rs;
            m_i[half] = mnew;
#pragma unroll
            for (int jn = 0; jn < 8; jn++) {
                oacc[jn][e0]     *= alpha;
                oacc[jn][e0 + 1] *= alpha;
            }
        }
        __syncwarp();

        // ---- O += P V : 4 k-steps of 16 over keys, V via ldmatrix.trans ----
#pragma unroll
        for (int s = 0; s < 4; s++) {
            int kof = s * 16 + 2 * t4;
            uint32_t a0 = *reinterpret_cast<const uint32_t*>(&Pme[g * PW_PADH + kof]);
            uint32_t a1 = *reinterpret_cast<const uint32_t*>(&Pme[(g + 8) * PW_PADH + kof]);
            uint32_t a2 = *reinterpret_cast<const uint32_t*>(&Pme[g * PW_PADH + kof + 8]);
            uint32_t a3 = *reinterpret_cast<const uint32_t*>(&Pme[(g + 8) * PW_PADH + kof + 8]);
            uint32_t vrow = Vs_u + (uint32_t)((s * 16 + lrow) * (VS_PADH * 2));
#pragma unroll
            for (int jn = 0; jn < 8; jn++) {
                uint32_t b0, b1;
                asm volatile(
                    "ldmatrix.sync.aligned.m8n8.x2.trans.shared.b16 {%0,%1}, [%2];"
                    : "=r"(b0), "=r"(b1)
                    : "r"(vrow + (uint32_t)(jn * 16)));
                mma_f16(oacc[jn], a0, a1, a2, a3, b0, b1);
            }
        }
        __syncwarp();
    }

    // ---- fp16 output ----
#pragma unroll
    for (int half = 0; half < 2; half++) {
        float inv = 1.0f / l_i[half];
        int r = row0 + qrowg + g + 8 * half;
        int e0 = half * 2;
#pragma unroll
        for (int jn = 0; jn < 8; jn++) {
            __half2 ov = __floats2half2_rn(oacc[jn][e0] * inv, oacc[jn][e0 + 1] * inv);
            *reinterpret_cast<__half2*>(o + (size_t)r * DM + col0 + jn * 8 + 2 * t4) = ov;
        }
    }
}

// ---------------- launch ----------------
extern "C" void kernel_launch(void* const* d_in, const int* in_sizes, int n_in,
                              void* d_out, int out_size) {
    const float* x     = (const float*)d_in[0];
    const float* wq    = (const float*)d_in[1];
    const float* wk    = (const float*)d_in[2];
    const float* wv    = (const float*)d_in[3];
    const float* wo    = (const float*)d_in[4];
    const float* ln1_w = (const float*)d_in[5];
    const float* ln2_w = (const float*)d_in[6];
    const float* w1    = (const float*)d_in[7];
    const float* w2    = (const float*)d_in[8];
    float* out = (float*)d_out;

    __half *p_xn, *p_q, *p_k, *p_v, *p_attn, *p_h;
    __half *p_wq, *p_wk, *p_wv, *p_wo, *p_w1, *p_w2;
    float *p_x1;
    cudaGetSymbolAddress((void**)&p_xn, g_xn);
    cudaGetSymbolAddress((void**)&p_q, g_q);
    cudaGetSymbolAddress((void**)&p_k, g_k);
    cudaGetSymbolAddress((void**)&p_v, g_v);
    cudaGetSymbolAddress((void**)&p_attn, g_attn);
    cudaGetSymbolAddress((void**)&p_x1, g_x1);
    cudaGetSymbolAddress((void**)&p_h, g_h);
    cudaGetSymbolAddress((void**)&p_wq, g_wq);
    cudaGetSymbolAddress((void**)&p_wk, g_wk);
    cudaGetSymbolAddress((void**)&p_wv, g_wv);
    cudaGetSymbolAddress((void**)&p_wo, g_wo);
    cudaGetSymbolAddress((void**)&p_w1, g_w1);
    cudaGetSymbolAddress((void**)&p_w2, g_w2);

    cudaFuncSetAttribute(gemm_h<GM_NONE>, cudaFuncAttributeMaxDynamicSharedMemorySize, GEMM_SMEM);
    cudaFuncSetAttribute(gemm_h<GM_GELU>, cudaFuncAttributeMaxDynamicSharedMemorySize, GEMM_SMEM);
    cudaFuncSetAttribute(gemm_h<GM_RES>,  cudaFuncAttributeMaxDynamicSharedMemorySize, GEMM_SMEM);
    cudaFuncSetAttribute(gemm_h<GM_H16>,  cudaFuncAttributeMaxDynamicSharedMemorySize, GEMM_SMEM);
    cudaFuncSetAttribute(attn_h, cudaFuncAttributeMaxDynamicSharedMemorySize, ATT_SMEM_BYTES);

    dim3 gd_1024(DM / 128, MT / 128);   // 8 x 32
    dim3 gd_ff(DFF / 128, MT / 128);    // 32 x 32

    // 0. all weights -> fp16 (single launch)
    cvt_all_kernel<<<(NTOT + 255) / 256, 256>>>(wq, wk, wv, wo, w1, w2,
                                                p_wq, p_wk, p_wv, p_wo, p_w1, p_w2);

    // 1. xn1 = rmsnorm(x, ln1_w) -> fp16
    rmsnorm_kernel<<<MT, 256>>>(x, ln1_w, p_xn);

    // 2. Q, K, V  (fp16 out)
    gemm_h<GM_H16><<<gd_1024, 128, GEMM_SMEM>>>(p_xn, p_wq, nullptr, nullptr, p_q, MT, DM, DM);
    gemm_h<GM_H16><<<gd_1024, 128, GEMM_SMEM>>>(p_xn, p_wk, nullptr, nullptr, p_k, MT, DM, DM);
    gemm_h<GM_H16><<<gd_1024, 128, GEMM_SMEM>>>(p_xn, p_wv, nullptr, nullptr, p_v, MT, DM, DM);

    // 3. fp16 causal flash attention
    attn_h<<<dim3(16, 16, 2), 256, ATT_SMEM_BYTES>>>(p_q, p_k, p_v, p_attn);

    // 4. x1 = x + attn @ wo.T  (fp32 out)
    gemm_h<GM_RES><<<gd_1024, 128, GEMM_SMEM>>>(p_attn, p_wo, x, p_x1, nullptr, MT, DM, DM);

    // 5. xn2 = rmsnorm(x1, ln2_w) -> fp16
    rmsnorm_kernel<<<MT, 256>>>(p_x1, ln2_w, p_xn);

    // 6. h = gelu(xn2 @ w1.T) -> fp16
    gemm_h<GM_GELU><<<gd_ff, 128, GEMM_SMEM>>>(p_xn, p_w1, nullptr, nullptr, p_h, MT, DFF, DM);

    // 7. out = x1 + h @ w2.T  (fp32 out)
    gemm_h<GM_RES><<<gd_1024, 128, GEMM_SMEM>>>(p_h, p_w2, p_x1, out, nullptr, MT, DM, DFF);
}

// round 14
// speedup vs baseline: 1.9004x; 1.0322x over previous
#include <cuda_runtime.h>
#include <cuda_fp16.h>
#include <math.h>
#include <stdint.h>

#define MT   4096    // B*T rows
#define DM   1024
#define DFF  4096

// ---------------- scratch (device globals; no allocation allowed) -----------
__device__ __half g_xn[MT * DM];
__device__ __half g_q[MT * DM];
__device__ __half g_k[MT * DM];
__device__ __half g_v[MT * DM];
__device__ __half g_attn[MT * DM];
__device__ float  g_x1[MT * DM];
__device__ __half g_h[MT * DFF];
// fp16 weights
__device__ __half g_wq[DM * DM];
__device__ __half g_wk[DM * DM];
__device__ __half g_wv[DM * DM];
__device__ __half g_wo[DM * DM];
__device__ __half g_w1[DFF * DM];
__device__ __half g_w2[DM * DFF];

// ---------------- helpers ----------------
__device__ __forceinline__ float ex2f(float x) {
    float r;
    asm("ex2.approx.f32 %0, %1;" : "=f"(r) : "f"(x));
    return r;
}

__device__ __forceinline__ void mma_f16(float c[4], uint32_t a0, uint32_t a1,
                                        uint32_t a2, uint32_t a3,
                                        uint32_t b0, uint32_t b1) {
    asm volatile(
        "mma.sync.aligned.m16n8k16.row.col.f32.f16.f16.f32 "
        "{%0,%1,%2,%3}, {%4,%5,%6,%7}, {%8,%9}, {%0,%1,%2,%3};"
        : "+f"(c[0]), "+f"(c[1]), "+f"(c[2]), "+f"(c[3])
        : "r"(a0), "r"(a1), "r"(a2), "r"(a3), "r"(b0), "r"(b1));
}

#define LDMATRIX_X4(r0, r1, r2, r3, addr) \
    asm volatile("ldmatrix.sync.aligned.m8n8.x4.shared.b16 {%0,%1,%2,%3}, [%4];" \
                 : "=r"(r0), "=r"(r1), "=r"(r2), "=r"(r3) : "r"(addr))

__device__ __forceinline__ float gelu_exact(float x) {
    return 0.5f * x * (1.0f + erff(x * 0.70710678118654752f));
}

__device__ __forceinline__ void cp_async16(uint32_t smaddr, const void* gptr) {
    asm volatile("cp.async.cg.shared.global [%0], [%1], 16;"
                 :: "r"(smaddr), "l"(gptr) : "memory");
}
#define CP_COMMIT()  asm volatile("cp.async.commit_group;" ::: "memory")
#define CP_WAIT(n)   asm volatile("cp.async.wait_group %0;" :: "n"(n) : "memory")

#define GM_NONE 0
#define GM_GELU 1
#define GM_RES  2
#define GM_H16  3

// ---------------- all-weights fp32 -> fp16 conversion (one launch) ----------
#define NS (DM * DM / 4)      // 2^18 float4 per small weight
#define NB (DFF * DM / 4)     // 2^20 float4 per big weight
#define NTOT (4 * NS + 2 * NB)

__global__ void cvt_all_kernel(const float* __restrict__ wq, const float* __restrict__ wk,
                               const float* __restrict__ wv, const float* __restrict__ wo,
                               const float* __restrict__ w1, const float* __restrict__ w2,
                               __half* dq, __half* dk, __half* dv, __half* dwo,
                               __half* d1, __half* d2) {
    int i = blockIdx.x * blockDim.x + threadIdx.x;
    if (i >= NTOT) return;
    const float* s;
    __half* d;
    int off;
    if (i < 4 * NS) {
        int seg = i >> 18;
        off = i & (NS - 1);
        s = (seg == 0) ? wq : (seg == 1) ? wk : (seg == 2) ? wv : wo;
        d = (seg == 0) ? dq : (seg == 1) ? dk : (seg == 2) ? dv : dwo;
    } else {
        int j = i - 4 * NS;
        int seg = j >> 20;
        off = j & (NB - 1);
        s = seg ? w2 : w1;
        d = seg ? d2 : d1;
    }
    float4 v = reinterpret_cast<const float4*>(s)[off];
    __half2* d2p = reinterpret_cast<__half2*>(d);
    d2p[off * 2]     = __floats2half2_rn(v.x, v.y);
    d2p[off * 2 + 1] = __floats2half2_rn(v.z, v.w);
}

// ============================================================================
// fp16 tensor-core GEMM: C[m,n] = sum_k A[m,k]*B[n,k]  (+ epilogue)
// CTA 128x128x64, 4 warps (2Mx2N), warp tile 64x64 (4x8 m16n8k16).
// 3-stage cp.async; rows 128B, chunk swizzle c^=(row&7).
// Fragments via ldmatrix.x4 (8 per s-step replace 32 scalar LDS),
// register double-buffered.
// ============================================================================
#define KT 64                            // halves per tile row (128 B)
#define TILEB (128 * KT * 2)             // 16 KB
#define GEMM_SMEM (3 * 2 * TILEB)        // 96 KB

template <int MODE>
__global__ __launch_bounds__(128, 2)
void gemm_h(const __half* __restrict__ A, const __half* __restrict__ B,
            const float* __restrict__ Res, float* __restrict__ C,
            __half* __restrict__ Ch, int M, int N, int K) {
    extern __shared__ char sm[];
    uint32_t smb = (uint32_t)__cvta_generic_to_shared(sm);

    int tid = threadIdx.x;
    int wid = tid >> 5;
    int lane = tid & 31;
    int wm = wid >> 1;
    int wn = wid & 1;
    int g  = lane >> 2;
    int t4 = lane & 3;

    int m0 = blockIdx.y * 128;
    int n0 = blockIdx.x * 128;
    const __half* Ag = A + (size_t)m0 * K;
    const __half* Bg = B + (size_t)n0 * K;

    int crow[8]; uint32_t coff[8]; int cchunk[8];
#pragma unroll
    for (int it = 0; it < 8; it++) {
        int idx = it * 128 + tid;
        int r = idx >> 3;
        int c = idx & 7;
        crow[it] = r;
        coff[it] = (uint32_t)(r * 128 + ((c ^ (r & 7)) << 4));
        cchunk[it] = c;
    }

    float acc[4][8][4];
#pragma unroll
    for (int i = 0; i < 4; i++)
#pragma unroll
        for (int j = 0; j < 8; j++)
#pragma unroll
            for (int r = 0; r < 4; r++) acc[i][j][r] = 0.f;

    int NT = K / KT;

    auto issue = [&](int t, int st) {
        uint32_t As = smb + st * 2 * TILEB;
        uint32_t Bs = As + TILEB;
        const __half* Agt = Ag + t * KT;
        const __half* Bgt = Bg + t * KT;
#pragma unroll
        for (int it = 0; it < 8; it++) {
            cp_async16(As + coff[it], Agt + (size_t)crow[it] * K + cchunk[it] * 8);
            cp_async16(Bs + coff[it], Bgt + (size_t)crow[it] * K + cchunk[it] * 8);
        }
    };

    // ldmatrix per-lane coordinates
    int rowin = lane & 15;        // A: row within 16-row tile
    int kha   = lane >> 4;        // A: k-half (chunk parity)
    int r7a   = rowin & 7;
    int rB    = lane & 7;         // B: row within 8-row n-tile
    int miB   = lane >> 3;        // B: matrix index 0..3
    int khb   = miB & 1;          // B: k-half
    int jofB  = miB >> 1;         // B: jn offset within pair

    uint32_t a_base[4], b_base[4];
#pragma unroll
    for (int i = 0; i < 4; i++)
        a_base[i] = (uint32_t)((wm * 64 + i * 16 + rowin) * 128);
#pragma unroll
    for (int p = 0; p < 4; p++)
        b_base[p] = (uint32_t)((wn * 64 + (2 * p + jofB) * 8 + rB) * 128);

    issue(0, 0); CP_COMMIT();
    if (NT > 1) issue(1, 1);
    CP_COMMIT();

    uint32_t afb[2][4][4];
    uint32_t bfb[2][4][4];

    for (int t = 0; t < NT; t++) {
        int st = t % 3;
        CP_WAIT(1);
        __syncthreads();

        if (t + 2 < NT) issue(t + 2, (t + 2) % 3);
        CP_COMMIT();

        uint32_t As = smb + st * 2 * TILEB;
        uint32_t Bs = As + TILEB;

        // load s=0 fragments into buffer 0
        {
            uint32_t cA = (uint32_t)((kha ^ r7a) << 4);          // 2s=0
            uint32_t cB = (uint32_t)((khb ^ rB) << 4);
#pragma unroll
            for (int i = 0; i < 4; i++)
                LDMATRIX_X4(afb[0][i][0], afb[0][i][1], afb[0][i][2], afb[0][i][3],
                            As + a_base[i] + cA);
#pragma unroll
            for (int p = 0; p < 4; p++)
                LDMATRIX_X4(bfb[0][p][0], bfb[0][p][1], bfb[0][p][2], bfb[0][p][3],
                            Bs + b_base[p] + cB);
        }

#pragma unroll
        for (int s = 0; s < 4; s++) {
            int cur = s & 1;
            int nxt = cur ^ 1;
            if (s < 3) {
                uint32_t cA = (uint32_t)((((2 * (s + 1)) + kha) ^ r7a) << 4);
                uint32_t cB = (uint32_t)((((2 * (s + 1)) + khb) ^ rB) << 4);
#pragma unroll
                for (int i = 0; i < 4; i++)
                    LDMATRIX_X4(afb[nxt][i][0], afb[nxt][i][1], afb[nxt][i][2], afb[nxt][i][3],
                                As + a_base[i] + cA);
#pragma unroll
                for (int p = 0; p < 4; p++)
                    LDMATRIX_X4(bfb[nxt][p][0], bfb[nxt][p][1], bfb[nxt][p][2], bfb[nxt][p][3],
                                Bs + b_base[p] + cB);
            }
#pragma unroll
            for (int i = 0; i < 4; i++)
#pragma unroll
                for (int jn = 0; jn < 8; jn++) {
                    int p = jn >> 1;
                    int hb = (jn & 1) * 2;
                    mma_f16(acc[i][jn], afb[cur][i][0], afb[cur][i][1],
                            afb[cur][i][2], afb[cur][i][3],
                            bfb[cur][p][hb], bfb[cur][p][hb + 1]);
                }
        }
    }

    // epilogue
#pragma unroll
    for (int i = 0; i < 4; i++) {
#pragma unroll
        for (int j = 0; j < 8; j++) {
            int mlo = m0 + wm * 64 + i * 16 + g;
            int n   = n0 + wn * 64 + j * 8 + t4 * 2;
            float2 v0 = make_float2(acc[i][j][0], acc[i][j][1]);
            float2 v1 = make_float2(acc[i][j][2], acc[i][j][3]);
            if (MODE == GM_GELU) {
                __half2 h0 = __floats2half2_rn(gelu_exact(v0.x), gelu_exact(v0.y));
                __half2 h1 = __floats2half2_rn(gelu_exact(v1.x), gelu_exact(v1.y));
                *reinterpret_cast<__half2*>(Ch + (size_t)mlo * N + n) = h0;
                *reinterpret_cast<__half2*>(Ch + (size_t)(mlo + 8) * N + n) = h1;
            } else if (MODE == GM_H16) {
                *reinterpret_cast<__half2*>(Ch + (size_t)mlo * N + n) =
                    __floats2half2_rn(v0.x, v0.y);
                *reinterpret_cast<__half2*>(Ch + (size_t)(mlo + 8) * N + n) =
                    __floats2half2_rn(v1.x, v1.y);
            } else {
                if (MODE == GM_RES) {
                    float2 r0 = *reinterpret_cast<const float2*>(Res + (size_t)mlo * N + n);
                    float2 r1 = *reinterpret_cast<const float2*>(Res + (size_t)(mlo + 8) * N + n);
                    v0.x += r0.x; v0.y += r0.y;
                    v1.x += r1.x; v1.y += r1.y;
                }
                *reinterpret_cast<float2*>(C + (size_t)mlo * N + n) = v0;
                *reinterpret_cast<float2*>(C + (size_t)(mlo + 8) * N + n) = v1;
            }
        }
    }
}

// ---------------- rmsnorm: fp32 in, fp16 out ----------------
__global__ void rmsnorm_kernel(const float* __restrict__ x,
                               const float* __restrict__ w,
                               __half* __restrict__ out) {
    int row = blockIdx.x;
    int tid = threadIdx.x;
    const float4* x4 = reinterpret_cast<const float4*>(x + (size_t)row * DM);
    const float4* w4 = reinterpret_cast<const float4*>(w);
    float4 v = x4[tid];
    float ss = v.x * v.x + v.y * v.y + v.z * v.z + v.w * v.w;
#pragma unroll
    for (int off = 16; off; off >>= 1)
        ss += __shfl_xor_sync(0xffffffffu, ss, off);
    __shared__ float sred[8];
    __shared__ float stot;
    if ((tid & 31) == 0) sred[tid >> 5] = ss;
    __syncthreads();
    if (tid == 0) {
        float t = 0.f;
#pragma unroll
        for (int i = 0; i < 8; i++) t += sred[i];
        stot = rsqrtf(t * (1.0f / DM) + 1e-5f);
    }
    __syncthreads();
    float rinv = stot;
    float4 wv = w4[tid];
    __half2* o2 = reinterpret_cast<__half2*>(out + (size_t)row * DM);
    o2[tid * 2]     = __floats2half2_rn(wv.x * v.x * rinv, wv.y * v.y * rinv);
    o2[tid * 2 + 1] = __floats2half2_rn(wv.z * v.z * rinv, wv.w * v.w * rinv);
}

// ============================================================================
// fp16 tensor-core causal flash attention (R13 design, unchanged).
// ============================================================================
#define QS_PADH 72
#define KS_PADH 72
#define VS_PADH 72
#define PW_PADH 72
#define ATT_SMEM_BYTES ((128 * QS_PADH + 64 * KS_PADH + 64 * VS_PADH + 128 * PW_PADH) * 2)

__global__ __launch_bounds__(256, 2)
void attn_h(const __half* __restrict__ q, const __half* __restrict__ k,
            const __half* __restrict__ v, __half* __restrict__ o) {
    extern __shared__ __half smh[];
    __half* Qs = smh;
    __half* Ks = Qs + 128 * QS_PADH;
    __half* Vs = Ks + 64 * KS_PADH;
    __half* Pw = Vs + 64 * VS_PADH;
    uint32_t Ks_u = (uint32_t)__cvta_generic_to_shared(Ks);
    uint32_t Vs_u = (uint32_t)__cvta_generic_to_shared(Vs);

    int qb  = blockIdx.x;
    int h   = blockIdx.y;
    int b   = blockIdx.z;
    int tid = threadIdx.x;
    int wid = tid >> 5;
    int lane = tid & 31;
    int g  = lane >> 2;
    int t4 = lane & 3;
    int row0 = b * 2048;
    int col0 = h * 64;

    int qrowg = qb * 128 + wid * 16;
    __half* Pme = Pw + wid * 16 * PW_PADH;
    int lrow = (lane & 7) + ((lane >> 3) & 1) * 8;

    const float QSCALE = 0.125f * 1.4426950408889634f;
#pragma unroll
    for (int it = 0; it < 8; it++) {
        int id = it * 256 + tid;
        int r  = id >> 4;
        int c  = id & 15;
        uint2 raw = *reinterpret_cast<const uint2*>(
            q + (size_t)(row0 + qb * 128 + r) * DM + col0 + c * 4);
        __half2 h0 = *reinterpret_cast<__half2*>(&raw.x);
        __half2 h1 = *reinterpret_cast<__half2*>(&raw.y);
        float2 f0 = __half22float2(h0);
        float2 f1 = __half22float2(h1);
        __half2 s0 = __floats2half2_rn(f0.x * QSCALE, f0.y * QSCALE);
        __half2 s1 = __floats2half2_rn(f1.x * QSCALE, f1.y * QSCALE);
        uint2 outw;
        outw.x = *reinterpret_cast<uint32_t*>(&s0);
        outw.y = *reinterpret_cast<uint32_t*>(&s1);
        *reinterpret_cast<uint2*>(&Qs[r * QS_PADH + c * 4]) = outw;
    }

    float m_i[2] = {-1e30f, -1e30f};
    float l_i[2] = {0.f, 0.f};
    float oacc[8][4];
#pragma unroll
    for (int j = 0; j < 8; j++)
#pragma unroll
        for (int r = 0; r < 4; r++) oacc[j][r] = 0.f;

    int nkb = 2 * qb + 2;
    for (int jb = 0; jb < nkb; jb++) {
        __syncthreads();
#pragma unroll
        for (int it = 0; it < 2; it++) {
            int id = it * 256 + tid;
            int r = id >> 3;
            int c = id & 7;
            size_t gi = (size_t)(row0 + jb * 64 + r) * DM + col0 + c * 8;
            cp_async16(Ks_u + (uint32_t)(r * (KS_PADH * 2) + c * 16), k + gi);
            cp_async16(Vs_u + (uint32_t)(r * (VS_PADH * 2) + c * 16), v + gi);
        }
        CP_COMMIT();
        CP_WAIT(0);
        __syncthreads();

        if (jb * 64 > qrowg + 15) continue;
        bool full_vis = (jb * 64 + 63 <= qrowg);

        float sacc[8][4];
#pragma unroll
        for (int j = 0; j < 8; j++)
#pragma unroll
            for (int r = 0; r < 4; r++) sacc[j][r] = 0.f;

        int qr = wid * 16;
#pragma unroll
        for (int s = 0; s < 4; s++) {
            int kof = s * 16 + 2 * t4;
            uint32_t a0 = *reinterpret_cast<const uint32_t*>(&Qs[(qr + g) * QS_PADH + kof]);
            uint32_t a1 = *reinterpret_cast<const uint32_t*>(&Qs[(qr + g + 8) * QS_PADH + kof]);
            uint32_t a2 = *reinterpret_cast<const uint32_t*>(&Qs[(qr + g) * QS_PADH + kof + 8]);
            uint32_t a3 = *reinterpret_cast<const uint32_t*>(&Qs[(qr + g + 8) * QS_PADH + kof + 8]);
#pragma unroll
            for (int jn = 0; jn < 8; jn++) {
                uint32_t b0 = *reinterpret_cast<const uint32_t*>(&Ks[(jn * 8 + g) * KS_PADH + kof]);
                uint32_t b1 = *reinterpret_cast<const uint32_t*>(&Ks[(jn * 8 + g) * KS_PADH + kof + 8]);
                mma_f16(sacc[jn], a0, a1, a2, a3, b0, b1);
            }
        }

        if (!full_vis) {
            int colb = jb * 64 + 2 * t4;
            int r0i = qrowg + g;
            int r1i = qrowg + g + 8;
#pragma unroll
            for (int jn = 0; jn < 8; jn++) {
                int c = colb + jn * 8;
                if (c     > r0i) sacc[jn][0] = -1e30f;
                if (c + 1 > r0i) sacc[jn][1] = -1e30f;
                if (c     > r1i) sacc[jn][2] = -1e30f;
                if (c + 1 > r1i) sacc[jn][3] = -1e30f;
            }
        }

#pragma unroll
        for (int half = 0; half < 2; half++) {
            int e0 = half * 2;
            float mx = -1e30f;
#pragma unroll
            for (int jn = 0; jn < 8; jn++)
                mx = fmaxf(mx, fmaxf(sacc[jn][e0], sacc[jn][e0 + 1]));
            mx = fmaxf(mx, __shfl_xor_sync(0xffffffffu, mx, 1));
            mx = fmaxf(mx, __shfl_xor_sync(0xffffffffu, mx, 2));
            float mnew = fmaxf(m_i[half], mx);
            float alpha = ex2f(m_i[half] - mnew);
            float rs = 0.f;
            int prow = (g + 8 * half) * PW_PADH + 2 * t4;
#pragma unroll
            for (int jn = 0; jn < 8; jn++) {
                float p0 = ex2f(sacc[jn][e0] - mnew);
                float p1 = ex2f(sacc[jn][e0 + 1] - mnew);
                rs += p0 + p1;
                *reinterpret_cast<__half2*>(&Pme[prow + jn * 8]) =
                    __floats2half2_rn(p0, p1);
            }
            rs += __shfl_xor_sync(0xffffffffu, rs, 1);
            rs += __shfl_xor_sync(0xffffffffu, rs, 2);
            l_i[half] = l_i[half] * alpha + rs;
            m_i[half] = mnew;
#pragma unroll
            for (int jn = 0; jn < 8; jn++) {
                oacc[jn][e0]     *= alpha;
                oacc[jn][e0 + 1] *= alpha;
            }
        }
        __syncwarp();

#pragma unroll
        for (int s = 0; s < 4; s++) {
            int kof = s * 16 + 2 * t4;
            uint32_t a0 = *reinterpret_cast<const uint32_t*>(&Pme[g * PW_PADH + kof]);
            uint32_t a1 = *reinterpret_cast<const uint32_t*>(&Pme[(g + 8) * PW_PADH + kof]);
            uint32_t a2 = *reinterpret_cast<const uint32_t*>(&Pme[g * PW_PADH + kof + 8]);
            uint32_t a3 = *reinterpret_cast<const uint32_t*>(&Pme[(g + 8) * PW_PADH + kof + 8]);
            uint32_t vrow = Vs_u + (uint32_t)((s * 16 + lrow) * (VS_PADH * 2));
#pragma unroll
            for (int jn = 0; jn < 8; jn++) {
                uint32_t b0, b1;
                asm volatile(
                    "ldmatrix.sync.aligned.m8n8.x2.trans.shared.b16 {%0,%1}, [%2];"
                    : "=r"(b0), "=r"(b1)
                    : "r"(vrow + (uint32_t)(jn * 16)));
                mma_f16(oacc[jn], a0, a1, a2, a3, b0, b1);
            }
        }
        __syncwarp();
    }

#pragma unroll
    for (int half = 0; half < 2; half++) {
        float inv = 1.0f / l_i[half];
        int r = row0 + qrowg + g + 8 * half;
        int e0 = half * 2;
#pragma unroll
        for (int jn = 0; jn < 8; jn++) {
            __half2 ov = __floats2half2_rn(oacc[jn][e0] * inv, oacc[jn][e0 + 1] * inv);
            *reinterpret_cast<__half2*>(o + (size_t)r * DM + col0 + jn * 8 + 2 * t4) = ov;
        }
    }
}

// ---------------- launch ----------------
extern "C" void kernel_launch(void* const* d_in, const int* in_sizes, int n_in,
                              void* d_out, int out_size) {
    const float* x     = (const float*)d_in[0];
    const float* wq    = (const float*)d_in[1];
    const float* wk    = (const float*)d_in[2];
    const float* wv    = (const float*)d_in[3];
    const float* wo    = (const float*)d_in[4];
    const float* ln1_w = (const float*)d_in[5];
    const float* ln2_w = (const float*)d_in[6];
    const float* w1    = (const float*)d_in[7];
    const float* w2    = (const float*)d_in[8];
    float* out = (float*)d_out;

    __half *p_xn, *p_q, *p_k, *p_v, *p_attn, *p_h;
    __half *p_wq, *p_wk, *p_wv, *p_wo, *p_w1, *p_w2;
    float *p_x1;
    cudaGetSymbolAddress((void**)&p_xn, g_xn);
    cudaGetSymbolAddress((void**)&p_q, g_q);
    cudaGetSymbolAddress((void**)&p_k, g_k);
    cudaGetSymbolAddress((void**)&p_v, g_v);
    cudaGetSymbolAddress((void**)&p_attn, g_attn);
    cudaGetSymbolAddress((void**)&p_x1, g_x1);
    cudaGetSymbolAddress((void**)&p_h, g_h);
    cudaGetSymbolAddress((void**)&p_wq, g_wq);
    cudaGetSymbolAddress((void**)&p_wk, g_wk);
    cudaGetSymbolAddress((void**)&p_wv, g_wv);
    cudaGetSymbolAddress((void**)&p_wo, g_wo);
    cudaGetSymbolAddress((void**)&p_w1, g_w1);
    cudaGetSymbolAddress((void**)&p_w2, g_w2);

    cudaFuncSetAttribute(gemm_h<GM_NONE>, cudaFuncAttributeMaxDynamicSharedMemorySize, GEMM_SMEM);
    cudaFuncSetAttribute(gemm_h<GM_GELU>, cudaFuncAttributeMaxDynamicSharedMemorySize, GEMM_SMEM);
    cudaFuncSetAttribute(gemm_h<GM_RES>,  cudaFuncAttributeMaxDynamicSharedMemorySize, GEMM_SMEM);
    cudaFuncSetAttribute(gemm_h<GM_H16>,  cudaFuncAttributeMaxDynamicSharedMemorySize, GEMM_SMEM);
    cudaFuncSetAttribute(attn_h, cudaFuncAttributeMaxDynamicSharedMemorySize, ATT_SMEM_BYTES);

    dim3 gd_1024(DM / 128, MT / 128);   // 8 x 32
    dim3 gd_ff(DFF / 128, MT / 128);    // 32 x 32

    // 0. all weights -> fp16 (single launch)
    cvt_all_kernel<<<(NTOT + 255) / 256, 256>>>(wq, wk, wv, wo, w1, w2,
                                                p_wq, p_wk, p_wv, p_wo, p_w1, p_w2);

    // 1. xn1 = rmsnorm(x, ln1_w) -> fp16
    rmsnorm_kernel<<<MT, 256>>>(x, ln1_w, p_xn);

    // 2. Q, K, V  (fp16 out)
    gemm_h<GM_H16><<<gd_1024, 128, GEMM_SMEM>>>(p_xn, p_wq, nullptr, nullptr, p_q, MT, DM, DM);
    gemm_h<GM_H16><<<gd_1024, 128, GEMM_SMEM>>>(p_xn, p_wk, nullptr, nullptr, p_k, MT, DM, DM);
    gemm_h<GM_H16><<<gd_1024, 128, GEMM_SMEM>>>(p_xn, p_wv, nullptr, nullptr, p_v, MT, DM, DM);

    // 3. fp16 causal flash attention
    attn_h<<<dim3(16, 16, 2), 256, ATT_SMEM_BYTES>>>(p_q, p_k, p_v, p_attn);

    // 4. x1 = x + attn @ wo.T  (fp32 out)
    gemm_h<GM_RES><<<gd_1024, 128, GEMM_SMEM>>>(p_attn, p_wo, x, p_x1, nullptr, MT, DM, DM);

    // 5. xn2 = rmsnorm(x1, ln2_w) -> fp16
    rmsnorm_kernel<<<MT, 256>>>(p_x1, ln2_w, p_xn);

    // 6. h = gelu(xn2 @ w1.T) -> fp16
    gemm_h<GM_GELU><<<gd_ff, 128, GEMM_SMEM>>>(p_xn, p_w1, nullptr, nullptr, p_h, MT, DFF, DM);

    // 7. out = x1 + h @ w2.T  (fp32 out)
    gemm_h<GM_RES><<<gd_1024, 128, GEMM_SMEM>>>(p_h, p_w2, p_x1, out, nullptr, MT, DM, DFF);
}

// round 16
// speedup vs baseline: 1.9191x; 1.0098x over previous
#include <cuda_runtime.h>
#include <cuda_fp16.h>
#include <math.h>
#include <stdint.h>

#define MT   4096    // B*T rows
#define DM   1024
#define DFF  4096
#define DQKV 3072

// ---------------- scratch (device globals; no allocation allowed) -----------
__device__ __half g_xn[MT * DM];
__device__ __half g_qkv[MT * DQKV];
__device__ __half g_attn[MT * DM];
__device__ float  g_x1[MT * DM];
__device__ __half g_h[MT * DFF];
// fp16 weights
__device__ __half g_wqkv[DQKV * DM];
__device__ __half g_wo[DM * DM];
__device__ __half g_w1[DFF * DM];
__device__ __half g_w2[DM * DFF];

// ---------------- helpers ----------------
__device__ __forceinline__ float ex2f(float x) {
    float r;
    asm("ex2.approx.f32 %0, %1;" : "=f"(r) : "f"(x));
    return r;
}

__device__ __forceinline__ void mma_f16(float c[4], uint32_t a0, uint32_t a1,
                                        uint32_t a2, uint32_t a3,
                                        uint32_t b0, uint32_t b1) {
    asm volatile(
        "mma.sync.aligned.m16n8k16.row.col.f32.f16.f16.f32 "
        "{%0,%1,%2,%3}, {%4,%5,%6,%7}, {%8,%9}, {%0,%1,%2,%3};"
        : "+f"(c[0]), "+f"(c[1]), "+f"(c[2]), "+f"(c[3])
        : "r"(a0), "r"(a1), "r"(a2), "r"(a3), "r"(b0), "r"(b1));
}

#define LDMATRIX_X4(r0, r1, r2, r3, addr) \
    asm volatile("ldmatrix.sync.aligned.m8n8.x4.shared.b16 {%0,%1,%2,%3}, [%4];" \
                 : "=r"(r0), "=r"(r1), "=r"(r2), "=r"(r3) : "r"(addr))

__device__ __forceinline__ float gelu_exact(float x) {
    return 0.5f * x * (1.0f + erff(x * 0.70710678118654752f));
}

__device__ __forceinline__ void cp_async16(uint32_t smaddr, const void* gptr) {
    asm volatile("cp.async.cg.shared.global [%0], [%1], 16;"
                 :: "r"(smaddr), "l"(gptr) : "memory");
}
#define CP_COMMIT()  asm volatile("cp.async.commit_group;" ::: "memory")
#define CP_WAIT(n)   asm volatile("cp.async.wait_group %0;" :: "n"(n) : "memory")

#define GM_NONE 0
#define GM_GELU 1
#define GM_RES  2
#define GM_H16  3

// ---------------- all-weights fp32 -> fp16 conversion (one launch) ----------
// wq/wk/wv land concatenated in g_wqkv; wo/w1/w2 to their own buffers.
#define NS (DM * DM / 4)      // 2^18 float4 per small weight
#define NB (DFF * DM / 4)     // 2^20 float4 per big weight
#define NTOT (4 * NS + 2 * NB)

__global__ void cvt_all_kernel(const float* __restrict__ wq, const float* __restrict__ wk,
                               const float* __restrict__ wv, const float* __restrict__ wo,
                               const float* __restrict__ w1, const float* __restrict__ w2,
                               __half* dqkv, __half* dwo, __half* d1, __half* d2) {
    int i = blockIdx.x * blockDim.x + threadIdx.x;
    if (i >= NTOT) return;
    const float* s;
    __half* d;
    int off;
    if (i < 4 * NS) {
        int seg = i >> 18;
        off = i & (NS - 1);
        s = (seg == 0) ? wq : (seg == 1) ? wk : (seg == 2) ? wv : wo;
        d = (seg == 3) ? dwo : (dqkv + seg * (DM * DM));
    } else {
        int j = i - 4 * NS;
        int seg = j >> 20;
        off = j & (NB - 1);
        s = seg ? w2 : w1;
        d = seg ? d2 : d1;
    }
    float4 v = reinterpret_cast<const float4*>(s)[off];
    __half2* d2p = reinterpret_cast<__half2*>(d);
    d2p[off * 2]     = __floats2half2_rn(v.x, v.y);
    d2p[off * 2 + 1] = __floats2half2_rn(v.z, v.w);
}

// ============================================================================
// fp16 tensor-core GEMM (R14 design, unchanged): C[m,n]=sum_k A[m,k]*B[n,k]
// CTA 128x128x64, 4 warps, ldmatrix.x4 fragments, register double-buffered,
// 3-stage cp.async, chunk swizzle c^=(row&7).
// ============================================================================
#define KT 64                            // halves per tile row (128 B)
#define TILEB (128 * KT * 2)             // 16 KB
#define GEMM_SMEM (3 * 2 * TILEB)        // 96 KB

template <int MODE>
__global__ __launch_bounds__(128, 2)
void gemm_h(const __half* __restrict__ A, const __half* __restrict__ B,
            const float* __restrict__ Res, float* __restrict__ C,
            __half* __restrict__ Ch, int M, int N, int K) {
    extern __shared__ char sm[];
    uint32_t smb = (uint32_t)__cvta_generic_to_shared(sm);

    int tid = threadIdx.x;
    int wid = tid >> 5;
    int lane = tid & 31;
    int wm = wid >> 1;
    int wn = wid & 1;
    int g  = lane >> 2;
    int t4 = lane & 3;

    int m0 = blockIdx.y * 128;
    int n0 = blockIdx.x * 128;
    const __half* Ag = A + (size_t)m0 * K;
    const __half* Bg = B + (size_t)n0 * K;

    int crow[8]; uint32_t coff[8]; int cchunk[8];
#pragma unroll
    for (int it = 0; it < 8; it++) {
        int idx = it * 128 + tid;
        int r = idx >> 3;
        int c = idx & 7;
        crow[it] = r;
        coff[it] = (uint32_t)(r * 128 + ((c ^ (r & 7)) << 4));
        cchunk[it] = c;
    }

    float acc[4][8][4];
#pragma unroll
    for (int i = 0; i < 4; i++)
#pragma unroll
        for (int j = 0; j < 8; j++)
#pragma unroll
            for (int r = 0; r < 4; r++) acc[i][j][r] = 0.f;

    int NT = K / KT;

    auto issue = [&](int t, int st) {
        uint32_t As = smb + st * 2 * TILEB;
        uint32_t Bs = As + TILEB;
        const __half* Agt = Ag + t * KT;
        const __half* Bgt = Bg + t * KT;
#pragma unroll
        for (int it = 0; it < 8; it++) {
            cp_async16(As + coff[it], Agt + (size_t)crow[it] * K + cchunk[it] * 8);
            cp_async16(Bs + coff[it], Bgt + (size_t)crow[it] * K + cchunk[it] * 8);
        }
    };

    int rowin = lane & 15;
    int kha   = lane >> 4;
    int r7a   = rowin & 7;
    int rB    = lane & 7;
    int miB   = lane >> 3;
    int khb   = miB & 1;
    int jofB  = miB >> 1;

    uint32_t a_base[4], b_base[4];
#pragma unroll
    for (int i = 0; i < 4; i++)
        a_base[i] = (uint32_t)((wm * 64 + i * 16 + rowin) * 128);
#pragma unroll
    for (int p = 0; p < 4; p++)
        b_base[p] = (uint32_t)((wn * 64 + (2 * p + jofB) * 8 + rB) * 128);

    issue(0, 0); CP_COMMIT();
    if (NT > 1) issue(1, 1);
    CP_COMMIT();

    uint32_t afb[2][4][4];
    uint32_t bfb[2][4][4];

    for (int t = 0; t < NT; t++) {
        int st = t % 3;
        CP_WAIT(1);
        __syncthreads();

        if (t + 2 < NT) issue(t + 2, (t + 2) % 3);
        CP_COMMIT();

        uint32_t As = smb + st * 2 * TILEB;
        uint32_t Bs = As + TILEB;

        {
            uint32_t cA = (uint32_t)((kha ^ r7a) << 4);
            uint32_t cB = (uint32_t)((khb ^ rB) << 4);
#pragma unroll
            for (int i = 0; i < 4; i++)
                LDMATRIX_X4(afb[0][i][0], afb[0][i][1], afb[0][i][2], afb[0][i][3],
                            As + a_base[i] + cA);
#pragma unroll
            for (int p = 0; p < 4; p++)
                LDMATRIX_X4(bfb[0][p][0], bfb[0][p][1], bfb[0][p][2], bfb[0][p][3],
                            Bs + b_base[p] + cB);
        }

#pragma unroll
        for (int s = 0; s < 4; s++) {
            int cur = s & 1;
            int nxt = cur ^ 1;
            if (s < 3) {
                uint32_t cA = (uint32_t)((((2 * (s + 1)) + kha) ^ r7a) << 4);
                uint32_t cB = (uint32_t)((((2 * (s + 1)) + khb) ^ rB) << 4);
#pragma unroll
                for (int i = 0; i < 4; i++)
                    LDMATRIX_X4(afb[nxt][i][0], afb[nxt][i][1], afb[nxt][i][2], afb[nxt][i][3],
                                As + a_base[i] + cA);
#pragma unroll
                for (int p = 0; p < 4; p++)
                    LDMATRIX_X4(bfb[nxt][p][0], bfb[nxt][p][1], bfb[nxt][p][2], bfb[nxt][p][3],
                                Bs + b_base[p] + cB);
            }
#pragma unroll
            for (int i = 0; i < 4; i++)
#pragma unroll
                for (int jn = 0; jn < 8; jn++) {
                    int p = jn >> 1;
                    int hb = (jn & 1) * 2;
                    mma_f16(acc[i][jn], afb[cur][i][0], afb[cur][i][1],
                            afb[cur][i][2], afb[cur][i][3],
                            bfb[cur][p][hb], bfb[cur][p][hb + 1]);
                }
        }
    }

    // epilogue
#pragma unroll
    for (int i = 0; i < 4; i++) {
#pragma unroll
        for (int j = 0; j < 8; j++) {
            int mlo = m0 + wm * 64 + i * 16 + g;
            int n   = n0 + wn * 64 + j * 8 + t4 * 2;
            float2 v0 = make_float2(acc[i][j][0], acc[i][j][1]);
            float2 v1 = make_float2(acc[i][j][2], acc[i][j][3]);
            if (MODE == GM_GELU) {
                __half2 h0 = __floats2half2_rn(gelu_exact(v0.x), gelu_exact(v0.y));
                __half2 h1 = __floats2half2_rn(gelu_exact(v1.x), gelu_exact(v1.y));
                *reinterpret_cast<__half2*>(Ch + (size_t)mlo * N + n) = h0;
                *reinterpret_cast<__half2*>(Ch + (size_t)(mlo + 8) * N + n) = h1;
            } else if (MODE == GM_H16) {
                *reinterpret_cast<__half2*>(Ch + (size_t)mlo * N + n) =
                    __floats2half2_rn(v0.x, v0.y);
                *reinterpret_cast<__half2*>(Ch + (size_t)(mlo + 8) * N + n) =
                    __floats2half2_rn(v1.x, v1.y);
            } else {
                if (MODE == GM_RES) {
                    float2 r0 = *reinterpret_cast<const float2*>(Res + (size_t)mlo * N + n);
                    float2 r1 = *reinterpret_cast<const float2*>(Res + (size_t)(mlo + 8) * N + n);
                    v0.x += r0.x; v0.y += r0.y;
                    v1.x += r1.x; v1.y += r1.y;
                }
                *reinterpret_cast<float2*>(C + (size_t)mlo * N + n) = v0;
                *reinterpret_cast<float2*>(C + (size_t)(mlo + 8) * N + n) = v1;
            }
        }
    }
}

// ---------------- rmsnorm: fp32 in, fp16 out ----------------
__global__ void rmsnorm_kernel(const float* __restrict__ x,
                               const float* __restrict__ w,
                               __half* __restrict__ out) {
    int row = blockIdx.x;
    int tid = threadIdx.x;
    const float4* x4 = reinterpret_cast<const float4*>(x + (size_t)row * DM);
    const float4* w4 = reinterpret_cast<const float4*>(w);
    float4 v = x4[tid];
    float ss = v.x * v.x + v.y * v.y + v.z * v.z + v.w * v.w;
#pragma unroll
    for (int off = 16; off; off >>= 1)
        ss += __shfl_xor_sync(0xffffffffu, ss, off);
    __shared__ float sred[8];
    __shared__ float stot;
    if ((tid & 31) == 0) sred[tid >> 5] = ss;
    __syncthreads();
    if (tid == 0) {
        float t = 0.f;
#pragma unroll
        for (int i = 0; i < 8; i++) t += sred[i];
        stot = rsqrtf(t * (1.0f / DM) + 1e-5f);
    }
    __syncthreads();
    float rinv = stot;
    float4 wv = w4[tid];
    __half2* o2 = reinterpret_cast<__half2*>(out + (size_t)row * DM);
    o2[tid * 2]     = __floats2half2_rn(wv.x * v.x * rinv, wv.y * v.y * rinv);
    o2[tid * 2 + 1] = __floats2half2_rn(wv.z * v.z * rinv, wv.w * v.w * rinv);
}

// ============================================================================
// fp16 tensor-core causal flash attention (R13 design; q/k/v strided by ldin
// from the fused QKV buffer).
// ============================================================================
#define QS_PADH 72
#define KS_PADH 72
#define VS_PADH 72
#define PW_PADH 72
#define ATT_SMEM_BYTES ((128 * QS_PADH + 64 * KS_PADH + 64 * VS_PADH + 128 * PW_PADH) * 2)

__global__ __launch_bounds__(256, 2)
void attn_h(const __half* __restrict__ q, const __half* __restrict__ k,
            const __half* __restrict__ v, __half* __restrict__ o, int ldin) {
    extern __shared__ __half smh[];
    __half* Qs = smh;
    __half* Ks = Qs + 128 * QS_PADH;
    __half* Vs = Ks + 64 * KS_PADH;
    __half* Pw = Vs + 64 * VS_PADH;
    uint32_t Ks_u = (uint32_t)__cvta_generic_to_shared(Ks);
    uint32_t Vs_u = (uint32_t)__cvta_generic_to_shared(Vs);

    int qb  = blockIdx.x;
    int h   = blockIdx.y;
    int b   = blockIdx.z;
    int tid = threadIdx.x;
    int wid = tid >> 5;
    int lane = tid & 31;
    int g  = lane >> 2;
    int t4 = lane & 3;
    int row0 = b * 2048;
    int col0 = h * 64;

    int qrowg = qb * 128 + wid * 16;
    __half* Pme = Pw + wid * 16 * PW_PADH;
    int lrow = (lane & 7) + ((lane >> 3) & 1) * 8;

    const float QSCALE = 0.125f * 1.4426950408889634f;
#pragma unroll
    for (int it = 0; it < 8; it++) {
        int id = it * 256 + tid;
        int r  = id >> 4;
        int c  = id & 15;
        uint2 raw = *reinterpret_cast<const uint2*>(
            q + (size_t)(row0 + qb * 128 + r) * ldin + col0 + c * 4);
        __half2 h0 = *reinterpret_cast<__half2*>(&raw.x);
        __half2 h1 = *reinterpret_cast<__half2*>(&raw.y);
        float2 f0 = __half22float2(h0);
        float2 f1 = __half22float2(h1);
        __half2 s0 = __floats2half2_rn(f0.x * QSCALE, f0.y * QSCALE);
        __half2 s1 = __floats2half2_rn(f1.x * QSCALE, f1.y * QSCALE);
        uint2 outw;
        outw.x = *reinterpret_cast<uint32_t*>(&s0);
        outw.y = *reinterpret_cast<uint32_t*>(&s1);
        *reinterpret_cast<uint2*>(&Qs[r * QS_PADH + c * 4]) = outw;
    }

    float m_i[2] = {-1e30f, -1e30f};
    float l_i[2] = {0.f, 0.f};
    float oacc[8][4];
#pragma unroll
    for (int j = 0; j < 8; j++)
#pragma unroll
        for (int r = 0; r < 4; r++) oacc[j][r] = 0.f;

    int nkb = 2 * qb + 2;
    for (int jb = 0; jb < nkb; jb++) {
        __syncthreads();
#pragma unroll
        for (int it = 0; it < 2; it++) {
            int id = it * 256 + tid;
            int r = id >> 3;
            int c = id & 7;
            size_t gi = (size_t)(row0 + jb * 64 + r) * ldin + col0 + c * 8;
            cp_async16(Ks_u + (uint32_t)(r * (KS_PADH * 2) + c * 16), k + gi);
            cp_async16(Vs_u + (uint32_t)(r * (VS_PADH * 2) + c * 16), v + gi);
        }
        CP_COMMIT();
        CP_WAIT(0);
        __syncthreads();

        if (jb * 64 > qrowg + 15) continue;
        bool full_vis = (jb * 64 + 63 <= qrowg);

        float sacc[8][4];
#pragma unroll
        for (int j = 0; j < 8; j++)
#pragma unroll
            for (int r = 0; r < 4; r++) sacc[j][r] = 0.f;

        int qr = wid * 16;
#pragma unroll
        for (int s = 0; s < 4; s++) {
            int kof = s * 16 + 2 * t4;
            uint32_t a0 = *reinterpret_cast<const uint32_t*>(&Qs[(qr + g) * QS_PADH + kof]);
            uint32_t a1 = *reinterpret_cast<const uint32_t*>(&Qs[(qr + g + 8) * QS_PADH + kof]);
            uint32_t a2 = *reinterpret_cast<const uint32_t*>(&Qs[(qr + g) * QS_PADH + kof + 8]);
            uint32_t a3 = *reinterpret_cast<const uint32_t*>(&Qs[(qr + g + 8) * QS_PADH + kof + 8]);
#pragma unroll
            for (int jn = 0; jn < 8; jn++) {
                uint32_t b0 = *reinterpret_cast<const uint32_t*>(&Ks[(jn * 8 + g) * KS_PADH + kof]);
                uint32_t b1 = *reinterpret_cast<const uint32_t*>(&Ks[(jn * 8 + g) * KS_PADH + kof + 8]);
                mma_f16(sacc[jn], a0, a1, a2, a3, b0, b1);
            }
        }

        if (!full_vis) {
            int colb = jb * 64 + 2 * t4;
            int r0i = qrowg + g;
            int r1i = qrowg + g + 8;
#pragma unroll
            for (int jn = 0; jn < 8; jn++) {
                int c = colb + jn * 8;
                if (c     > r0i) sacc[jn][0] = -1e30f;
                if (c + 1 > r0i) sacc[jn][1] = -1e30f;
                if (c     > r1i) sacc[jn][2] = -1e30f;
                if (c + 1 > r1i) sacc[jn][3] = -1e30f;
            }
        }

#pragma unroll
        for (int half = 0; half < 2; half++) {
            int e0 = half * 2;
            float mx = -1e30f;
#pragma unroll
            for (int jn = 0; jn < 8; jn++)
                mx = fmaxf(mx, fmaxf(sacc[jn][e0], sacc[jn][e0 + 1]));
            mx = fmaxf(mx, __shfl_xor_sync(0xffffffffu, mx, 1));
            mx = fmaxf(mx, __shfl_xor_sync(0xffffffffu, mx, 2));
            float mnew = fmaxf(m_i[half], mx);
            float alpha = ex2f(m_i[half] - mnew);
            float rs = 0.f;
            int prow = (g + 8 * half) * PW_PADH + 2 * t4;
#pragma unroll
            for (int jn = 0; jn < 8; jn++) {
                float p0 = ex2f(sacc[jn][e0] - mnew);
                float p1 = ex2f(sacc[jn][e0 + 1] - mnew);
                rs += p0 + p1;
                *reinterpret_cast<__half2*>(&Pme[prow + jn * 8]) =
                    __floats2half2_rn(p0, p1);
            }
            rs += __shfl_xor_sync(0xffffffffu, rs, 1);
            rs += __shfl_xor_sync(0xffffffffu, rs, 2);
            l_i[half] = l_i[half] * alpha + rs;
            m_i[half] = mnew;
#pragma unroll
            for (int jn = 0; jn < 8; jn++) {
                oacc[jn][e0]     *= alpha;
                oacc[jn][e0 + 1] *= alpha;
            }
        }
        __syncwarp();

#pragma unroll
        for (int s = 0; s < 4; s++) {
            int kof = s * 16 + 2 * t4;
            uint32_t a0 = *reinterpret_cast<const uint32_t*>(&Pme[g * PW_PADH + kof]);
            uint32_t a1 = *reinterpret_cast<const uint32_t*>(&Pme[(g + 8) * PW_PADH + kof]);
            uint32_t a2 = *reinterpret_cast<const uint32_t*>(&Pme[g * PW_PADH + kof + 8]);
            uint32_t a3 = *reinterpret_cast<const uint32_t*>(&Pme[(g + 8) * PW_PADH + kof + 8]);
            uint32_t vrow = Vs_u + (uint32_t)((s * 16 + lrow) * (VS_PADH * 2));
#pragma unroll
            for (int jn = 0; jn < 8; jn++) {
                uint32_t b0, b1;
                asm volatile(
                    "ldmatrix.sync.aligned.m8n8.x2.trans.shared.b16 {%0,%1}, [%2];"
                    : "=r"(b0), "=r"(b1)
                    : "r"(vrow + (uint32_t)(jn * 16)));
                mma_f16(oacc[jn], a0, a1, a2, a3, b0, b1);
            }
        }
        __syncwarp();
    }

#pragma unroll
    for (int half = 0; half < 2; half++) {
        float inv = 1.0f / l_i[half];
        int r = row0 + qrowg + g + 8 * half;
        int e0 = half * 2;
#pragma unroll
        for (int jn = 0; jn < 8; jn++) {
            __half2 ov = __floats2half2_rn(oacc[jn][e0] * inv, oacc[jn][e0 + 1] * inv);
            *reinterpret_cast<__half2*>(o + (size_t)r * DM + col0 + jn * 8 + 2 * t4) = ov;
        }
    }
}

// ---------------- launch ----------------
extern "C" void kernel_launch(void* const* d_in, const int* in_sizes, int n_in,
                              void* d_out, int out_size) {
    const float* x     = (const float*)d_in[0];
    const float* wq    = (const float*)d_in[1];
    const float* wk    = (const float*)d_in[2];
    const float* wv    = (const float*)d_in[3];
    const float* wo    = (const float*)d_in[4];
    const float* ln1_w = (const float*)d_in[5];
    const float* ln2_w = (const float*)d_in[6];
    const float* w1    = (const float*)d_in[7];
    const float* w2    = (const float*)d_in[8];
    float* out = (float*)d_out;

    __half *p_xn, *p_qkv, *p_attn, *p_h;
    __half *p_wqkv, *p_wo, *p_w1, *p_w2;
    float *p_x1;
    cudaGetSymbolAddress((void**)&p_xn, g_xn);
    cudaGetSymbolAddress((void**)&p_qkv, g_qkv);
    cudaGetSymbolAddress((void**)&p_attn, g_attn);
    cudaGetSymbolAddress((void**)&p_x1, g_x1);
    cudaGetSymbolAddress((void**)&p_h, g_h);
    cudaGetSymbolAddress((void**)&p_wqkv, g_wqkv);
    cudaGetSymbolAddress((void**)&p_wo, g_wo);
    cudaGetSymbolAddress((void**)&p_w1, g_w1);
    cudaGetSymbolAddress((void**)&p_w2, g_w2);

    cudaFuncSetAttribute(gemm_h<GM_NONE>, cudaFuncAttributeMaxDynamicSharedMemorySize, GEMM_SMEM);
    cudaFuncSetAttribute(gemm_h<GM_GELU>, cudaFuncAttributeMaxDynamicSharedMemorySize, GEMM_SMEM);
    cudaFuncSetAttribute(gemm_h<GM_RES>,  cudaFuncAttributeMaxDynamicSharedMemorySize, GEMM_SMEM);
    cudaFuncSetAttribute(gemm_h<GM_H16>,  cudaFuncAttributeMaxDynamicSharedMemorySize, GEMM_SMEM);
    cudaFuncSetAttribute(attn_h, cudaFuncAttributeMaxDynamicSharedMemorySize, ATT_SMEM_BYTES);

    dim3 gd_qkv(DQKV / 128, MT / 128);  // 24 x 32 = 768 CTAs
    dim3 gd_1024(DM / 128, MT / 128);   // 8 x 32
    dim3 gd_ff(DFF / 128, MT / 128);    // 32 x 32

    // 0. all weights -> fp16 (single launch; wq/wk/wv concatenated)
    cvt_all_kernel<<<(NTOT + 255) / 256, 256>>>(wq, wk, wv, wo, w1, w2,
                                                p_wqkv, p_wo, p_w1, p_w2);

    // 1. xn1 = rmsnorm(x, ln1_w) -> fp16
    rmsnorm_kernel<<<MT, 256>>>(x, ln1_w, p_xn);

    // 2. fused QKV = xn1 @ wqkv.T  (fp16 out, [MT, 3072])
    gemm_h<GM_H16><<<gd_qkv, 128, GEMM_SMEM>>>(p_xn, p_wqkv, nullptr, nullptr, p_qkv, MT, DQKV, DM);

    // 3. fp16 causal flash attention (strided Q/K/V)
    attn_h<<<dim3(16, 16, 2), 256, ATT_SMEM_BYTES>>>(
        p_qkv, p_qkv + DM, p_qkv + 2 * DM, p_attn, DQKV);

    // 4. x1 = x + attn @ wo.T  (fp32 out)
    gemm_h<GM_RES><<<gd_1024, 128, GEMM_SMEM>>>(p_attn, p_wo, x, p_x1, nullptr, MT, DM, DM);

    // 5. xn2 = rmsnorm(x1, ln2_w) -> fp16
    rmsnorm_kernel<<<MT, 256>>>(p_x1, ln2_w, p_xn);

    // 6. h = gelu(xn2 @ w1.T) -> fp16
    gemm_h<GM_GELU><<<gd_ff, 128, GEMM_SMEM>>>(p_xn, p_w1, nullptr, nullptr, p_h, MT, DFF, DM);

    // 7. out = x1 + h @ w2.T  (fp32 out)
    gemm_h<GM_RES><<<gd_1024, 128, GEMM_SMEM>>>(p_h, p_w2, p_x1, out, nullptr, MT, DM, DFF);
}

// round 17
// speedup vs baseline: 1.9615x; 1.0221x over previous
#include <cuda_runtime.h>
#include <cuda_fp16.h>
#include <math.h>
#include <stdint.h>

#define MT   4096    // B*T rows
#define DM   1024
#define DFF  4096
#define DQKV 3072

// ---------------- scratch (device globals; no allocation allowed) -----------
__device__ __half g_xn[MT * DM];
__device__ __half g_qkv[MT * DQKV];
__device__ __half g_attn[MT * DM];
__device__ float  g_x1[MT * DM];
__device__ __half g_h[MT * DFF];
// fp16 weights
__device__ __half g_wqkv[DQKV * DM];
__device__ __half g_wo[DM * DM];
__device__ __half g_w1[DFF * DM];
__device__ __half g_w2[DM * DFF];

// ---------------- helpers ----------------
__device__ __forceinline__ float ex2f(float x) {
    float r;
    asm("ex2.approx.f32 %0, %1;" : "=f"(r) : "f"(x));
    return r;
}

__device__ __forceinline__ void mma_f16(float c[4], uint32_t a0, uint32_t a1,
                                        uint32_t a2, uint32_t a3,
                                        uint32_t b0, uint32_t b1) {
    asm volatile(
        "mma.sync.aligned.m16n8k16.row.col.f32.f16.f16.f32 "
        "{%0,%1,%2,%3}, {%4,%5,%6,%7}, {%8,%9}, {%0,%1,%2,%3};"
        : "+f"(c[0]), "+f"(c[1]), "+f"(c[2]), "+f"(c[3])
        : "r"(a0), "r"(a1), "r"(a2), "r"(a3), "r"(b0), "r"(b1));
}

#define LDMATRIX_X4(r0, r1, r2, r3, addr) \
    asm volatile("ldmatrix.sync.aligned.m8n8.x4.shared.b16 {%0,%1,%2,%3}, [%4];" \
                 : "=r"(r0), "=r"(r1), "=r"(r2), "=r"(r3) : "r"(addr))

__device__ __forceinline__ float gelu_exact(float x) {
    return 0.5f * x * (1.0f + erff(x * 0.70710678118654752f));
}

__device__ __forceinline__ void cp_async16(uint32_t smaddr, const void* gptr) {
    asm volatile("cp.async.cg.shared.global [%0], [%1], 16;"
                 :: "r"(smaddr), "l"(gptr) : "memory");
}
#define CP_COMMIT()  asm volatile("cp.async.commit_group;" ::: "memory")
#define CP_WAIT(n)   asm volatile("cp.async.wait_group %0;" :: "n"(n) : "memory")

#define GM_NONE 0
#define GM_GELU 1
#define GM_RES  2
#define GM_H16  3

// ---------------- all-weights fp32 -> fp16 conversion (one launch) ----------
#define NS (DM * DM / 4)      // 2^18 float4 per small weight
#define NB (DFF * DM / 4)     // 2^20 float4 per big weight
#define NTOT (4 * NS + 2 * NB)

__global__ void cvt_all_kernel(const float* __restrict__ wq, const float* __restrict__ wk,
                               const float* __restrict__ wv, const float* __restrict__ wo,
                               const float* __restrict__ w1, const float* __restrict__ w2,
                               __half* dqkv, __half* dwo, __half* d1, __half* d2) {
    int i = blockIdx.x * blockDim.x + threadIdx.x;
    if (i >= NTOT) return;
    const float* s;
    __half* d;
    int off;
    if (i < 4 * NS) {
        int seg = i >> 18;
        off = i & (NS - 1);
        s = (seg == 0) ? wq : (seg == 1) ? wk : (seg == 2) ? wv : wo;
        d = (seg == 3) ? dwo : (dqkv + seg * (DM * DM));
    } else {
        int j = i - 4 * NS;
        int seg = j >> 20;
        off = j & (NB - 1);
        s = seg ? w2 : w1;
        d = seg ? d2 : d1;
    }
    float4 v = reinterpret_cast<const float4*>(s)[off];
    __half2* d2p = reinterpret_cast<__half2*>(d);
    d2p[off * 2]     = __floats2half2_rn(v.x, v.y);
    d2p[off * 2 + 1] = __floats2half2_rn(v.z, v.w);
}

// ============================================================================
// fp16 tensor-core GEMM (R14 design, unchanged)
// ============================================================================
#define KT 64                            // halves per tile row (128 B)
#define TILEB (128 * KT * 2)             // 16 KB
#define GEMM_SMEM (3 * 2 * TILEB)        // 96 KB

template <int MODE>
__global__ __launch_bounds__(128, 2)
void gemm_h(const __half* __restrict__ A, const __half* __restrict__ B,
            const float* __restrict__ Res, float* __restrict__ C,
            __half* __restrict__ Ch, int M, int N, int K) {
    extern __shared__ char sm[];
    uint32_t smb = (uint32_t)__cvta_generic_to_shared(sm);

    int tid = threadIdx.x;
    int wid = tid >> 5;
    int lane = tid & 31;
    int wm = wid >> 1;
    int wn = wid & 1;
    int g  = lane >> 2;
    int t4 = lane & 3;

    int m0 = blockIdx.y * 128;
    int n0 = blockIdx.x * 128;
    const __half* Ag = A + (size_t)m0 * K;
    const __half* Bg = B + (size_t)n0 * K;

    int crow[8]; uint32_t coff[8]; int cchunk[8];
#pragma unroll
    for (int it = 0; it < 8; it++) {
        int idx = it * 128 + tid;
        int r = idx >> 3;
        int c = idx & 7;
        crow[it] = r;
        coff[it] = (uint32_t)(r * 128 + ((c ^ (r & 7)) << 4));
        cchunk[it] = c;
    }

    float acc[4][8][4];
#pragma unroll
    for (int i = 0; i < 4; i++)
#pragma unroll
        for (int j = 0; j < 8; j++)
#pragma unroll
            for (int r = 0; r < 4; r++) acc[i][j][r] = 0.f;

    int NT = K / KT;

    auto issue = [&](int t, int st) {
        uint32_t As = smb + st * 2 * TILEB;
        uint32_t Bs = As + TILEB;
        const __half* Agt = Ag + t * KT;
        const __half* Bgt = Bg + t * KT;
#pragma unroll
        for (int it = 0; it < 8; it++) {
            cp_async16(As + coff[it], Agt + (size_t)crow[it] * K + cchunk[it] * 8);
            cp_async16(Bs + coff[it], Bgt + (size_t)crow[it] * K + cchunk[it] * 8);
        }
    };

    int rowin = lane & 15;
    int kha   = lane >> 4;
    int r7a   = rowin & 7;
    int rB    = lane & 7;
    int miB   = lane >> 3;
    int khb   = miB & 1;
    int jofB  = miB >> 1;

    uint32_t a_base[4], b_base[4];
#pragma unroll
    for (int i = 0; i < 4; i++)
        a_base[i] = (uint32_t)((wm * 64 + i * 16 + rowin) * 128);
#pragma unroll
    for (int p = 0; p < 4; p++)
        b_base[p] = (uint32_t)((wn * 64 + (2 * p + jofB) * 8 + rB) * 128);

    issue(0, 0); CP_COMMIT();
    if (NT > 1) issue(1, 1);
    CP_COMMIT();

    uint32_t afb[2][4][4];
    uint32_t bfb[2][4][4];

    for (int t = 0; t < NT; t++) {
        int st = t % 3;
        CP_WAIT(1);
        __syncthreads();

        if (t + 2 < NT) issue(t + 2, (t + 2) % 3);
        CP_COMMIT();

        uint32_t As = smb + st * 2 * TILEB;
        uint32_t Bs = As + TILEB;

        {
            uint32_t cA = (uint32_t)((kha ^ r7a) << 4);
            uint32_t cB = (uint32_t)((khb ^ rB) << 4);
#pragma unroll
            for (int i = 0; i < 4; i++)
                LDMATRIX_X4(afb[0][i][0], afb[0][i][1], afb[0][i][2], afb[0][i][3],
                            As + a_base[i] + cA);
#pragma unroll
            for (int p = 0; p < 4; p++)
                LDMATRIX_X4(bfb[0][p][0], bfb[0][p][1], bfb[0][p][2], bfb[0][p][3],
                            Bs + b_base[p] + cB);
        }

#pragma unroll
        for (int s = 0; s < 4; s++) {
            int cur = s & 1;
            int nxt = cur ^ 1;
            if (s < 3) {
                uint32_t cA = (uint32_t)((((2 * (s + 1)) + kha) ^ r7a) << 4);
                uint32_t cB = (uint32_t)((((2 * (s + 1)) + khb) ^ rB) << 4);
#pragma unroll
                for (int i = 0; i < 4; i++)
                    LDMATRIX_X4(afb[nxt][i][0], afb[nxt][i][1], afb[nxt][i][2], afb[nxt][i][3],
                                As + a_base[i] + cA);
#pragma unroll
                for (int p = 0; p < 4; p++)
                    LDMATRIX_X4(bfb[nxt][p][0], bfb[nxt][p][1], bfb[nxt][p][2], bfb[nxt][p][3],
                                Bs + b_base[p] + cB);
            }
#pragma unroll
            for (int i = 0; i < 4; i++)
#pragma unroll
                for (int jn = 0; jn < 8; jn++) {
                    int p = jn >> 1;
                    int hb = (jn & 1) * 2;
                    mma_f16(acc[i][jn], afb[cur][i][0], afb[cur][i][1],
                            afb[cur][i][2], afb[cur][i][3],
                            bfb[cur][p][hb], bfb[cur][p][hb + 1]);
                }
        }
    }

    // epilogue
#pragma unroll
    for (int i = 0; i < 4; i++) {
#pragma unroll
        for (int j = 0; j < 8; j++) {
            int mlo = m0 + wm * 64 + i * 16 + g;
            int n   = n0 + wn * 64 + j * 8 + t4 * 2;
            float2 v0 = make_float2(acc[i][j][0], acc[i][j][1]);
            float2 v1 = make_float2(acc[i][j][2], acc[i][j][3]);
            if (MODE == GM_GELU) {
                __half2 h0 = __floats2half2_rn(gelu_exact(v0.x), gelu_exact(v0.y));
                __half2 h1 = __floats2half2_rn(gelu_exact(v1.x), gelu_exact(v1.y));
                *reinterpret_cast<__half2*>(Ch + (size_t)mlo * N + n) = h0;
                *reinterpret_cast<__half2*>(Ch + (size_t)(mlo + 8) * N + n) = h1;
            } else if (MODE == GM_H16) {
                *reinterpret_cast<__half2*>(Ch + (size_t)mlo * N + n) =
                    __floats2half2_rn(v0.x, v0.y);
                *reinterpret_cast<__half2*>(Ch + (size_t)(mlo + 8) * N + n) =
                    __floats2half2_rn(v1.x, v1.y);
            } else {
                if (MODE == GM_RES) {
                    float2 r0 = *reinterpret_cast<const float2*>(Res + (size_t)mlo * N + n);
                    float2 r1 = *reinterpret_cast<const float2*>(Res + (size_t)(mlo + 8) * N + n);
                    v0.x += r0.x; v0.y += r0.y;
                    v1.x += r1.x; v1.y += r1.y;
                }
                *reinterpret_cast<float2*>(C + (size_t)mlo * N + n) = v0;
                *reinterpret_cast<float2*>(C + (size_t)(mlo + 8) * N + n) = v1;
            }
        }
    }
}

// ---------------- rmsnorm: fp32 in, fp16 out ----------------
__global__ void rmsnorm_kernel(const float* __restrict__ x,
                               const float* __restrict__ w,
                               __half* __restrict__ out) {
    int row = blockIdx.x;
    int tid = threadIdx.x;
    const float4* x4 = reinterpret_cast<const float4*>(x + (size_t)row * DM);
    const float4* w4 = reinterpret_cast<const float4*>(w);
    float4 v = x4[tid];
    float ss = v.x * v.x + v.y * v.y + v.z * v.z + v.w * v.w;
#pragma unroll
    for (int off = 16; off; off >>= 1)
        ss += __shfl_xor_sync(0xffffffffu, ss, off);
    __shared__ float sred[8];
    __shared__ float stot;
    if ((tid & 31) == 0) sred[tid >> 5] = ss;
    __syncthreads();
    if (tid == 0) {
        float t = 0.f;
#pragma unroll
        for (int i = 0; i < 8; i++) t += sred[i];
        stot = rsqrtf(t * (1.0f / DM) + 1e-5f);
    }
    __syncthreads();
    float rinv = stot;
    float4 wv = w4[tid];
    __half2* o2 = reinterpret_cast<__half2*>(out + (size_t)row * DM);
    o2[tid * 2]     = __floats2half2_rn(wv.x * v.x * rinv, wv.y * v.y * rinv);
    o2[tid * 2 + 1] = __floats2half2_rn(wv.z * v.z * rinv, wv.w * v.w * rinv);
}

// ============================================================================
// fp16 tensor-core causal flash attention with double-buffered K/V:
// load of block jb+1 overlaps compute of block jb; one __syncthreads/iter.
// Bq=128 (8 warps x 16 rows), Bk=64, dk=64. Grid (16,16,2), 256 threads.
// ============================================================================
#define QS_PADH 72
#define KS_PADH 72
#define VS_PADH 72
#define PW_PADH 72
#define KV_F (64 * KS_PADH)   // halves per K (or V) buffer
#define ATT_SMEM_BYTES ((128 * QS_PADH + 2 * KV_F + 2 * KV_F + 128 * PW_PADH) * 2)

__global__ __launch_bounds__(256, 2)
void attn_h(const __half* __restrict__ q, const __half* __restrict__ k,
            const __half* __restrict__ v, __half* __restrict__ o, int ldin) {
    extern __shared__ __half smh[];
    __half* Qs = smh;                       // 128 x 72
    __half* Kb = Qs + 128 * QS_PADH;        // 2 x 64 x 72
    __half* Vb = Kb + 2 * KV_F;             // 2 x 64 x 72
    __half* Pw = Vb + 2 * KV_F;             // 8 x 16 x 72
    uint32_t Kb_u = (uint32_t)__cvta_generic_to_shared(Kb);
    uint32_t Vb_u = (uint32_t)__cvta_generic_to_shared(Vb);

    int qb  = blockIdx.x;
    int h   = blockIdx.y;
    int b   = blockIdx.z;
    int tid = threadIdx.x;
    int wid = tid >> 5;
    int lane = tid & 31;
    int g  = lane >> 2;
    int t4 = lane & 3;
    int row0 = b * 2048;
    int col0 = h * 64;

    int qrowg = qb * 128 + wid * 16;
    __half* Pme = Pw + wid * 16 * PW_PADH;
    int lrow = (lane & 7) + ((lane >> 3) & 1) * 8;

    int sr = tid >> 3;        // 0..31: row base
    int sc = tid & 7;         // 16B chunk

    auto stage_kv = [&](int jb, int buf) {
        uint32_t Kst = Kb_u + (uint32_t)buf * (KV_F * 2);
        uint32_t Vst = Vb_u + (uint32_t)buf * (KV_F * 2);
#pragma unroll
        for (int it = 0; it < 2; it++) {
            int r = sr + it * 32;
            size_t gi = (size_t)(row0 + jb * 64 + r) * ldin + col0 + sc * 8;
            cp_async16(Kst + (uint32_t)(r * (KS_PADH * 2) + sc * 16), k + gi);
            cp_async16(Vst + (uint32_t)(r * (VS_PADH * 2) + sc * 16), v + gi);
        }
    };

    const float QSCALE = 0.125f * 1.4426950408889634f;
#pragma unroll
    for (int it = 0; it < 8; it++) {
        int id = it * 256 + tid;
        int r  = id >> 4;
        int c  = id & 15;
        uint2 raw = *reinterpret_cast<const uint2*>(
            q + (size_t)(row0 + qb * 128 + r) * ldin + col0 + c * 4);
        __half2 h0 = *reinterpret_cast<__half2*>(&raw.x);
        __half2 h1 = *reinterpret_cast<__half2*>(&raw.y);
        float2 f0 = __half22float2(h0);
        float2 f1 = __half22float2(h1);
        __half2 s0 = __floats2half2_rn(f0.x * QSCALE, f0.y * QSCALE);
        __half2 s1 = __floats2half2_rn(f1.x * QSCALE, f1.y * QSCALE);
        uint2 outw;
        outw.x = *reinterpret_cast<uint32_t*>(&s0);
        outw.y = *reinterpret_cast<uint32_t*>(&s1);
        *reinterpret_cast<uint2*>(&Qs[r * QS_PADH + c * 4]) = outw;
    }

    float m_i[2] = {-1e30f, -1e30f};
    float l_i[2] = {0.f, 0.f};
    float oacc[8][4];
#pragma unroll
    for (int j = 0; j < 8; j++)
#pragma unroll
        for (int r = 0; r < 4; r++) oacc[j][r] = 0.f;

    int nkb = 2 * qb + 2;

    // prologue: stage block 0 into buffer 0
    stage_kv(0, 0); CP_COMMIT();

    for (int jb = 0; jb < nkb; jb++) {
        int buf = jb & 1;
        CP_WAIT(0);          // jb's data arrived (thread-local)
        __syncthreads();     // visible to all; all done computing jb-1 on buf^1
        if (jb + 1 < nkb) {  // overlap jb+1's load with jb's compute
            stage_kv(jb + 1, buf ^ 1);
            CP_COMMIT();
        }

        if (jb * 64 > qrowg + 15) continue;   // fully masked for this warp
        bool full_vis = (jb * 64 + 63 <= qrowg);

        const __half* Ks = Kb + buf * KV_F;
        const __half* Vs = Vb + buf * KV_F;
        uint32_t Vs_u = Vb_u + (uint32_t)buf * (KV_F * 2);

        float sacc[8][4];
#pragma unroll
        for (int j = 0; j < 8; j++)
#pragma unroll
            for (int r = 0; r < 4; r++) sacc[j][r] = 0.f;

        int qr = wid * 16;
#pragma unroll
        for (int s = 0; s < 4; s++) {
            int kof = s * 16 + 2 * t4;
            uint32_t a0 = *reinterpret_cast<const uint32_t*>(&Qs[(qr + g) * QS_PADH + kof]);
            uint32_t a1 = *reinterpret_cast<const uint32_t*>(&Qs[(qr + g + 8) * QS_PADH + kof]);
            uint32_t a2 = *reinterpret_cast<const uint32_t*>(&Qs[(qr + g) * QS_PADH + kof + 8]);
            uint32_t a3 = *reinterpret_cast<const uint32_t*>(&Qs[(qr + g + 8) * QS_PADH + kof + 8]);
#pragma unroll
            for (int jn = 0; jn < 8; jn++) {
                uint32_t b0 = *reinterpret_cast<const uint32_t*>(&Ks[(jn * 8 + g) * KS_PADH + kof]);
                uint32_t b1 = *reinterpret_cast<const uint32_t*>(&Ks[(jn * 8 + g) * KS_PADH + kof + 8]);
                mma_f16(sacc[jn], a0, a1, a2, a3, b0, b1);
            }
        }

        if (!full_vis) {
            int colb = jb * 64 + 2 * t4;
            int r0i = qrowg + g;
            int r1i = qrowg + g + 8;
#pragma unroll
            for (int jn = 0; jn < 8; jn++) {
                int c = colb + jn * 8;
                if (c     > r0i) sacc[jn][0] = -1e30f;
                if (c + 1 > r0i) sacc[jn][1] = -1e30f;
                if (c     > r1i) sacc[jn][2] = -1e30f;
                if (c + 1 > r1i) sacc[jn][3] = -1e30f;
            }
        }

#pragma unroll
        for (int half = 0; half < 2; half++) {
            int e0 = half * 2;
            float mx = -1e30f;
#pragma unroll
            for (int jn = 0; jn < 8; jn++)
                mx = fmaxf(mx, fmaxf(sacc[jn][e0], sacc[jn][e0 + 1]));
            mx = fmaxf(mx, __shfl_xor_sync(0xffffffffu, mx, 1));
            mx = fmaxf(mx, __shfl_xor_sync(0xffffffffu, mx, 2));
            float mnew = fmaxf(m_i[half], mx);
            float alpha = ex2f(m_i[half] - mnew);
            float rs = 0.f;
            int prow = (g + 8 * half) * PW_PADH + 2 * t4;
#pragma unroll
            for (int jn = 0; jn < 8; jn++) {
                float p0 = ex2f(sacc[jn][e0] - mnew);
                float p1 = ex2f(sacc[jn][e0 + 1] - mnew);
                rs += p0 + p1;
                *reinterpret_cast<__half2*>(&Pme[prow + jn * 8]) =
                    __floats2half2_rn(p0, p1);
            }
            rs += __shfl_xor_sync(0xffffffffu, rs, 1);
            rs += __shfl_xor_sync(0xffffffffu, rs, 2);
            l_i[half] = l_i[half] * alpha + rs;
            m_i[half] = mnew;
#pragma unroll
            for (int jn = 0; jn < 8; jn++) {
                oacc[jn][e0]     *= alpha;
                oacc[jn][e0 + 1] *= alpha;
            }
        }
        __syncwarp();

#pragma unroll
        for (int s = 0; s < 4; s++) {
            int kof = s * 16 + 2 * t4;
            uint32_t a0 = *reinterpret_cast<const uint32_t*>(&Pme[g * PW_PADH + kof]);
            uint32_t a1 = *reinterpret_cast<const uint32_t*>(&Pme[(g + 8) * PW_PADH + kof]);
            uint32_t a2 = *reinterpret_cast<const uint32_t*>(&Pme[g * PW_PADH + kof + 8]);
            uint32_t a3 = *reinterpret_cast<const uint32_t*>(&Pme[(g + 8) * PW_PADH + kof + 8]);
            uint32_t vrow = Vs_u + (uint32_t)((s * 16 + lrow) * (VS_PADH * 2));
#pragma unroll
            for (int jn = 0; jn < 8; jn++) {
                uint32_t b0, b1;
                asm volatile(
                    "ldmatrix.sync.aligned.m8n8.x2.trans.shared.b16 {%0,%1}, [%2];"
                    : "=r"(b0), "=r"(b1)
                    : "r"(vrow + (uint32_t)(jn * 16)));
                mma_f16(oacc[jn], a0, a1, a2, a3, b0, b1);
            }
        }
        __syncwarp();
        (void)Vs;
    }

#pragma unroll
    for (int half = 0; half < 2; half++) {
        float inv = 1.0f / l_i[half];
        int r = row0 + qrowg + g + 8 * half;
        int e0 = half * 2;
#pragma unroll
        for (int jn = 0; jn < 8; jn++) {
            __half2 ov = __floats2half2_rn(oacc[jn][e0] * inv, oacc[jn][e0 + 1] * inv);
            *reinterpret_cast<__half2*>(o + (size_t)r * DM + col0 + jn * 8 + 2 * t4) = ov;
        }
    }
}

// ---------------- launch ----------------
extern "C" void kernel_launch(void* const* d_in, const int* in_sizes, int n_in,
                              void* d_out, int out_size) {
    const float* x     = (const float*)d_in[0];
    const float* wq    = (const float*)d_in[1];
    const float* wk    = (const float*)d_in[2];
    const float* wv    = (const float*)d_in[3];
    const float* wo    = (const float*)d_in[4];
    const float* ln1_w = (const float*)d_in[5];
    const float* ln2_w = (const float*)d_in[6];
    const float* w1    = (const float*)d_in[7];
    const float* w2    = (const float*)d_in[8];
    float* out = (float*)d_out;

    __half *p_xn, *p_qkv, *p_attn, *p_h;
    __half *p_wqkv, *p_wo, *p_w1, *p_w2;
    float *p_x1;
    cudaGetSymbolAddress((void**)&p_xn, g_xn);
    cudaGetSymbolAddress((void**)&p_qkv, g_qkv);
    cudaGetSymbolAddress((void**)&p_attn, g_attn);
    cudaGetSymbolAddress((void**)&p_x1, g_x1);
    cudaGetSymbolAddress((void**)&p_h, g_h);
    cudaGetSymbolAddress((void**)&p_wqkv, g_wqkv);
    cudaGetSymbolAddress((void**)&p_wo, g_wo);
    cudaGetSymbolAddress((void**)&p_w1, g_w1);
    cudaGetSymbolAddress((void**)&p_w2, g_w2);

    cudaFuncSetAttribute(gemm_h<GM_NONE>, cudaFuncAttributeMaxDynamicSharedMemorySize, GEMM_SMEM);
    cudaFuncSetAttribute(gemm_h<GM_GELU>, cudaFuncAttributeMaxDynamicSharedMemorySize, GEMM_SMEM);
    cudaFuncSetAttribute(gemm_h<GM_RES>,  cudaFuncAttributeMaxDynamicSharedMemorySize, GEMM_SMEM);
    cudaFuncSetAttribute(gemm_h<GM_H16>,  cudaFuncAttributeMaxDynamicSharedMemorySize, GEMM_SMEM);
    cudaFuncSetAttribute(attn_h, cudaFuncAttributeMaxDynamicSharedMemorySize, ATT_SMEM_BYTES);

    dim3 gd_qkv(DQKV / 128, MT / 128);  // 24 x 32 = 768 CTAs
    dim3 gd_1024(DM / 128, MT / 128);   // 8 x 32
    dim3 gd_ff(DFF / 128, MT / 128);    // 32 x 32

    // 0. all weights -> fp16 (single launch; wq/wk/wv concatenated)
    cvt_all_kernel<<<(NTOT + 255) / 256, 256>>>(wq, wk, wv, wo, w1, w2,
                                                p_wqkv, p_wo, p_w1, p_w2);

    // 1. xn1 = rmsnorm(x, ln1_w) -> fp16
    rmsnorm_kernel<<<MT, 256>>>(x, ln1_w, p_xn);

    // 2. fused QKV = xn1 @ wqkv.T  (fp16 out, [MT, 3072])
    gemm_h<GM_H16><<<gd_qkv, 128, GEMM_SMEM>>>(p_xn, p_wqkv, nullptr, nullptr, p_qkv, MT, DQKV, DM);

    // 3. fp16 causal flash attention (strided Q/K/V, double-buffered K/V)
    attn_h<<<dim3(16, 16, 2), 256, ATT_SMEM_BYTES>>>(
        p_qkv, p_qkv + DM, p_qkv + 2 * DM, p_attn, DQKV);

    // 4. x1 = x + attn @ wo.T  (fp32 out)
    gemm_h<GM_RES><<<gd_1024, 128, GEMM_SMEM>>>(p_attn, p_wo, x, p_x1, nullptr, MT, DM, DM);

    // 5. xn2 = rmsnorm(x1, ln2_w) -> fp16
    rmsnorm_kernel<<<MT, 256>>>(p_x1, ln2_w, p_xn);

    // 6. h = gelu(xn2 @ w1.T) -> fp16
    gemm_h<GM_GELU><<<gd_ff, 128, GEMM_SMEM>>>(p_xn, p_w1, nullptr, nullptr, p_h, MT, DFF, DM);

    // 7. out = x1 + h @ w2.T  (fp32 out)
    gemm_h<GM_RES><<<gd_1024, 128, GEMM_SMEM>>>(p_h, p_w2, p_x1, out, nullptr, MT, DM, DFF);
}